// round 2
// baseline (speedup 1.0000x reference)
#include <cuda_runtime.h>

// Problem dims (fixed by the dataset)
#define BB 16
#define NN 4096
#define DD 512
#define KK 128
#define REGC 1e-6f

// Scratch (__device__ globals: no allocations allowed)
__device__ float g_A[BB * KK * DD];       // A = evecs_x @ feat_x  [16,128,512]
__device__ float g_B[BB * KK * DD];       // B = evecs_y @ feat_y
__device__ float g_S[2 * BB * KK * KK];   // (b*2+dir): dir0 = AAt+regI, dir1 = BBt+regI
__device__ float g_Sinv[2 * BB * KK * KK];
__device__ float g_R[BB * KK * KK];       // BAt[b]  (rhs rows for dir0; transpose for dir1)
__device__ float g_D[2 * BB * KK * KK];   // combined mask (100*main + 25*aux)
__device__ float g_X0[2 * BB * KK * KK];
__device__ float g_X1[2 * BB * KK * KK];

// ---------------------------------------------------------------------------
// Kernel 1: projection GEMM. C[128,512] = E[128,4096] @ F[4096,512] per (b,which)
// BM=128, BN=128, BK=16, 256 threads, 8x8 per thread.
// grid: x = N tiles (4), z = b*2+which (32)
// ---------------------------------------------------------------------------
__global__ void gemm_proj(const float* __restrict__ evx, const float* __restrict__ evy,
                          const float* __restrict__ fx,  const float* __restrict__ fy) {
    int bz = blockIdx.z;
    int b = bz >> 1, w = bz & 1;
    const float* E = (w ? evy : evx) + (size_t)b * KK * NN;
    const float* F = (w ? fy : fx) + (size_t)b * NN * DD;
    float* C = (w ? g_B : g_A) + (size_t)b * KK * DD;
    int n0 = blockIdx.x * 128;

    __shared__ float Es[128][16];
    __shared__ float Fs[16][128];

    int tid = threadIdx.x;
    int ty = tid >> 4, tx = tid & 15;

    float acc[8][8];
#pragma unroll
    for (int r = 0; r < 8; r++)
#pragma unroll
        for (int c = 0; c < 8; c++) acc[r][c] = 0.0f;

    for (int k0 = 0; k0 < NN; k0 += 16) {
        // Es: 128x16 (2048 floats = 512 float4, 2 per thread), contiguous float4
#pragma unroll
        for (int u = 0; u < 2; u++) {
            int v = tid + u * 256;
            int m = v >> 2, c4 = (v & 3) << 2;
            float4 t = *(const float4*)(E + (size_t)m * NN + k0 + c4);
            *(float4*)&Es[m][c4] = t;
        }
        // Fs: 16x128
#pragma unroll
        for (int u = 0; u < 2; u++) {
            int v = tid + u * 256;
            int kk = v >> 5, c4 = (v & 31) << 2;
            float4 t = *(const float4*)(F + (size_t)(k0 + kk) * DD + n0 + c4);
            *(float4*)&Fs[kk][c4] = t;
        }
        __syncthreads();
#pragma unroll
        for (int k = 0; k < 16; k++) {
            float a[8], bb[8];
#pragma unroll
            for (int r = 0; r < 8; r++) a[r] = Es[ty + 16 * r][k];
#pragma unroll
            for (int c = 0; c < 8; c++) bb[c] = Fs[k][tx + 16 * c];
#pragma unroll
            for (int r = 0; r < 8; r++)
#pragma unroll
                for (int c = 0; c < 8; c++) acc[r][c] += a[r] * bb[c];
        }
        __syncthreads();
    }
#pragma unroll
    for (int r = 0; r < 8; r++) {
        int m = ty + 16 * r;
#pragma unroll
        for (int c = 0; c < 8; c++) {
            C[(size_t)m * DD + n0 + tx + 16 * c] = acc[r][c];
        }
    }
}

// ---------------------------------------------------------------------------
// Kernel 2: NT GEMM 128x128, K=512. C[i,j] = sum_d P[i,d]*Q[j,d] (+REG on diag)
// mode 0: S_x = A A^T + reg I  -> g_S[b*2+0]
// mode 1: S_y = B B^T + reg I  -> g_S[b*2+1]
// mode 2: R   = B A^T          -> g_R[b]
// grid: 48 CTAs (b*3+mode), 256 threads, 8x8 per thread.
// ---------------------------------------------------------------------------
__global__ void gemm_nt() {
    int id = blockIdx.x;
    int b = id / 3, mode = id % 3;
    const float* P;
    const float* Q;
    float* C;
    if (mode == 0)      { P = g_A + (size_t)b * KK * DD; Q = P; C = g_S + (size_t)(b * 2 + 0) * KK * KK; }
    else if (mode == 1) { P = g_B + (size_t)b * KK * DD; Q = P; C = g_S + (size_t)(b * 2 + 1) * KK * KK; }
    else                { P = g_B + (size_t)b * KK * DD; Q = g_A + (size_t)b * KK * DD; C = g_R + (size_t)b * KK * KK; }

    __shared__ float Ps[128][16];
    __shared__ float Qs[16][132];   // transposed store, padded

    int tid = threadIdx.x;
    int ty = tid >> 4, tx = tid & 15;

    float acc[8][8];
#pragma unroll
    for (int r = 0; r < 8; r++)
#pragma unroll
        for (int c = 0; c < 8; c++) acc[r][c] = 0.0f;

    for (int d0 = 0; d0 < DD; d0 += 16) {
#pragma unroll
        for (int u = 0; u < 2; u++) {
            int v = tid + u * 256;
            int m = v >> 2, c4 = (v & 3) << 2;
            float4 t = *(const float4*)(P + (size_t)m * DD + d0 + c4);
            *(float4*)&Ps[m][c4] = t;
            float4 q = *(const float4*)(Q + (size_t)m * DD + d0 + c4);
            Qs[c4 + 0][m] = q.x; Qs[c4 + 1][m] = q.y; Qs[c4 + 2][m] = q.z; Qs[c4 + 3][m] = q.w;
        }
        __syncthreads();
#pragma unroll
        for (int k = 0; k < 16; k++) {
            float a[8], bb[8];
#pragma unroll
            for (int r = 0; r < 8; r++) a[r] = Ps[ty + 16 * r][k];
#pragma unroll
            for (int c = 0; c < 8; c++) bb[c] = Qs[k][tx + 16 * c];
#pragma unroll
            for (int r = 0; r < 8; r++)
#pragma unroll
                for (int c = 0; c < 8; c++) acc[r][c] += a[r] * bb[c];
        }
        __syncthreads();
    }
#pragma unroll
    for (int r = 0; r < 8; r++) {
        int m = ty + 16 * r;
#pragma unroll
        for (int c = 0; c < 8; c++) {
            int n = tx + 16 * c;
            float v = acc[r][c];
            if (mode < 2 && m == n) v += REGC;
            C[m * KK + n] = v;
        }
    }
}

// ---------------------------------------------------------------------------
// Kernel 3: combined mask D = 100*mask(main) + 25*mask(aux) per (b,dir)
// dir0 (Cxy): e1=evals_x, e2=evals_y (rows i from e2, cols j from e1)
// dir1 (Cyx): swapped. g = sqrt(e/scale); d = e/scale + 1; t = g/d; u = 1/d
// M[i,j] = (t2[i]-t1[j])^2 + (u2[i]-u1[j])^2
// ---------------------------------------------------------------------------
__global__ void mask_kernel(const float* __restrict__ evx, const float* __restrict__ evy,
                            const float* __restrict__ ax,  const float* __restrict__ ay) {
    int id = blockIdx.x;
    int b = id >> 1, dir = id & 1;
    const float* e1p = (dir ? evy : evx) + b * KK;
    const float* e2p = (dir ? evx : evy) + b * KK;
    const float* a1p = (dir ? ay : ax) + b * KK;
    const float* a2p = (dir ? ax : ay) + b * KK;

    __shared__ float t1[128], u1[128], t2[128], u2[128];
    __shared__ float v1[128], w1[128], v2[128], w2[128];
    __shared__ float red[128];
    __shared__ float sc_main, sc_aux;

    int tid = threadIdx.x;
    float e1 = 0.f, e2 = 0.f, q1 = 0.f, q2 = 0.f;
    if (tid < 128) {
        e1 = fmaxf(e1p[tid], 1e-10f);
        e2 = fmaxf(e2p[tid], 1e-10f);
        q1 = fmaxf(a1p[tid], 1e-10f);
        q2 = fmaxf(a2p[tid], 1e-10f);
        red[tid] = fmaxf(e1, e2);
    }
    __syncthreads();
    for (int off = 64; off; off >>= 1) {
        if (tid < off) red[tid] = fmaxf(red[tid], red[tid + off]);
        __syncthreads();
    }
    if (tid == 0) sc_main = fmaxf(red[0], 1e-10f);
    __syncthreads();
    if (tid < 128) red[tid] = fmaxf(q1, q2);
    __syncthreads();
    for (int off = 64; off; off >>= 1) {
        if (tid < off) red[tid] = fmaxf(red[tid], red[tid + off]);
        __syncthreads();
    }
    if (tid == 0) sc_aux = fmaxf(red[0], 1e-10f);
    __syncthreads();

    if (tid < 128) {
        float r, d;
        r = e1 / sc_main; d = r + 1.0f; t1[tid] = sqrtf(r) / d; u1[tid] = 1.0f / d;
        r = e2 / sc_main; d = r + 1.0f; t2[tid] = sqrtf(r) / d; u2[tid] = 1.0f / d;
        r = q1 / sc_aux;  d = r + 1.0f; v1[tid] = sqrtf(r) / d; w1[tid] = 1.0f / d;
        r = q2 / sc_aux;  d = r + 1.0f; v2[tid] = sqrtf(r) / d; w2[tid] = 1.0f / d;
    }
    __syncthreads();

    float* Dp = g_D + (size_t)id * (KK * KK);
    for (int v = tid; v < KK * KK; v += 256) {
        int i = v >> 7, j = v & 127;
        float mr = t2[i] - t1[j], mi = u2[i] - u1[j];
        float ar = v2[i] - v1[j], ai = w2[i] - w1[j];
        Dp[v] = 100.0f * (mr * mr + mi * mi) + 25.0f * (ar * ar + ai * ai);
    }
}

// ---------------------------------------------------------------------------
// Kernel 4: Gauss-Jordan in-place inversion (SPD, no pivoting). One CTA per
// matrix (32 CTAs), 256 threads: thread (i = tid>>1, seg s = tid&1) owns 64
// columns of row i. Dynamic smem 128x129 floats.
// ---------------------------------------------------------------------------
__global__ void invert_kernel() {
    extern __shared__ float sm[];   // [128][129]
    int mat = blockIdx.x;
    const float* S = g_S + (size_t)mat * (KK * KK);
    float* Si = g_Sinv + (size_t)mat * (KK * KK);
    int tid = threadIdx.x;
    int i = tid >> 1, s = tid & 1;
    int cb = s * 64;

    for (int c = 0; c < 64; c++) sm[i * 129 + cb + c] = S[i * 128 + cb + c];
    __syncthreads();

    for (int j = 0; j < 128; j++) {
        float pivinv = 1.0f / sm[j * 129 + j];
        __syncthreads();
        if (i == j) {
            // scale pivot row; element (j,j) becomes pivinv
#pragma unroll 8
            for (int c = 0; c < 64; c++) {
                int l = cb + c;
                float v = (l == j) ? pivinv : sm[j * 129 + l] * pivinv;
                sm[j * 129 + l] = v;
            }
        }
        __syncthreads();
        if (i != j) {
            float f = sm[i * 129 + j];
#pragma unroll 8
            for (int c = 0; c < 64; c++) {
                int l = cb + c;
                float v = (l == j) ? 0.0f : sm[i * 129 + l];
                sm[i * 129 + l] = v - f * sm[j * 129 + l];
            }
        }
        __syncthreads();
    }
    for (int c = 0; c < 64; c++) Si[i * 128 + cb + c] = sm[i * 129 + cb + c];
}

// ---------------------------------------------------------------------------
// Kernel 5: solve GEMM per (b,dir), 128x128x128. Three passes:
//  mode 0: X0 = R * Sinv                 (R = BAt for dir0, BAt^T for dir1)
//  mode 1: X1 = X0 - (D o X0) * Sinv
//  mode 2: out = X0 - (D o X1) * Sinv
// ---------------------------------------------------------------------------
__global__ void solve_gemm(float* __restrict__ out, int mode) {
    int id = blockIdx.x;                // b*2+dir
    int b = id >> 1, dir = id & 1;
    const float* Si = g_Sinv + (size_t)id * (KK * KK);
    const float* Dm = g_D + (size_t)id * (KK * KK);
    const float* Rb = g_R + (size_t)b * (KK * KK);
    const float* Xp = (mode == 1 ? g_X0 : g_X1) + (size_t)id * (KK * KK);
    const float* base = g_X0 + (size_t)id * (KK * KK);
    float* Cout;
    if (mode == 0)      Cout = g_X0 + (size_t)id * (KK * KK);
    else if (mode == 1) Cout = g_X1 + (size_t)id * (KK * KK);
    else                Cout = out + (size_t)(dir ? BB * KK * KK : 0) + (size_t)b * (KK * KK);

    __shared__ float Ts[128][16];
    __shared__ float Ss[16][128];

    int tid = threadIdx.x;
    int ty = tid >> 4, tx = tid & 15;

    float acc[8][8];
#pragma unroll
    for (int r = 0; r < 8; r++)
#pragma unroll
        for (int c = 0; c < 8; c++) acc[r][c] = 0.0f;

    for (int k0 = 0; k0 < KK; k0 += 16) {
        // T tile (LHS rows): mode0 = R (transposed read for dir1); else D o Xprev
#pragma unroll
        for (int u = 0; u < 8; u++) {
            int v = tid + u * 256;
            int m = v >> 4, kk = v & 15;
            int kg = k0 + kk;
            float val;
            if (mode == 0) val = dir ? Rb[kg * 128 + m] : Rb[m * 128 + kg];
            else           val = Dm[m * 128 + kg] * Xp[m * 128 + kg];
            Ts[m][kk] = val;
        }
        // Sinv tile rows k0..k0+15 (full width)
#pragma unroll
        for (int u = 0; u < 2; u++) {
            int v = tid + u * 256;
            int kk = v >> 5, c4 = (v & 31) << 2;
            *(float4*)&Ss[kk][c4] = *(const float4*)(Si + (size_t)(k0 + kk) * 128 + c4);
        }
        __syncthreads();
#pragma unroll
        for (int k = 0; k < 16; k++) {
            float a[8], bb[8];
#pragma unroll
            for (int r = 0; r < 8; r++) a[r] = Ts[ty + 16 * r][k];
#pragma unroll
            for (int c = 0; c < 8; c++) bb[c] = Ss[k][tx + 16 * c];
#pragma unroll
            for (int r = 0; r < 8; r++)
#pragma unroll
                for (int c = 0; c < 8; c++) acc[r][c] += a[r] * bb[c];
        }
        __syncthreads();
    }
#pragma unroll
    for (int r = 0; r < 8; r++) {
        int m = ty + 16 * r;
#pragma unroll
        for (int c = 0; c < 8; c++) {
            int n = tx + 16 * c;
            int idx = m * 128 + n;
            float v = acc[r][c];
            if (mode != 0) v = base[idx] - v;
            Cout[idx] = v;
        }
    }
}

// ---------------------------------------------------------------------------
extern "C" void kernel_launch(void* const* d_in, const int* in_sizes, int n_in,
                              void* d_out, int out_size) {
    const float* feat_x  = (const float*)d_in[0];
    const float* feat_y  = (const float*)d_in[1];
    const float* evals_x = (const float*)d_in[2];
    const float* evals_y = (const float*)d_in[3];
    const float* evecs_x = (const float*)d_in[4];
    const float* evecs_y = (const float*)d_in[5];
    const float* aux_x   = (const float*)d_in[6];
    const float* aux_y   = (const float*)d_in[7];
    float* out = (float*)d_out;

    // 1. A = evecs_x @ feat_x, B = evecs_y @ feat_y
    gemm_proj<<<dim3(4, 1, 32), 256>>>(evecs_x, evecs_y, feat_x, feat_y);
    // 2. S_x = AA^T + regI, S_y = BB^T + regI, R = BA^T
    gemm_nt<<<48, 256>>>();
    // 3. masks
    mask_kernel<<<32, 256>>>(evals_x, evals_y, aux_x, aux_y);
    // 4. invert S (Gauss-Jordan, SPD)
    cudaFuncSetAttribute(invert_kernel, cudaFuncAttributeMaxDynamicSharedMemorySize,
                         128 * 129 * 4);
    invert_kernel<<<32, 256, 128 * 129 * 4>>>();
    // 5. Neumann-corrected batched solve via GEMMs
    solve_gemm<<<32, 256>>>(out, 0);
    solve_gemm<<<32, 256>>>(out, 1);
    solve_gemm<<<32, 256>>>(out, 2);
}

// round 3
// speedup vs baseline: 1.5288x; 1.5288x over previous
#include <cuda_runtime.h>

#define BB 16
#define NN 4096
#define DD 512
#define KK 128
#define REGC 1e-6f

typedef unsigned long long ull;

__device__ __forceinline__ ull pack2(float x, float y) {
    ull r; asm("mov.b64 %0, {%1, %2};" : "=l"(r) : "f"(x), "f"(y)); return r;
}
__device__ __forceinline__ void unpack2(ull v, float& lo, float& hi) {
    asm("mov.b64 {%0, %1}, %2;" : "=f"(lo), "=f"(hi) : "l"(v));
}
__device__ __forceinline__ void ffma2(ull& d, ull a, ull b) {
    asm("fma.rn.f32x2 %0, %1, %2, %0;" : "+l"(d) : "l"(a), "l"(b));
}

// Scratch
__device__ float g_A[BB * KK * DD];
__device__ float g_B[BB * KK * DD];
__device__ float g_S[2 * BB * KK * KK];
__device__ float g_Sinv[2 * BB * KK * KK];
__device__ float g_R[BB * KK * KK];
__device__ float g_RT[BB * KK * KK];
__device__ float g_D[2 * BB * KK * KK];
__device__ float g_X0[2 * BB * KK * KK];
__device__ float g_X1[2 * BB * KK * KK];

// ---------------------------------------------------------------------------
// Kernel 1: projection GEMM. C[128,512] = E[128,4096] @ F[4096,512]
// 256 thr, thread tile 8x8, FFMA2 inner, register-prefetch double buffer.
// grid: x = N tiles (4), z = b*2+which (32)
// ---------------------------------------------------------------------------
#define EST 20
#define FST 132
__global__ void gemm_proj(const float* __restrict__ evx, const float* __restrict__ evy,
                          const float* __restrict__ fx,  const float* __restrict__ fy) {
    int bz = blockIdx.z;
    int b = bz >> 1, w = bz & 1;
    const float* E = (w ? evy : evx) + (size_t)b * KK * NN;
    const float* F = (w ? fy : fx) + (size_t)b * NN * DD;
    float* C = (w ? g_B : g_A) + (size_t)b * KK * DD;
    int n0 = blockIdx.x * 128;

    __shared__ float Es[128 * EST];
    __shared__ float Fs[16 * FST];

    int tid = threadIdx.x;
    int ty = tid >> 4, tx = tid & 15;
    int v0 = tid, v1 = tid + 256;
    int em0 = v0 >> 2, ec0 = (v0 & 3) << 2;
    int em1 = v1 >> 2, ec1 = (v1 & 3) << 2;
    int fk0 = v0 >> 5, fc0 = (v0 & 31) << 2;
    int fk1 = v1 >> 5, fc1 = (v1 & 31) << 2;

    ull acc[8][4];
#pragma unroll
    for (int r = 0; r < 8; r++)
#pragma unroll
        for (int c = 0; c < 4; c++) acc[r][c] = 0ULL;

    float4 pe0, pe1, pf0, pf1;
    pe0 = *(const float4*)(E + (size_t)em0 * NN + ec0);
    pe1 = *(const float4*)(E + (size_t)em1 * NN + ec1);
    pf0 = *(const float4*)(F + (size_t)fk0 * DD + n0 + fc0);
    pf1 = *(const float4*)(F + (size_t)fk1 * DD + n0 + fc1);

    for (int k0 = 0; k0 < NN; k0 += 16) {
        *(float4*)&Es[em0 * EST + ec0] = pe0;
        *(float4*)&Es[em1 * EST + ec1] = pe1;
        *(float4*)&Fs[fk0 * FST + fc0] = pf0;
        *(float4*)&Fs[fk1 * FST + fc1] = pf1;
        __syncthreads();
        if (k0 + 16 < NN) {
            pe0 = *(const float4*)(E + (size_t)em0 * NN + k0 + 16 + ec0);
            pe1 = *(const float4*)(E + (size_t)em1 * NN + k0 + 16 + ec1);
            pf0 = *(const float4*)(F + (size_t)(k0 + 16 + fk0) * DD + n0 + fc0);
            pf1 = *(const float4*)(F + (size_t)(k0 + 16 + fk1) * DD + n0 + fc1);
        }
#pragma unroll
        for (int k = 0; k < 16; k++) {
            ull b0 = *(const ull*)&Fs[k * FST + tx * 8];
            ull b1 = *(const ull*)&Fs[k * FST + tx * 8 + 2];
            ull b2 = *(const ull*)&Fs[k * FST + tx * 8 + 4];
            ull b3 = *(const ull*)&Fs[k * FST + tx * 8 + 6];
#pragma unroll
            for (int r = 0; r < 8; r++) {
                float av = Es[(ty * 8 + r) * EST + k];
                ull a2 = pack2(av, av);
                ffma2(acc[r][0], a2, b0);
                ffma2(acc[r][1], a2, b1);
                ffma2(acc[r][2], a2, b2);
                ffma2(acc[r][3], a2, b3);
            }
        }
        __syncthreads();
    }
#pragma unroll
    for (int r = 0; r < 8; r++) {
        int m = ty * 8 + r;
#pragma unroll
        for (int c = 0; c < 4; c++) {
            *(ull*)(C + (size_t)m * DD + n0 + tx * 8 + 2 * c) = acc[r][c];
        }
    }
}

// ---------------------------------------------------------------------------
// Kernel 2: NT GEMM tile 128x64, K=512. C[i,j] = sum_d P[i,d]*Q[j,d]
// grid: (2 ntiles, 48 = b*3+mode). mode 0/1: S(+regI); mode 2: R (and RT).
// ---------------------------------------------------------------------------
#define PST 20
#define QST 68
__global__ void gemm_nt() {
    int id = blockIdx.y;
    int b = id / 3, mode = id % 3;
    int n0 = blockIdx.x * 64;
    const float* P;
    const float* Q;
    float* C;
    if (mode == 0)      { P = g_A + (size_t)b * KK * DD; Q = P; C = g_S + (size_t)(b * 2 + 0) * KK * KK; }
    else if (mode == 1) { P = g_B + (size_t)b * KK * DD; Q = P; C = g_S + (size_t)(b * 2 + 1) * KK * KK; }
    else                { P = g_B + (size_t)b * KK * DD; Q = g_A + (size_t)b * KK * DD; C = g_R + (size_t)b * KK * KK; }
    float* CT = g_RT + (size_t)b * KK * KK;

    __shared__ float Ps[128 * PST];
    __shared__ float Qs[16 * QST];

    int tid = threadIdx.x;
    int ty = tid >> 4, tx = tid & 15;
    int v0 = tid, v1 = tid + 256;
    int pm0 = v0 >> 2, pc0 = (v0 & 3) << 2;
    int pm1 = v1 >> 2, pc1 = (v1 & 3) << 2;
    int qj = tid >> 2, qc = (tid & 3) << 2;

    ull acc[8][2];
#pragma unroll
    for (int r = 0; r < 8; r++) { acc[r][0] = 0ULL; acc[r][1] = 0ULL; }

    float4 pp0, pp1, pq;
    pp0 = *(const float4*)(P + (size_t)pm0 * DD + pc0);
    pp1 = *(const float4*)(P + (size_t)pm1 * DD + pc1);
    pq  = *(const float4*)(Q + (size_t)(n0 + qj) * DD + qc);

    for (int d0 = 0; d0 < DD; d0 += 16) {
        *(float4*)&Ps[pm0 * PST + pc0] = pp0;
        *(float4*)&Ps[pm1 * PST + pc1] = pp1;
        Qs[(qc + 0) * QST + qj] = pq.x;
        Qs[(qc + 1) * QST + qj] = pq.y;
        Qs[(qc + 2) * QST + qj] = pq.z;
        Qs[(qc + 3) * QST + qj] = pq.w;
        __syncthreads();
        if (d0 + 16 < DD) {
            pp0 = *(const float4*)(P + (size_t)pm0 * DD + d0 + 16 + pc0);
            pp1 = *(const float4*)(P + (size_t)pm1 * DD + d0 + 16 + pc1);
            pq  = *(const float4*)(Q + (size_t)(n0 + qj) * DD + d0 + 16 + qc);
        }
#pragma unroll
        for (int k = 0; k < 16; k++) {
            ull b0 = *(const ull*)&Qs[k * QST + tx * 4];
            ull b1 = *(const ull*)&Qs[k * QST + tx * 4 + 2];
#pragma unroll
            for (int r = 0; r < 8; r++) {
                float av = Ps[(ty * 8 + r) * PST + k];
                ull a2 = pack2(av, av);
                ffma2(acc[r][0], a2, b0);
                ffma2(acc[r][1], a2, b1);
            }
        }
        __syncthreads();
    }
#pragma unroll
    for (int r = 0; r < 8; r++) {
        int m = ty * 8 + r;
#pragma unroll
        for (int c2 = 0; c2 < 2; c2++) {
            int n = n0 + tx * 4 + 2 * c2;
            float lo, hi;
            unpack2(acc[r][c2], lo, hi);
            if (mode < 2) {
                if (m == n) lo += REGC;
                if (m == n + 1) hi += REGC;
            }
            C[m * KK + n] = lo;
            C[m * KK + n + 1] = hi;
            if (mode == 2) {
                CT[n * KK + m] = lo;
                CT[(n + 1) * KK + m] = hi;
            }
        }
    }
}

// ---------------------------------------------------------------------------
// Kernel 3: combined mask D = 100*mask(main) + 25*mask(aux) per (b,dir)
// ---------------------------------------------------------------------------
__global__ void mask_kernel(const float* __restrict__ evx, const float* __restrict__ evy,
                            const float* __restrict__ ax,  const float* __restrict__ ay) {
    int id = blockIdx.x;
    int b = id >> 1, dir = id & 1;
    const float* e1p = (dir ? evy : evx) + b * KK;
    const float* e2p = (dir ? evx : evy) + b * KK;
    const float* a1p = (dir ? ay : ax) + b * KK;
    const float* a2p = (dir ? ax : ay) + b * KK;

    __shared__ float t1[128], u1[128], t2[128], u2[128];
    __shared__ float v1[128], w1[128], v2[128], w2[128];
    __shared__ float red[128];
    __shared__ float sc_main, sc_aux;

    int tid = threadIdx.x;
    float e1 = 0.f, e2 = 0.f, q1 = 0.f, q2 = 0.f;
    if (tid < 128) {
        e1 = fmaxf(e1p[tid], 1e-10f);
        e2 = fmaxf(e2p[tid], 1e-10f);
        q1 = fmaxf(a1p[tid], 1e-10f);
        q2 = fmaxf(a2p[tid], 1e-10f);
        red[tid] = fmaxf(e1, e2);
    }
    __syncthreads();
    for (int off = 64; off; off >>= 1) {
        if (tid < off) red[tid] = fmaxf(red[tid], red[tid + off]);
        __syncthreads();
    }
    if (tid == 0) sc_main = fmaxf(red[0], 1e-10f);
    __syncthreads();
    if (tid < 128) red[tid] = fmaxf(q1, q2);
    __syncthreads();
    for (int off = 64; off; off >>= 1) {
        if (tid < off) red[tid] = fmaxf(red[tid], red[tid + off]);
        __syncthreads();
    }
    if (tid == 0) sc_aux = fmaxf(red[0], 1e-10f);
    __syncthreads();

    if (tid < 128) {
        float r, d;
        r = e1 / sc_main; d = r + 1.0f; t1[tid] = sqrtf(r) / d; u1[tid] = 1.0f / d;
        r = e2 / sc_main; d = r + 1.0f; t2[tid] = sqrtf(r) / d; u2[tid] = 1.0f / d;
        r = q1 / sc_aux;  d = r + 1.0f; v1[tid] = sqrtf(r) / d; w1[tid] = 1.0f / d;
        r = q2 / sc_aux;  d = r + 1.0f; v2[tid] = sqrtf(r) / d; w2[tid] = 1.0f / d;
    }
    __syncthreads();

    float* Dp = g_D + (size_t)id * (KK * KK);
    for (int v = tid; v < KK * KK; v += 256) {
        int i = v >> 7, j = v & 127;
        float mr = t2[i] - t1[j], mi = u2[i] - u1[j];
        float ar = v2[i] - v1[j], ai = w2[i] - w1[j];
        Dp[v] = 100.0f * (mr * mr + mi * mi) + 25.0f * (ar * ar + ai * ai);
    }
}

// ---------------------------------------------------------------------------
// Kernel 4: Blocked Gauss-Jordan inversion (SPD, no pivot). One CTA / matrix.
// Panel width 32; full matrix in smem; rank-32 updates register-tiled + FFMA2.
// ---------------------------------------------------------------------------
#define MST 132
#define CST 36
#define TST 36
#define INV_SMEM ((128 * MST + 128 * CST + 32 * TST) * 4)

__global__ void invert_blocked() {
    extern __shared__ float sm[];
    float* M  = sm;
    float* Cs = sm + 128 * MST;
    float* T  = Cs + 128 * CST;
    int mat = blockIdx.x;
    const float* S = g_S + (size_t)mat * KK * KK;
    float* Si = g_Sinv + (size_t)mat * KK * KK;
    int tid = threadIdx.x;
    int ty = tid >> 4, tx = tid & 15;

    // load M (coalesced, conflict-free)
#pragma unroll
    for (int u = 0; u < 16; u++) {
        int v = tid + u * 256;
        int m = v >> 5, c4 = (v & 31) << 2;
        *(float4*)(M + m * MST + c4) = *(const float4*)(S + m * 128 + c4);
    }
    __syncthreads();

    for (int p = 0; p < 4; p++) {
        int p0 = p * 32;
        // save column panel C (all rows), copy pivot block to T
#pragma unroll
        for (int u = 0; u < 4; u++) {
            int v = tid + u * 256;
            int i = v >> 3, q4 = (v & 7) << 2;
            *(float4*)(Cs + i * CST + q4) = *(const float4*)(M + i * MST + p0 + q4);
        }
        {
            int q = tid >> 3, r4 = (tid & 7) << 2;
            *(float4*)(T + q * TST + r4) = *(const float4*)(M + (p0 + q) * MST + p0 + r4);
        }
        __syncthreads();

        // GJ invert T (32x32), each thread owns 4 elems of row q
        {
            int q = tid >> 3, rb = (tid & 7) << 2;
            for (int j = 0; j < 32; j++) {
                float pivinv = 1.0f / T[j * TST + j];
                float f = T[q * TST + j];
                float pr[4], cu[4];
#pragma unroll
                for (int a = 0; a < 4; a++) { pr[a] = T[j * TST + rb + a]; cu[a] = T[q * TST + rb + a]; }
                __syncthreads();
                float o[4];
                if (q == j) {
#pragma unroll
                    for (int a = 0; a < 4; a++) o[a] = (rb + a == j) ? pivinv : pr[a] * pivinv;
                } else {
                    float fp = f * pivinv;
#pragma unroll
                    for (int a = 0; a < 4; a++) o[a] = (rb + a == j) ? -fp : cu[a] - fp * pr[a];
                }
#pragma unroll
                for (int a = 0; a < 4; a++) T[q * TST + rb + a] = o[a];
                __syncthreads();
            }
        }

        // Row panel: M[P,:] <- Dinv * Mold[P,:], with M[P,P] <- Dinv
        {
            int qr = tid >> 3;
            int cb = (tid & 7) << 4;
            float out[16];
#pragma unroll
            for (int a = 0; a < 16; a++) out[a] = 0.0f;
            for (int r = 0; r < 32; r++) {
                float tq = T[qr * TST + r];
                const float* Mr = M + (p0 + r) * MST + cb;
#pragma unroll
                for (int a = 0; a < 16; a += 4) {
                    float4 mv = *(const float4*)(Mr + a);
                    out[a + 0] += tq * mv.x;
                    out[a + 1] += tq * mv.y;
                    out[a + 2] += tq * mv.z;
                    out[a + 3] += tq * mv.w;
                }
            }
            __syncthreads();
#pragma unroll
            for (int a = 0; a < 16; a++) {
                int l = cb + a;
                float vv = (l >= p0 && l < p0 + 32) ? T[qr * TST + (l - p0)] : out[a];
                M[(p0 + qr) * MST + l] = vv;
            }
            __syncthreads();
        }

        // Rank-32 update of all rows not in P, all 128 cols (cols in P get -C*Dinv)
        {
            ull acc[6][4];
#pragma unroll
            for (int r = 0; r < 6; r++)
#pragma unroll
                for (int c = 0; c < 4; c++) acc[r][c] = 0ULL;
            for (int q = 0; q < 32; q++) {
                const float* Mp = M + (p0 + q) * MST + tx * 8;
                ull b0 = *(const ull*)(Mp + 0);
                ull b1 = *(const ull*)(Mp + 2);
                ull b2 = *(const ull*)(Mp + 4);
                ull b3 = *(const ull*)(Mp + 6);
#pragma unroll
                for (int r = 0; r < 6; r++) {
                    int z = ty + 16 * r;
                    int i = (z < p0) ? z : z + 32;
                    float av = Cs[i * CST + q];
                    ull a2 = pack2(av, av);
                    ffma2(acc[r][0], a2, b0);
                    ffma2(acc[r][1], a2, b1);
                    ffma2(acc[r][2], a2, b2);
                    ffma2(acc[r][3], a2, b3);
                }
            }
            // epilogue: each (i,l) owned by exactly one thread; no barrier needed before
#pragma unroll
            for (int r = 0; r < 6; r++) {
                int z = ty + 16 * r;
                int i = (z < p0) ? z : z + 32;
#pragma unroll
                for (int c = 0; c < 4; c++) {
                    int l = tx * 8 + 2 * c;
                    float lo, hi;
                    unpack2(acc[r][c], lo, hi);
                    float* Mp = M + i * MST + l;
                    bool inP0 = (l >= p0 && l < p0 + 32);
                    bool inP1 = (l + 1 >= p0 && l + 1 < p0 + 32);
                    float o0 = (inP0 ? 0.0f : Mp[0]) - lo;
                    float o1 = (inP1 ? 0.0f : Mp[1]) - hi;
                    Mp[0] = o0;
                    Mp[1] = o1;
                }
            }
            __syncthreads();
        }
    }

    // write out
#pragma unroll
    for (int u = 0; u < 16; u++) {
        int v = tid + u * 256;
        int m = v >> 5, c4 = (v & 31) << 2;
        *(float4*)(Si + m * 128 + c4) = *(const float4*)(M + m * MST + c4);
    }
}

// ---------------------------------------------------------------------------
// Kernel 5: solve GEMM, tile 128x64, K=128, FFMA2. grid (2 ntiles, 32 id).
//  mode 0: X0 = R * Sinv   (RT for dir1)
//  mode 1: X1 = X0 - (D o X0) * Sinv
//  mode 2: out = X0 - (D o X1) * Sinv
// ---------------------------------------------------------------------------
#define SST 68
__global__ void solve_gemm(float* __restrict__ out, int mode) {
    int id = blockIdx.y;
    int b = id >> 1, dir = id & 1;
    int n0 = blockIdx.x * 64;
    const float* Si = g_Sinv + (size_t)id * (KK * KK);
    const float* Dm = g_D + (size_t)id * (KK * KK);
    const float* Rb = (dir ? g_RT : g_R) + (size_t)b * (KK * KK);
    const float* Xp = (mode == 1 ? g_X0 : g_X1) + (size_t)id * (KK * KK);
    const float* base = g_X0 + (size_t)id * (KK * KK);
    float* Cout;
    if (mode == 0)      Cout = g_X0 + (size_t)id * (KK * KK);
    else if (mode == 1) Cout = g_X1 + (size_t)id * (KK * KK);
    else                Cout = out + (size_t)(dir ? BB * KK * KK : 0) + (size_t)b * (KK * KK);

    __shared__ float Ts[128 * EST];
    __shared__ float Ss[16 * SST];

    int tid = threadIdx.x;
    int ty = tid >> 4, tx = tid & 15;
    int v0 = tid, v1 = tid + 256;
    int tm0 = v0 >> 2, tc0 = (v0 & 3) << 2;
    int tm1 = v1 >> 2, tc1 = (v1 & 3) << 2;
    int sk = tid >> 4, sc = (tid & 15) << 2;

    ull acc[8][2];
#pragma unroll
    for (int r = 0; r < 8; r++) { acc[r][0] = 0ULL; acc[r][1] = 0ULL; }

    for (int k0 = 0; k0 < KK; k0 += 16) {
        if (mode == 0) {
            *(float4*)&Ts[tm0 * EST + tc0] = *(const float4*)(Rb + tm0 * 128 + k0 + tc0);
            *(float4*)&Ts[tm1 * EST + tc1] = *(const float4*)(Rb + tm1 * 128 + k0 + tc1);
        } else {
            float4 d0 = *(const float4*)(Dm + tm0 * 128 + k0 + tc0);
            float4 x0 = *(const float4*)(Xp + tm0 * 128 + k0 + tc0);
            float4 d1 = *(const float4*)(Dm + tm1 * 128 + k0 + tc1);
            float4 x1 = *(const float4*)(Xp + tm1 * 128 + k0 + tc1);
            float4 o0 = make_float4(d0.x * x0.x, d0.y * x0.y, d0.z * x0.z, d0.w * x0.w);
            float4 o1 = make_float4(d1.x * x1.x, d1.y * x1.y, d1.z * x1.z, d1.w * x1.w);
            *(float4*)&Ts[tm0 * EST + tc0] = o0;
            *(float4*)&Ts[tm1 * EST + tc1] = o1;
        }
        *(float4*)&Ss[sk * SST + sc] = *(const float4*)(Si + (size_t)(k0 + sk) * 128 + n0 + sc);
        __syncthreads();
#pragma unroll
        for (int k = 0; k < 16; k++) {
            ull b0 = *(const ull*)&Ss[k * SST + tx * 4];
            ull b1 = *(const ull*)&Ss[k * SST + tx * 4 + 2];
#pragma unroll
            for (int r = 0; r < 8; r++) {
                float av = Ts[(ty * 8 + r) * EST + k];
                ull a2 = pack2(av, av);
                ffma2(acc[r][0], a2, b0);
                ffma2(acc[r][1], a2, b1);
            }
        }
        __syncthreads();
    }
#pragma unroll
    for (int r = 0; r < 8; r++) {
        int m = ty * 8 + r;
#pragma unroll
        for (int c2 = 0; c2 < 2; c2++) {
            int n = n0 + tx * 4 + 2 * c2;
            int idx = m * 128 + n;
            float lo, hi;
            unpack2(acc[r][c2], lo, hi);
            if (mode != 0) {
                lo = base[idx] - lo;
                hi = base[idx + 1] - hi;
            }
            Cout[idx] = lo;
            Cout[idx + 1] = hi;
        }
    }
}

// ---------------------------------------------------------------------------
extern "C" void kernel_launch(void* const* d_in, const int* in_sizes, int n_in,
                              void* d_out, int out_size) {
    const float* feat_x  = (const float*)d_in[0];
    const float* feat_y  = (const float*)d_in[1];
    const float* evals_x = (const float*)d_in[2];
    const float* evals_y = (const float*)d_in[3];
    const float* evecs_x = (const float*)d_in[4];
    const float* evecs_y = (const float*)d_in[5];
    const float* aux_x   = (const float*)d_in[6];
    const float* aux_y   = (const float*)d_in[7];
    float* out = (float*)d_out;

    gemm_proj<<<dim3(4, 1, 32), 256>>>(evecs_x, evecs_y, feat_x, feat_y);
    gemm_nt<<<dim3(2, 48), 256>>>();
    mask_kernel<<<32, 256>>>(evals_x, evals_y, aux_x, aux_y);
    cudaFuncSetAttribute(invert_blocked, cudaFuncAttributeMaxDynamicSharedMemorySize, INV_SMEM);
    invert_blocked<<<32, 256, INV_SMEM>>>();
    solve_gemm<<<dim3(2, 32), 256>>>(out, 0);
    solve_gemm<<<dim3(2, 32), 256>>>(out, 1);
    solve_gemm<<<dim3(2, 32), 256>>>(out, 2);
}

// round 6
// speedup vs baseline: 2.7695x; 1.8115x over previous
#include <cuda_runtime.h>
#include <cuda_bf16.h>

#define BB 16
#define NN 4096
#define DD 512
#define KK 128
#define REGC 1e-6f

typedef unsigned long long ull;

__device__ __forceinline__ ull pack2(float x, float y) {
    ull r; asm("mov.b64 %0, {%1, %2};" : "=l"(r) : "f"(x), "f"(y)); return r;
}
__device__ __forceinline__ void unpack2(ull v, float& lo, float& hi) {
    asm("mov.b64 {%0, %1}, %2;" : "=f"(lo), "=f"(hi) : "l"(v));
}
__device__ __forceinline__ void ffma2(ull& d, ull a, ull b) {
    asm("fma.rn.f32x2 %0, %1, %2, %0;" : "+l"(d) : "l"(a), "l"(b));
}
__device__ __forceinline__ unsigned smem_u32(const void* p) {
    unsigned a;
    asm("{ .reg .u64 t; cvta.to.shared.u64 t, %1; cvt.u32.u64 %0, t; }" : "=r"(a) : "l"(p));
    return a;
}
__device__ __forceinline__ void ldm4(unsigned* r, unsigned addr) {
    asm volatile("ldmatrix.sync.aligned.m8n8.x4.shared.b16 {%0,%1,%2,%3}, [%4];"
                 : "=r"(r[0]), "=r"(r[1]), "=r"(r[2]), "=r"(r[3]) : "r"(addr));
}
__device__ __forceinline__ void mma_bf16(float* d, const unsigned* a, const unsigned* b) {
    asm volatile(
        "mma.sync.aligned.m16n8k16.row.col.f32.bf16.bf16.f32 "
        "{%0,%1,%2,%3}, {%4,%5,%6,%7}, {%8,%9}, {%0,%1,%2,%3};"
        : "+f"(d[0]), "+f"(d[1]), "+f"(d[2]), "+f"(d[3])
        : "r"(a[0]), "r"(a[1]), "r"(a[2]), "r"(a[3]), "r"(b[0]), "r"(b[1]));
}
#define SWZ(o) ((o) ^ (((o) >> 3) & 0x70))

// Scratch
__device__ float g_A[BB * KK * DD];
__device__ float g_B[BB * KK * DD];
__device__ float g_S[2 * BB * KK * KK];
__device__ float g_Sinv[2 * BB * KK * KK];
__device__ float g_R[BB * KK * KK];
__device__ float g_RT[BB * KK * KK];
__device__ float g_D[2 * BB * KK * KK];
__device__ float g_X0[2 * BB * KK * KK];
__device__ float g_X1[2 * BB * KK * KK];
// bf16 split operands: E [p=w*16+b][128][4096], F transposed [p][512][4096]
__device__ __nv_bfloat16 g_Ehi[2 * BB * KK * NN];
__device__ __nv_bfloat16 g_Elo[2 * BB * KK * NN];
__device__ __nv_bfloat16 g_Fhi[2 * BB * DD * NN];
__device__ __nv_bfloat16 g_Flo[2 * BB * DD * NN];

__device__ __forceinline__ void split1(float x, unsigned short& h, unsigned short& l) {
    __nv_bfloat16 hb = __float2bfloat16_rn(x);
    float r = x - __bfloat162float(hb);
    __nv_bfloat16 lb = __float2bfloat16_rn(r);
    h = __bfloat16_as_ushort(hb);
    l = __bfloat16_as_ushort(lb);
}

// ---------------------------------------------------------------------------
// split_E: evecs fp32 [b][128][4096] -> g_Ehi/g_Elo bf16, same layout, p=w*16+b
// ---------------------------------------------------------------------------
__global__ void split_E(const float* __restrict__ ex, const float* __restrict__ ey) {
    int w = blockIdx.y;
    const float* E = w ? ey : ex;
    size_t i4 = (size_t)blockIdx.x * 256 + threadIdx.x;
    float4 t = *((const float4*)E + i4);
    unsigned short h0, h1, h2, h3, l0, l1, l2, l3;
    split1(t.x, h0, l0); split1(t.y, h1, l1); split1(t.z, h2, l2); split1(t.w, h3, l3);
    ull hp = (ull)h0 | ((ull)h1 << 16) | ((ull)h2 << 32) | ((ull)h3 << 48);
    ull lp = (ull)l0 | ((ull)l1 << 16) | ((ull)l2 << 32) | ((ull)l3 << 48);
    size_t o = (size_t)w * (BB * KK * NN) + i4 * 4;
    *(ull*)(g_Ehi + o) = hp;
    *(ull*)(g_Elo + o) = lp;
}

// ---------------------------------------------------------------------------
// split_F: feat fp32 [b][4096][512] -> transposed bf16 [p][512][4096]
// ---------------------------------------------------------------------------
__global__ void split_F(const float* __restrict__ fx, const float* __restrict__ fy) {
    int p = blockIdx.z; int w = p >> 4, b = p & 15;
    const float* F = (w ? fy : fx) + (size_t)b * NN * DD;
    int k0 = blockIdx.x * 64, d0 = blockIdx.y * 64;
    __shared__ float ts[64 * 65];
    int tid = threadIdx.x;
#pragma unroll
    for (int u = 0; u < 4; u++) {
        int v = tid + u * 256;
        int r = v >> 4, c4 = (v & 15) << 2;
        float4 t = *(const float4*)(F + (size_t)(k0 + r) * DD + d0 + c4);
        ts[r * 65 + c4 + 0] = t.x;
        ts[r * 65 + c4 + 1] = t.y;
        ts[r * 65 + c4 + 2] = t.z;
        ts[r * 65 + c4 + 3] = t.w;
    }
    __syncthreads();
    size_t obase = ((size_t)p * DD + d0) * NN + k0;
#pragma unroll
    for (int u = 0; u < 4; u++) {
        int v = tid + u * 256;
        int d = v >> 4, ks = (v & 15) << 2;
        unsigned short h[4], l[4];
#pragma unroll
        for (int j = 0; j < 4; j++) split1(ts[(ks + j) * 65 + d], h[j], l[j]);
        ull hp = (ull)h[0] | ((ull)h[1] << 16) | ((ull)h[2] << 32) | ((ull)h[3] << 48);
        ull lp = (ull)l[0] | ((ull)l[1] << 16) | ((ull)l[2] << 32) | ((ull)l[3] << 48);
        size_t o = obase + (size_t)d * NN + ks;
        *(ull*)(g_Fhi + o) = hp;
        *(ull*)(g_Flo + o) = lp;
    }
}

// ---------------------------------------------------------------------------
// mma_proj: C[128,128-tile] = E @ F via mma.sync bf16 3-product split.
// grid (4 ntiles, 32 p) x 256. 8 warps x (64x32) warp tiles. kc=64 stages,
// cp.async double buffer, SW128-swizzled smem, ldmatrix fragments.
// Swizzle note: SWZ(row*128 + c) = row*128 + (c ^ ((row&7)<<4)); all fragment
// rows satisfy row&7 == lane&7, so per-kk address = rowoff + ((c0+kk*32)^msk).
// ---------------------------------------------------------------------------
#define STAGE_BYTES 65536   // Ah 16K | Al 16K | Bh 16K | Bl 16K
#define MMA_SMEM (1024 + 2 * STAGE_BYTES)

__global__ void __launch_bounds__(256, 1) mma_proj() {
    extern __shared__ char smraw[];
    unsigned base = (smem_u32(smraw) + 1023) & ~1023u;
    int tid = threadIdx.x, wid = tid >> 5, lane = tid & 31;

    int p = blockIdx.y; int w = p >> 4, b = p & 15;
    int n0 = blockIdx.x * 128;
    const __nv_bfloat16* Eh = g_Ehi + (size_t)p * KK * NN;
    const __nv_bfloat16* El = g_Elo + (size_t)p * KK * NN;
    const __nv_bfloat16* Fh = g_Fhi + ((size_t)p * DD + n0) * NN;
    const __nv_bfloat16* Fl = g_Flo + ((size_t)p * DD + n0) * NN;
    float* C = (w ? g_B : g_A) + (size_t)b * KK * DD + n0;

    int wm = (wid & 1) * 64, wn = (wid >> 1) * 32;

    float acc[4][4][4];
#pragma unroll
    for (int mt = 0; mt < 4; mt++)
#pragma unroll
        for (int nt = 0; nt < 4; nt++)
#pragma unroll
            for (int i = 0; i < 4; i++) acc[mt][nt][i] = 0.0f;

    // per-thread swizzle components
    unsigned msk = (unsigned)((lane & 7) << 4);
    unsigned a_c0 = (unsigned)((lane >> 4) * 16);
    unsigned b_c0 = (unsigned)(((lane >> 3) & 1) * 16);
    unsigned a_row[4], b_row[2];
#pragma unroll
    for (int mt = 0; mt < 4; mt++)
        a_row[mt] = (unsigned)((wm + mt * 16 + (lane & 15)) * 128);
#pragma unroll
    for (int np = 0; np < 2; np++)
        b_row[np] = (unsigned)((wn + np * 16 + ((lane >> 4) << 3) + (lane & 7)) * 128);

    auto issue = [&](int c) {
        unsigned stage = base + (unsigned)(c & 1) * STAGE_BYTES;
        int k0 = c * 64;
#pragma unroll
        for (int u = 0; u < 16; u++) {
            int tile = u >> 2;
            int v = tid + (u & 3) * 256;
            int r = v >> 3, s = v & 7;
            unsigned off = (unsigned)(r * 128 + s * 16);
            unsigned sa = stage + tile * 16384 + SWZ(off);
            const __nv_bfloat16* g;
            if (tile == 0)      g = Eh;
            else if (tile == 1) g = El;
            else if (tile == 2) g = Fh;
            else                g = Fl;
            g += (size_t)r * NN + k0 + s * 8;
            asm volatile("cp.async.cg.shared.global [%0], [%1], 16;"
                         :: "r"(sa), "l"(g) : "memory");
        }
        asm volatile("cp.async.commit_group;" ::: "memory");
    };

    issue(0);
    for (int c = 0; c < 64; c++) {
        if (c < 63) {
            issue(c + 1);
            asm volatile("cp.async.wait_group 1;" ::: "memory");
        } else {
            asm volatile("cp.async.wait_group 0;" ::: "memory");
        }
        __syncthreads();
        unsigned stage = base + (unsigned)(c & 1) * STAGE_BYTES;
        unsigned sAh = stage, sAl = stage + 16384, sBh = stage + 32768, sBl = stage + 49152;
#pragma unroll
        for (int kk = 0; kk < 4; kk++) {
            unsigned ca = (a_c0 + (unsigned)(kk * 32)) ^ msk;
            unsigned cb = (b_c0 + (unsigned)(kk * 32)) ^ msk;
            unsigned ah[4][4], al[4][4], bh[2][4], bl[2][4];
#pragma unroll
            for (int mt = 0; mt < 4; mt++) {
                ldm4(ah[mt], sAh + a_row[mt] + ca);
                ldm4(al[mt], sAl + a_row[mt] + ca);
            }
#pragma unroll
            for (int np = 0; np < 2; np++) {
                ldm4(bh[np], sBh + b_row[np] + cb);
                ldm4(bl[np], sBl + b_row[np] + cb);
            }
#pragma unroll
            for (int mt = 0; mt < 4; mt++)
#pragma unroll
                for (int nt = 0; nt < 4; nt++)
                    mma_bf16(acc[mt][nt], ah[mt], &bh[nt >> 1][(nt & 1) * 2]);
#pragma unroll
            for (int mt = 0; mt < 4; mt++)
#pragma unroll
                for (int nt = 0; nt < 4; nt++)
                    mma_bf16(acc[mt][nt], ah[mt], &bl[nt >> 1][(nt & 1) * 2]);
#pragma unroll
            for (int mt = 0; mt < 4; mt++)
#pragma unroll
                for (int nt = 0; nt < 4; nt++)
                    mma_bf16(acc[mt][nt], al[mt], &bh[nt >> 1][(nt & 1) * 2]);
        }
        __syncthreads();
    }

    // epilogue
#pragma unroll
    for (int mt = 0; mt < 4; mt++) {
#pragma unroll
        for (int nt = 0; nt < 4; nt++) {
            int r0 = wm + mt * 16 + (lane >> 2);
            int c0 = wn + nt * 8 + (lane & 3) * 2;
            float2 v01 = make_float2(acc[mt][nt][0], acc[mt][nt][1]);
            float2 v23 = make_float2(acc[mt][nt][2], acc[mt][nt][3]);
            *(float2*)(C + (size_t)r0 * DD + c0) = v01;
            *(float2*)(C + (size_t)(r0 + 8) * DD + c0) = v23;
        }
    }
}

// ---------------------------------------------------------------------------
// Kernel 2: NT GEMM tile 128x64, K=512 (unchanged)
// ---------------------------------------------------------------------------
#define EST 20
#define PST 20
#define QST 68
__global__ void gemm_nt() {
    int id = blockIdx.y;
    int b = id / 3, mode = id % 3;
    int n0 = blockIdx.x * 64;
    const float* P;
    const float* Q;
    float* C;
    if (mode == 0)      { P = g_A + (size_t)b * KK * DD; Q = P; C = g_S + (size_t)(b * 2 + 0) * KK * KK; }
    else if (mode == 1) { P = g_B + (size_t)b * KK * DD; Q = P; C = g_S + (size_t)(b * 2 + 1) * KK * KK; }
    else                { P = g_B + (size_t)b * KK * DD; Q = g_A + (size_t)b * KK * DD; C = g_R + (size_t)b * KK * KK; }
    float* CT = g_RT + (size_t)b * KK * KK;

    __shared__ float Ps[128 * PST];
    __shared__ float Qs[16 * QST];

    int tid = threadIdx.x;
    int ty = tid >> 4, tx = tid & 15;
    int v0 = tid, v1 = tid + 256;
    int pm0 = v0 >> 2, pc0 = (v0 & 3) << 2;
    int pm1 = v1 >> 2, pc1 = (v1 & 3) << 2;
    int qj = tid >> 2, qc = (tid & 3) << 2;

    ull acc[8][2];
#pragma unroll
    for (int r = 0; r < 8; r++) { acc[r][0] = 0ULL; acc[r][1] = 0ULL; }

    float4 pp0, pp1, pq;
    pp0 = *(const float4*)(P + (size_t)pm0 * DD + pc0);
    pp1 = *(const float4*)(P + (size_t)pm1 * DD + pc1);
    pq  = *(const float4*)(Q + (size_t)(n0 + qj) * DD + qc);

    for (int d0 = 0; d0 < DD; d0 += 16) {
        *(float4*)&Ps[pm0 * PST + pc0] = pp0;
        *(float4*)&Ps[pm1 * PST + pc1] = pp1;
        Qs[(qc + 0) * QST + qj] = pq.x;
        Qs[(qc + 1) * QST + qj] = pq.y;
        Qs[(qc + 2) * QST + qj] = pq.z;
        Qs[(qc + 3) * QST + qj] = pq.w;
        __syncthreads();
        if (d0 + 16 < DD) {
            pp0 = *(const float4*)(P + (size_t)pm0 * DD + d0 + 16 + pc0);
            pp1 = *(const float4*)(P + (size_t)pm1 * DD + d0 + 16 + pc1);
            pq  = *(const float4*)(Q + (size_t)(n0 + qj) * DD + d0 + 16 + qc);
        }
#pragma unroll
        for (int k = 0; k < 16; k++) {
            ull b0 = *(const ull*)&Qs[k * QST + tx * 4];
            ull b1 = *(const ull*)&Qs[k * QST + tx * 4 + 2];
#pragma unroll
            for (int r = 0; r < 8; r++) {
                float av = Ps[(ty * 8 + r) * PST + k];
                ull a2 = pack2(av, av);
                ffma2(acc[r][0], a2, b0);
                ffma2(acc[r][1], a2, b1);
            }
        }
        __syncthreads();
    }
#pragma unroll
    for (int r = 0; r < 8; r++) {
        int m = ty * 8 + r;
#pragma unroll
        for (int c2 = 0; c2 < 2; c2++) {
            int n = n0 + tx * 4 + 2 * c2;
            float lo, hi;
            unpack2(acc[r][c2], lo, hi);
            if (mode < 2) {
                if (m == n) lo += REGC;
                if (m == n + 1) hi += REGC;
            }
            C[m * KK + n] = lo;
            C[m * KK + n + 1] = hi;
            if (mode == 2) {
                CT[n * KK + m] = lo;
                CT[(n + 1) * KK + m] = hi;
            }
        }
    }
}

// ---------------------------------------------------------------------------
// Kernel 3: combined mask (unchanged)
// ---------------------------------------------------------------------------
__global__ void mask_kernel(const float* __restrict__ evx, const float* __restrict__ evy,
                            const float* __restrict__ ax,  const float* __restrict__ ay) {
    int id = blockIdx.x;
    int b = id >> 1, dir = id & 1;
    const float* e1p = (dir ? evy : evx) + b * KK;
    const float* e2p = (dir ? evx : evy) + b * KK;
    const float* a1p = (dir ? ay : ax) + b * KK;
    const float* a2p = (dir ? ax : ay) + b * KK;

    __shared__ float t1[128], u1[128], t2[128], u2[128];
    __shared__ float v1[128], w1[128], v2[128], w2[128];
    __shared__ float red[128];
    __shared__ float sc_main, sc_aux;

    int tid = threadIdx.x;
    float e1 = 0.f, e2 = 0.f, q1 = 0.f, q2 = 0.f;
    if (tid < 128) {
        e1 = fmaxf(e1p[tid], 1e-10f);
        e2 = fmaxf(e2p[tid], 1e-10f);
        q1 = fmaxf(a1p[tid], 1e-10f);
        q2 = fmaxf(a2p[tid], 1e-10f);
        red[tid] = fmaxf(e1, e2);
    }
    __syncthreads();
    for (int off = 64; off; off >>= 1) {
        if (tid < off) red[tid] = fmaxf(red[tid], red[tid + off]);
        __syncthreads();
    }
    if (tid == 0) sc_main = fmaxf(red[0], 1e-10f);
    __syncthreads();
    if (tid < 128) red[tid] = fmaxf(q1, q2);
    __syncthreads();
    for (int off = 64; off; off >>= 1) {
        if (tid < off) red[tid] = fmaxf(red[tid], red[tid + off]);
        __syncthreads();
    }
    if (tid == 0) sc_aux = fmaxf(red[0], 1e-10f);
    __syncthreads();

    if (tid < 128) {
        float r, d;
        r = e1 / sc_main; d = r + 1.0f; t1[tid] = sqrtf(r) / d; u1[tid] = 1.0f / d;
        r = e2 / sc_main; d = r + 1.0f; t2[tid] = sqrtf(r) / d; u2[tid] = 1.0f / d;
        r = q1 / sc_aux;  d = r + 1.0f; v1[tid] = sqrtf(r) / d; w1[tid] = 1.0f / d;
        r = q2 / sc_aux;  d = r + 1.0f; v2[tid] = sqrtf(r) / d; w2[tid] = 1.0f / d;
    }
    __syncthreads();

    float* Dp = g_D + (size_t)id * (KK * KK);
    for (int v = tid; v < KK * KK; v += 256) {
        int i = v >> 7, j = v & 127;
        float mr = t2[i] - t1[j], mi = u2[i] - u1[j];
        float ar = v2[i] - v1[j], ai = w2[i] - w1[j];
        Dp[v] = 100.0f * (mr * mr + mi * mi) + 25.0f * (ar * ar + ai * ai);
    }
}

// ---------------------------------------------------------------------------
// Kernel 4: Blocked Gauss-Jordan inversion (unchanged)
// ---------------------------------------------------------------------------
#define MST 132
#define CST 36
#define TST 36
#define INV_SMEM ((128 * MST + 128 * CST + 32 * TST) * 4)

__global__ void invert_blocked() {
    extern __shared__ float sm[];
    float* M  = sm;
    float* Cs = sm + 128 * MST;
    float* T  = Cs + 128 * CST;
    int mat = blockIdx.x;
    const float* S = g_S + (size_t)mat * KK * KK;
    float* Si = g_Sinv + (size_t)mat * KK * KK;
    int tid = threadIdx.x;
    int ty = tid >> 4, tx = tid & 15;

#pragma unroll
    for (int u = 0; u < 16; u++) {
        int v = tid + u * 256;
        int m = v >> 5, c4 = (v & 31) << 2;
        *(float4*)(M + m * MST + c4) = *(const float4*)(S + m * 128 + c4);
    }
    __syncthreads();

    for (int p = 0; p < 4; p++) {
        int p0 = p * 32;
#pragma unroll
        for (int u = 0; u < 4; u++) {
            int v = tid + u * 256;
            int i = v >> 3, q4 = (v & 7) << 2;
            *(float4*)(Cs + i * CST + q4) = *(const float4*)(M + i * MST + p0 + q4);
        }
        {
            int q = tid >> 3, r4 = (tid & 7) << 2;
            *(float4*)(T + q * TST + r4) = *(const float4*)(M + (p0 + q) * MST + p0 + r4);
        }
        __syncthreads();

        {
            int q = tid >> 3, rb = (tid & 7) << 2;
            for (int j = 0; j < 32; j++) {
                float pivinv = 1.0f / T[j * TST + j];
                float f = T[q * TST + j];
                float pr[4], cu[4];
#pragma unroll
                for (int a = 0; a < 4; a++) { pr[a] = T[j * TST + rb + a]; cu[a] = T[q * TST + rb + a]; }
                __syncthreads();
                float o[4];
                if (q == j) {
#pragma unroll
                    for (int a = 0; a < 4; a++) o[a] = (rb + a == j) ? pivinv : pr[a] * pivinv;
                } else {
                    float fp = f * pivinv;
#pragma unroll
                    for (int a = 0; a < 4; a++) o[a] = (rb + a == j) ? -fp : cu[a] - fp * pr[a];
                }
#pragma unroll
                for (int a = 0; a < 4; a++) T[q * TST + rb + a] = o[a];
                __syncthreads();
            }
        }

        {
            int qr = tid >> 3;
            int cb = (tid & 7) << 4;
            float out[16];
#pragma unroll
            for (int a = 0; a < 16; a++) out[a] = 0.0f;
            for (int r = 0; r < 32; r++) {
                float tq = T[qr * TST + r];
                const float* Mr = M + (p0 + r) * MST + cb;
#pragma unroll
                for (int a = 0; a < 16; a += 4) {
                    float4 mv = *(const float4*)(Mr + a);
                    out[a + 0] += tq * mv.x;
                    out[a + 1] += tq * mv.y;
                    out[a + 2] += tq * mv.z;
                    out[a + 3] += tq * mv.w;
                }
            }
            __syncthreads();
#pragma unroll
            for (int a = 0; a < 16; a++) {
                int l = cb + a;
                float vv = (l >= p0 && l < p0 + 32) ? T[qr * TST + (l - p0)] : out[a];
                M[(p0 + qr) * MST + l] = vv;
            }
            __syncthreads();
        }

        {
            ull acc[6][4];
#pragma unroll
            for (int r = 0; r < 6; r++)
#pragma unroll
                for (int c = 0; c < 4; c++) acc[r][c] = 0ULL;
            for (int q = 0; q < 32; q++) {
                const float* Mp = M + (p0 + q) * MST + tx * 8;
                ull b0 = *(const ull*)(Mp + 0);
                ull b1 = *(const ull*)(Mp + 2);
                ull b2 = *(const ull*)(Mp + 4);
                ull b3 = *(const ull*)(Mp + 6);
#pragma unroll
                for (int r = 0; r < 6; r++) {
                    int z = ty + 16 * r;
                    int i = (z < p0) ? z : z + 32;
                    float av = Cs[i * CST + q];
                    ull a2 = pack2(av, av);
                    ffma2(acc[r][0], a2, b0);
                    ffma2(acc[r][1], a2, b1);
                    ffma2(acc[r][2], a2, b2);
                    ffma2(acc[r][3], a2, b3);
                }
            }
#pragma unroll
            for (int r = 0; r < 6; r++) {
                int z = ty + 16 * r;
                int i = (z < p0) ? z : z + 32;
#pragma unroll
                for (int c = 0; c < 4; c++) {
                    int l = tx * 8 + 2 * c;
                    float lo, hi;
                    unpack2(acc[r][c], lo, hi);
                    float* Mp = M + i * MST + l;
                    bool inP0 = (l >= p0 && l < p0 + 32);
                    bool inP1 = (l + 1 >= p0 && l + 1 < p0 + 32);
                    float o0 = (inP0 ? 0.0f : Mp[0]) - lo;
                    float o1 = (inP1 ? 0.0f : Mp[1]) - hi;
                    Mp[0] = o0;
                    Mp[1] = o1;
                }
            }
            __syncthreads();
        }
    }

#pragma unroll
    for (int u = 0; u < 16; u++) {
        int v = tid + u * 256;
        int m = v >> 5, c4 = (v & 31) << 2;
        *(float4*)(Si + m * 128 + c4) = *(const float4*)(M + m * MST + c4);
    }
}

// ---------------------------------------------------------------------------
// Kernel 5: solve GEMM (unchanged)
// ---------------------------------------------------------------------------
#define SST 68
__global__ void solve_gemm(float* __restrict__ out, int mode) {
    int id = blockIdx.y;
    int b = id >> 1, dir = id & 1;
    int n0 = blockIdx.x * 64;
    const float* Si = g_Sinv + (size_t)id * (KK * KK);
    const float* Dm = g_D + (size_t)id * (KK * KK);
    const float* Rb = (dir ? g_RT : g_R) + (size_t)b * (KK * KK);
    const float* Xp = (mode == 1 ? g_X0 : g_X1) + (size_t)id * (KK * KK);
    const float* base = g_X0 + (size_t)id * (KK * KK);
    float* Cout;
    if (mode == 0)      Cout = g_X0 + (size_t)id * (KK * KK);
    else if (mode == 1) Cout = g_X1 + (size_t)id * (KK * KK);
    else                Cout = out + (size_t)(dir ? BB * KK * KK : 0) + (size_t)b * (KK * KK);

    __shared__ float Ts[128 * EST];
    __shared__ float Ss[16 * SST];

    int tid = threadIdx.x;
    int ty = tid >> 4, tx = tid & 15;
    int v0 = tid, v1 = tid + 256;
    int tm0 = v0 >> 2, tc0 = (v0 & 3) << 2;
    int tm1 = v1 >> 2, tc1 = (v1 & 3) << 2;
    int sk = tid >> 4, sc = (tid & 15) << 2;

    ull acc[8][2];
#pragma unroll
    for (int r = 0; r < 8; r++) { acc[r][0] = 0ULL; acc[r][1] = 0ULL; }

    for (int k0 = 0; k0 < KK; k0 += 16) {
        if (mode == 0) {
            *(float4*)&Ts[tm0 * EST + tc0] = *(const float4*)(Rb + tm0 * 128 + k0 + tc0);
            *(float4*)&Ts[tm1 * EST + tc1] = *(const float4*)(Rb + tm1 * 128 + k0 + tc1);
        } else {
            float4 d0 = *(const float4*)(Dm + tm0 * 128 + k0 + tc0);
            float4 x0 = *(const float4*)(Xp + tm0 * 128 + k0 + tc0);
            float4 d1 = *(const float4*)(Dm + tm1 * 128 + k0 + tc1);
            float4 x1 = *(const float4*)(Xp + tm1 * 128 + k0 + tc1);
            float4 o0 = make_float4(d0.x * x0.x, d0.y * x0.y, d0.z * x0.z, d0.w * x0.w);
            float4 o1 = make_float4(d1.x * x1.x, d1.y * x1.y, d1.z * x1.z, d1.w * x1.w);
            *(float4*)&Ts[tm0 * EST + tc0] = o0;
            *(float4*)&Ts[tm1 * EST + tc1] = o1;
        }
        *(float4*)&Ss[sk * SST + sc] = *(const float4*)(Si + (size_t)(k0 + sk) * 128 + n0 + sc);
        __syncthreads();
#pragma unroll
        for (int k = 0; k < 16; k++) {
            ull b0 = *(const ull*)&Ss[k * SST + tx * 4];
            ull b1 = *(const ull*)&Ss[k * SST + tx * 4 + 2];
#pragma unroll
            for (int r = 0; r < 8; r++) {
                float av = Ts[(ty * 8 + r) * EST + k];
                ull a2 = pack2(av, av);
                ffma2(acc[r][0], a2, b0);
                ffma2(acc[r][1], a2, b1);
            }
        }
        __syncthreads();
    }
#pragma unroll
    for (int r = 0; r < 8; r++) {
        int m = ty * 8 + r;
#pragma unroll
        for (int c2 = 0; c2 < 2; c2++) {
            int n = n0 + tx * 4 + 2 * c2;
            int idx = m * 128 + n;
            float lo, hi;
            unpack2(acc[r][c2], lo, hi);
            if (mode != 0) {
                lo = base[idx] - lo;
                hi = base[idx + 1] - hi;
            }
            Cout[idx] = lo;
            Cout[idx + 1] = hi;
        }
    }
}

// ---------------------------------------------------------------------------
extern "C" void kernel_launch(void* const* d_in, const int* in_sizes, int n_in,
                              void* d_out, int out_size) {
    const float* feat_x  = (const float*)d_in[0];
    const float* feat_y  = (const float*)d_in[1];
    const float* evals_x = (const float*)d_in[2];
    const float* evals_y = (const float*)d_in[3];
    const float* evecs_x = (const float*)d_in[4];
    const float* evecs_y = (const float*)d_in[5];
    const float* aux_x   = (const float*)d_in[6];
    const float* aux_y   = (const float*)d_in[7];
    float* out = (float*)d_out;

    split_E<<<dim3(8192, 2), 256>>>(evecs_x, evecs_y);
    split_F<<<dim3(64, 8, 32), 256>>>(feat_x, feat_y);

    cudaFuncSetAttribute(mma_proj, cudaFuncAttributeMaxDynamicSharedMemorySize, MMA_SMEM);
    mma_proj<<<dim3(4, 32), 256, MMA_SMEM>>>();

    gemm_nt<<<dim3(2, 48), 256>>>();
    mask_kernel<<<32, 256>>>(evals_x, evals_y, aux_x, aux_y);
    cudaFuncSetAttribute(invert_blocked, cudaFuncAttributeMaxDynamicSharedMemorySize, INV_SMEM);
    invert_blocked<<<32, 256, INV_SMEM>>>();
    solve_gemm<<<dim3(2, 32), 256>>>(out, 0);
    solve_gemm<<<dim3(2, 32), 256>>>(out, 1);
    solve_gemm<<<dim3(2, 32), 256>>>(out, 2);
}

// round 7
// speedup vs baseline: 2.8917x; 1.0441x over previous
#include <cuda_runtime.h>
#include <cuda_bf16.h>

#define BB 16
#define NN 4096
#define DD 512
#define KK 128
#define REGC 1e-6f

typedef unsigned long long ull;

__device__ __forceinline__ ull pack2(float x, float y) {
    ull r; asm("mov.b64 %0, {%1, %2};" : "=l"(r) : "f"(x), "f"(y)); return r;
}
__device__ __forceinline__ void unpack2(ull v, float& lo, float& hi) {
    asm("mov.b64 {%0, %1}, %2;" : "=f"(lo), "=f"(hi) : "l"(v));
}
__device__ __forceinline__ void ffma2(ull& d, ull a, ull b) {
    asm("fma.rn.f32x2 %0, %1, %2, %0;" : "+l"(d) : "l"(a), "l"(b));
}
__device__ __forceinline__ unsigned smem_u32(const void* p) {
    unsigned a;
    asm("{ .reg .u64 t; cvta.to.shared.u64 t, %1; cvt.u32.u64 %0, t; }" : "=r"(a) : "l"(p));
    return a;
}
__device__ __forceinline__ void ldm4(unsigned* r, unsigned addr) {
    asm volatile("ldmatrix.sync.aligned.m8n8.x4.shared.b16 {%0,%1,%2,%3}, [%4];"
                 : "=r"(r[0]), "=r"(r[1]), "=r"(r[2]), "=r"(r[3]) : "r"(addr));
}
__device__ __forceinline__ void mma_bf16(float* d, const unsigned* a, const unsigned* b) {
    asm volatile(
        "mma.sync.aligned.m16n8k16.row.col.f32.bf16.bf16.f32 "
        "{%0,%1,%2,%3}, {%4,%5,%6,%7}, {%8,%9}, {%0,%1,%2,%3};"
        : "+f"(d[0]), "+f"(d[1]), "+f"(d[2]), "+f"(d[3])
        : "r"(a[0]), "r"(a[1]), "r"(a[2]), "r"(a[3]), "r"(b[0]), "r"(b[1]));
}
#define SWZ(o) ((o) ^ (((o) >> 3) & 0x70))

// Scratch
__device__ float g_A[BB * KK * DD];
__device__ float g_B[BB * KK * DD];
__device__ float g_S[2 * BB * KK * KK];
__device__ float g_Sinv[2 * BB * KK * KK];
__device__ float g_R[BB * KK * KK];
__device__ float g_RT[BB * KK * KK];
__device__ float g_D[2 * BB * KK * KK];
__device__ float g_X0[2 * BB * KK * KK];
__device__ float g_X1[2 * BB * KK * KK];
// bf16 split operands: E [p=w*16+b][128][4096], F transposed [p][512][4096]
__device__ __nv_bfloat16 g_Ehi[2 * BB * KK * NN];
__device__ __nv_bfloat16 g_Elo[2 * BB * KK * NN];
__device__ __nv_bfloat16 g_Fhi[2 * BB * DD * NN];
__device__ __nv_bfloat16 g_Flo[2 * BB * DD * NN];
// bf16 split of projected A/B: [sel(0=A,1=B)][b][128][512]
__device__ __nv_bfloat16 g_ABhi[2 * BB * KK * DD];
__device__ __nv_bfloat16 g_ABlo[2 * BB * KK * DD];

__device__ __forceinline__ void split1(float x, unsigned short& h, unsigned short& l) {
    __nv_bfloat16 hb = __float2bfloat16_rn(x);
    float r = x - __bfloat162float(hb);
    __nv_bfloat16 lb = __float2bfloat16_rn(r);
    h = __bfloat16_as_ushort(hb);
    l = __bfloat16_as_ushort(lb);
}

// ---------------------------------------------------------------------------
// split_E: evecs fp32 [b][128][4096] -> g_Ehi/g_Elo bf16, same layout
// ---------------------------------------------------------------------------
__global__ void split_E(const float* __restrict__ ex, const float* __restrict__ ey) {
    int w = blockIdx.y;
    const float* E = w ? ey : ex;
    size_t i4 = (size_t)blockIdx.x * 256 + threadIdx.x;
    float4 t = *((const float4*)E + i4);
    unsigned short h0, h1, h2, h3, l0, l1, l2, l3;
    split1(t.x, h0, l0); split1(t.y, h1, l1); split1(t.z, h2, l2); split1(t.w, h3, l3);
    ull hp = (ull)h0 | ((ull)h1 << 16) | ((ull)h2 << 32) | ((ull)h3 << 48);
    ull lp = (ull)l0 | ((ull)l1 << 16) | ((ull)l2 << 32) | ((ull)l3 << 48);
    size_t o = (size_t)w * (BB * KK * NN) + i4 * 4;
    *(ull*)(g_Ehi + o) = hp;
    *(ull*)(g_Elo + o) = lp;
}

// ---------------------------------------------------------------------------
// split_F: feat fp32 [b][4096][512] -> transposed bf16 [p][512][4096]
// ---------------------------------------------------------------------------
__global__ void split_F(const float* __restrict__ fx, const float* __restrict__ fy) {
    int p = blockIdx.z; int w = p >> 4, b = p & 15;
    const float* F = (w ? fy : fx) + (size_t)b * NN * DD;
    int k0 = blockIdx.x * 64, d0 = blockIdx.y * 64;
    __shared__ float ts[64 * 65];
    int tid = threadIdx.x;
#pragma unroll
    for (int u = 0; u < 4; u++) {
        int v = tid + u * 256;
        int r = v >> 4, c4 = (v & 15) << 2;
        float4 t = *(const float4*)(F + (size_t)(k0 + r) * DD + d0 + c4);
        ts[r * 65 + c4 + 0] = t.x;
        ts[r * 65 + c4 + 1] = t.y;
        ts[r * 65 + c4 + 2] = t.z;
        ts[r * 65 + c4 + 3] = t.w;
    }
    __syncthreads();
    size_t obase = ((size_t)p * DD + d0) * NN + k0;
#pragma unroll
    for (int u = 0; u < 4; u++) {
        int v = tid + u * 256;
        int d = v >> 4, ks = (v & 15) << 2;
        unsigned short h[4], l[4];
#pragma unroll
        for (int j = 0; j < 4; j++) split1(ts[(ks + j) * 65 + d], h[j], l[j]);
        ull hp = (ull)h[0] | ((ull)h[1] << 16) | ((ull)h[2] << 32) | ((ull)h[3] << 48);
        ull lp = (ull)l[0] | ((ull)l[1] << 16) | ((ull)l[2] << 32) | ((ull)l[3] << 48);
        size_t o = obase + (size_t)d * NN + ks;
        *(ull*)(g_Fhi + o) = hp;
        *(ull*)(g_Flo + o) = lp;
    }
}

// ---------------------------------------------------------------------------
// split_AB: g_A/g_B fp32 [b][128][512] -> g_ABhi/lo bf16, same layout
// grid (1024, 2) x 256
// ---------------------------------------------------------------------------
__global__ void split_AB() {
    int sel = blockIdx.y;
    const float* src = sel ? g_B : g_A;
    size_t i4 = (size_t)blockIdx.x * 256 + threadIdx.x;
    float4 t = *((const float4*)src + i4);
    unsigned short h0, h1, h2, h3, l0, l1, l2, l3;
    split1(t.x, h0, l0); split1(t.y, h1, l1); split1(t.z, h2, l2); split1(t.w, h3, l3);
    ull hp = (ull)h0 | ((ull)h1 << 16) | ((ull)h2 << 32) | ((ull)h3 << 48);
    ull lp = (ull)l0 | ((ull)l1 << 16) | ((ull)l2 << 32) | ((ull)l3 << 48);
    size_t o = (size_t)sel * (BB * KK * DD) + i4 * 4;
    *(ull*)(g_ABhi + o) = hp;
    *(ull*)(g_ABlo + o) = lp;
}

// ---------------------------------------------------------------------------
// mma_proj: C[128,128-tile] = E @ F via mma.sync bf16 3-product split.
// 3-stage cp.async pipeline, ONE __syncthreads per chunk.
// ---------------------------------------------------------------------------
#define STAGE_BYTES 65536   // Ah 16K | Al 16K | Bh 16K | Bl 16K
#define MMA_SMEM (1024 + 3 * STAGE_BYTES)

__global__ void __launch_bounds__(256, 1) mma_proj() {
    extern __shared__ char smraw[];
    unsigned base = (smem_u32(smraw) + 1023) & ~1023u;
    int tid = threadIdx.x, wid = tid >> 5, lane = tid & 31;

    int p = blockIdx.y; int w = p >> 4, b = p & 15;
    int n0 = blockIdx.x * 128;
    const __nv_bfloat16* Eh = g_Ehi + (size_t)p * KK * NN;
    const __nv_bfloat16* El = g_Elo + (size_t)p * KK * NN;
    const __nv_bfloat16* Fh = g_Fhi + ((size_t)p * DD + n0) * NN;
    const __nv_bfloat16* Fl = g_Flo + ((size_t)p * DD + n0) * NN;
    float* C = (w ? g_B : g_A) + (size_t)b * KK * DD + n0;

    int wm = (wid & 1) * 64, wn = (wid >> 1) * 32;

    float acc[4][4][4];
#pragma unroll
    for (int mt = 0; mt < 4; mt++)
#pragma unroll
        for (int nt = 0; nt < 4; nt++)
#pragma unroll
            for (int i = 0; i < 4; i++) acc[mt][nt][i] = 0.0f;

    unsigned msk = (unsigned)((lane & 7) << 4);
    unsigned a_c0 = (unsigned)((lane >> 4) * 16);
    unsigned b_c0 = (unsigned)(((lane >> 3) & 1) * 16);
    unsigned a_row[4], b_row[2];
#pragma unroll
    for (int mt = 0; mt < 4; mt++)
        a_row[mt] = (unsigned)((wm + mt * 16 + (lane & 15)) * 128);
#pragma unroll
    for (int np = 0; np < 2; np++)
        b_row[np] = (unsigned)((wn + np * 16 + ((lane >> 4) << 3) + (lane & 7)) * 128);

    auto issue = [&](int c) {
        unsigned stage = base + 1024 + (unsigned)(c % 3) * STAGE_BYTES;
        int k0 = c * 64;
#pragma unroll
        for (int u = 0; u < 16; u++) {
            int tile = u >> 2;
            int v = tid + (u & 3) * 256;
            int r = v >> 3, s = v & 7;
            unsigned off = (unsigned)(r * 128 + s * 16);
            unsigned sa = stage + tile * 16384 + SWZ(off);
            const __nv_bfloat16* g;
            if (tile == 0)      g = Eh;
            else if (tile == 1) g = El;
            else if (tile == 2) g = Fh;
            else                g = Fl;
            g += (size_t)r * NN + k0 + s * 8;
            asm volatile("cp.async.cg.shared.global [%0], [%1], 16;"
                         :: "r"(sa), "l"(g) : "memory");
        }
        asm volatile("cp.async.commit_group;" ::: "memory");
    };

    issue(0);
    issue(1);
    for (int c = 0; c < 64; c++) {
        if (c < 63)
            asm volatile("cp.async.wait_group 1;" ::: "memory");
        else
            asm volatile("cp.async.wait_group 0;" ::: "memory");
        __syncthreads();
        if (c + 2 < 64) issue(c + 2);   // buffer (c+2)%3 freed by sync above
        unsigned stage = base + 1024 + (unsigned)(c % 3) * STAGE_BYTES;
        unsigned sAh = stage, sAl = stage + 16384, sBh = stage + 32768, sBl = stage + 49152;
#pragma unroll
        for (int kk = 0; kk < 4; kk++) {
            unsigned ca = (a_c0 + (unsigned)(kk * 32)) ^ msk;
            unsigned cb = (b_c0 + (unsigned)(kk * 32)) ^ msk;
            unsigned ah[4][4], al[4][4], bh[2][4], bl[2][4];
#pragma unroll
            for (int mt = 0; mt < 4; mt++) {
                ldm4(ah[mt], sAh + a_row[mt] + ca);
                ldm4(al[mt], sAl + a_row[mt] + ca);
            }
#pragma unroll
            for (int np = 0; np < 2; np++) {
                ldm4(bh[np], sBh + b_row[np] + cb);
                ldm4(bl[np], sBl + b_row[np] + cb);
            }
#pragma unroll
            for (int mt = 0; mt < 4; mt++)
#pragma unroll
                for (int nt = 0; nt < 4; nt++)
                    mma_bf16(acc[mt][nt], ah[mt], &bh[nt >> 1][(nt & 1) * 2]);
#pragma unroll
            for (int mt = 0; mt < 4; mt++)
#pragma unroll
                for (int nt = 0; nt < 4; nt++)
                    mma_bf16(acc[mt][nt], ah[mt], &bl[nt >> 1][(nt & 1) * 2]);
#pragma unroll
            for (int mt = 0; mt < 4; mt++)
#pragma unroll
                for (int nt = 0; nt < 4; nt++)
                    mma_bf16(acc[mt][nt], al[mt], &bh[nt >> 1][(nt & 1) * 2]);
        }
    }

#pragma unroll
    for (int mt = 0; mt < 4; mt++) {
#pragma unroll
        for (int nt = 0; nt < 4; nt++) {
            int r0 = wm + mt * 16 + (lane >> 2);
            int c0 = wn + nt * 8 + (lane & 3) * 2;
            float2 v01 = make_float2(acc[mt][nt][0], acc[mt][nt][1]);
            float2 v23 = make_float2(acc[mt][nt][2], acc[mt][nt][3]);
            *(float2*)(C + (size_t)r0 * DD + c0) = v01;
            *(float2*)(C + (size_t)(r0 + 8) * DD + c0) = v23;
        }
    }
}

// ---------------------------------------------------------------------------
// gemm_nt_hmma: S_x/S_y/R via HMMA on bf16-split A/B. 48 CTAs, 128x128, K=512.
// Same fragment scheme as mma_proj; gmem row stride DD.
// ---------------------------------------------------------------------------
#define NT_SMEM (1024 + 3 * STAGE_BYTES)
__global__ void __launch_bounds__(256, 1) gemm_nt_hmma() {
    extern __shared__ char smraw[];
    unsigned base = (smem_u32(smraw) + 1023) & ~1023u;
    int tid = threadIdx.x, wid = tid >> 5, lane = tid & 31;

    int id = blockIdx.x;
    int b = id / 3, mode = id % 3;
    size_t offA = (size_t)b * KK * DD;
    size_t offB = (size_t)(BB + b) * KK * DD;
    size_t offP = (mode == 0) ? offA : offB;                 // rows (M)
    size_t offQ = (mode == 1) ? offB : offA;                 // cols (N)
    const __nv_bfloat16* Ph = g_ABhi + offP;
    const __nv_bfloat16* Pl = g_ABlo + offP;
    const __nv_bfloat16* Qh = g_ABhi + offQ;
    const __nv_bfloat16* Ql = g_ABlo + offQ;
    float* C = (mode < 2) ? g_S + (size_t)(b * 2 + mode) * KK * KK
                          : g_R + (size_t)b * KK * KK;
    float* CT = g_RT + (size_t)b * KK * KK;

    int wm = (wid & 1) * 64, wn = (wid >> 1) * 32;

    float acc[4][4][4];
#pragma unroll
    for (int mt = 0; mt < 4; mt++)
#pragma unroll
        for (int nt = 0; nt < 4; nt++)
#pragma unroll
            for (int i = 0; i < 4; i++) acc[mt][nt][i] = 0.0f;

    unsigned msk = (unsigned)((lane & 7) << 4);
    unsigned a_c0 = (unsigned)((lane >> 4) * 16);
    unsigned b_c0 = (unsigned)(((lane >> 3) & 1) * 16);
    unsigned a_row[4], b_row[2];
#pragma unroll
    for (int mt = 0; mt < 4; mt++)
        a_row[mt] = (unsigned)((wm + mt * 16 + (lane & 15)) * 128);
#pragma unroll
    for (int np = 0; np < 2; np++)
        b_row[np] = (unsigned)((wn + np * 16 + ((lane >> 4) << 3) + (lane & 7)) * 128);

    auto issue = [&](int c) {
        unsigned stage = base + 1024 + (unsigned)(c % 3) * STAGE_BYTES;
        int k0 = c * 64;
#pragma unroll
        for (int u = 0; u < 16; u++) {
            int tile = u >> 2;
            int v = tid + (u & 3) * 256;
            int r = v >> 3, s = v & 7;
            unsigned off = (unsigned)(r * 128 + s * 16);
            unsigned sa = stage + tile * 16384 + SWZ(off);
            const __nv_bfloat16* g;
            if (tile == 0)      g = Ph;
            else if (tile == 1) g = Pl;
            else if (tile == 2) g = Qh;
            else                g = Ql;
            g += (size_t)r * DD + k0 + s * 8;
            asm volatile("cp.async.cg.shared.global [%0], [%1], 16;"
                         :: "r"(sa), "l"(g) : "memory");
        }
        asm volatile("cp.async.commit_group;" ::: "memory");
    };

    issue(0);
    issue(1);
    for (int c = 0; c < 8; c++) {
        if (c < 7)
            asm volatile("cp.async.wait_group 1;" ::: "memory");
        else
            asm volatile("cp.async.wait_group 0;" ::: "memory");
        __syncthreads();
        if (c + 2 < 8) issue(c + 2);
        unsigned stage = base + 1024 + (unsigned)(c % 3) * STAGE_BYTES;
        unsigned sAh = stage, sAl = stage + 16384, sBh = stage + 32768, sBl = stage + 49152;
#pragma unroll
        for (int kk = 0; kk < 4; kk++) {
            unsigned ca = (a_c0 + (unsigned)(kk * 32)) ^ msk;
            unsigned cb = (b_c0 + (unsigned)(kk * 32)) ^ msk;
            unsigned ah[4][4], al[4][4], bh[2][4], bl[2][4];
#pragma unroll
            for (int mt = 0; mt < 4; mt++) {
                ldm4(ah[mt], sAh + a_row[mt] + ca);
                ldm4(al[mt], sAl + a_row[mt] + ca);
            }
#pragma unroll
            for (int np = 0; np < 2; np++) {
                ldm4(bh[np], sBh + b_row[np] + cb);
                ldm4(bl[np], sBl + b_row[np] + cb);
            }
#pragma unroll
            for (int mt = 0; mt < 4; mt++)
#pragma unroll
                for (int nt = 0; nt < 4; nt++)
                    mma_bf16(acc[mt][nt], ah[mt], &bh[nt >> 1][(nt & 1) * 2]);
#pragma unroll
            for (int mt = 0; mt < 4; mt++)
#pragma unroll
                for (int nt = 0; nt < 4; nt++)
                    mma_bf16(acc[mt][nt], ah[mt], &bl[nt >> 1][(nt & 1) * 2]);
#pragma unroll
            for (int mt = 0; mt < 4; mt++)
#pragma unroll
                for (int nt = 0; nt < 4; nt++)
                    mma_bf16(acc[mt][nt], al[mt], &bh[nt >> 1][(nt & 1) * 2]);
        }
    }

#pragma unroll
    for (int mt = 0; mt < 4; mt++) {
#pragma unroll
        for (int nt = 0; nt < 4; nt++) {
            int r0 = wm + mt * 16 + (lane >> 2);
            int c0 = wn + nt * 8 + (lane & 3) * 2;
            float v0 = acc[mt][nt][0], v1 = acc[mt][nt][1];
            float v2 = acc[mt][nt][2], v3 = acc[mt][nt][3];
            if (mode < 2) {
                if (r0 == c0) v0 += REGC;
                if (r0 == c0 + 1) v1 += REGC;
                if (r0 + 8 == c0) v2 += REGC;
                if (r0 + 8 == c0 + 1) v3 += REGC;
            }
            C[r0 * KK + c0] = v0;
            C[r0 * KK + c0 + 1] = v1;
            C[(r0 + 8) * KK + c0] = v2;
            C[(r0 + 8) * KK + c0 + 1] = v3;
            if (mode == 2) {
                CT[c0 * KK + r0] = v0;
                CT[(c0 + 1) * KK + r0] = v1;
                CT[c0 * KK + r0 + 8] = v2;
                CT[(c0 + 1) * KK + r0 + 8] = v3;
            }
        }
    }
}

// ---------------------------------------------------------------------------
// Kernel 3: combined mask (unchanged)
// ---------------------------------------------------------------------------
__global__ void mask_kernel(const float* __restrict__ evx, const float* __restrict__ evy,
                            const float* __restrict__ ax,  const float* __restrict__ ay) {
    int id = blockIdx.x;
    int b = id >> 1, dir = id & 1;
    const float* e1p = (dir ? evy : evx) + b * KK;
    const float* e2p = (dir ? evx : evy) + b * KK;
    const float* a1p = (dir ? ay : ax) + b * KK;
    const float* a2p = (dir ? ax : ay) + b * KK;

    __shared__ float t1[128], u1[128], t2[128], u2[128];
    __shared__ float v1[128], w1[128], v2[128], w2[128];
    __shared__ float red[128];
    __shared__ float sc_main, sc_aux;

    int tid = threadIdx.x;
    float e1 = 0.f, e2 = 0.f, q1 = 0.f, q2 = 0.f;
    if (tid < 128) {
        e1 = fmaxf(e1p[tid], 1e-10f);
        e2 = fmaxf(e2p[tid], 1e-10f);
        q1 = fmaxf(a1p[tid], 1e-10f);
        q2 = fmaxf(a2p[tid], 1e-10f);
        red[tid] = fmaxf(e1, e2);
    }
    __syncthreads();
    for (int off = 64; off; off >>= 1) {
        if (tid < off) red[tid] = fmaxf(red[tid], red[tid + off]);
        __syncthreads();
    }
    if (tid == 0) sc_main = fmaxf(red[0], 1e-10f);
    __syncthreads();
    if (tid < 128) red[tid] = fmaxf(q1, q2);
    __syncthreads();
    for (int off = 64; off; off >>= 1) {
        if (tid < off) red[tid] = fmaxf(red[tid], red[tid + off]);
        __syncthreads();
    }
    if (tid == 0) sc_aux = fmaxf(red[0], 1e-10f);
    __syncthreads();

    if (tid < 128) {
        float r, d;
        r = e1 / sc_main; d = r + 1.0f; t1[tid] = sqrtf(r) / d; u1[tid] = 1.0f / d;
        r = e2 / sc_main; d = r + 1.0f; t2[tid] = sqrtf(r) / d; u2[tid] = 1.0f / d;
        r = q1 / sc_aux;  d = r + 1.0f; v1[tid] = sqrtf(r) / d; w1[tid] = 1.0f / d;
        r = q2 / sc_aux;  d = r + 1.0f; v2[tid] = sqrtf(r) / d; w2[tid] = 1.0f / d;
    }
    __syncthreads();

    float* Dp = g_D + (size_t)id * (KK * KK);
    for (int v = tid; v < KK * KK; v += 256) {
        int i = v >> 7, j = v & 127;
        float mr = t2[i] - t1[j], mi = u2[i] - u1[j];
        float ar = v2[i] - v1[j], ai = w2[i] - w1[j];
        Dp[v] = 100.0f * (mr * mr + mi * mi) + 25.0f * (ar * ar + ai * ai);
    }
}

// ---------------------------------------------------------------------------
// Kernel 4: Blocked Gauss-Jordan inversion (unchanged)
// ---------------------------------------------------------------------------
#define MST 132
#define CST 36
#define TST 36
#define INV_SMEM ((128 * MST + 128 * CST + 32 * TST) * 4)

__global__ void invert_blocked() {
    extern __shared__ float sm[];
    float* M  = sm;
    float* Cs = sm + 128 * MST;
    float* T  = Cs + 128 * CST;
    int mat = blockIdx.x;
    const float* S = g_S + (size_t)mat * KK * KK;
    float* Si = g_Sinv + (size_t)mat * KK * KK;
    int tid = threadIdx.x;
    int ty = tid >> 4, tx = tid & 15;

#pragma unroll
    for (int u = 0; u < 16; u++) {
        int v = tid + u * 256;
        int m = v >> 5, c4 = (v & 31) << 2;
        *(float4*)(M + m * MST + c4) = *(const float4*)(S + m * 128 + c4);
    }
    __syncthreads();

    for (int p = 0; p < 4; p++) {
        int p0 = p * 32;
#pragma unroll
        for (int u = 0; u < 4; u++) {
            int v = tid + u * 256;
            int i = v >> 3, q4 = (v & 7) << 2;
            *(float4*)(Cs + i * CST + q4) = *(const float4*)(M + i * MST + p0 + q4);
        }
        {
            int q = tid >> 3, r4 = (tid & 7) << 2;
            *(float4*)(T + q * TST + r4) = *(const float4*)(M + (p0 + q) * MST + p0 + r4);
        }
        __syncthreads();

        {
            int q = tid >> 3, rb = (tid & 7) << 2;
            for (int j = 0; j < 32; j++) {
                float pivinv = 1.0f / T[j * TST + j];
                float f = T[q * TST + j];
                float pr[4], cu[4];
#pragma unroll
                for (int a = 0; a < 4; a++) { pr[a] = T[j * TST + rb + a]; cu[a] = T[q * TST + rb + a]; }
                __syncthreads();
                float o[4];
                if (q == j) {
#pragma unroll
                    for (int a = 0; a < 4; a++) o[a] = (rb + a == j) ? pivinv : pr[a] * pivinv;
                } else {
                    float fp = f * pivinv;
#pragma unroll
                    for (int a = 0; a < 4; a++) o[a] = (rb + a == j) ? -fp : cu[a] - fp * pr[a];
                }
#pragma unroll
                for (int a = 0; a < 4; a++) T[q * TST + rb + a] = o[a];
                __syncthreads();
            }
        }

        {
            int qr = tid >> 3;
            int cb = (tid & 7) << 4;
            float out[16];
#pragma unroll
            for (int a = 0; a < 16; a++) out[a] = 0.0f;
            for (int r = 0; r < 32; r++) {
                float tq = T[qr * TST + r];
                const float* Mr = M + (p0 + r) * MST + cb;
#pragma unroll
                for (int a = 0; a < 16; a += 4) {
                    float4 mv = *(const float4*)(Mr + a);
                    out[a + 0] += tq * mv.x;
                    out[a + 1] += tq * mv.y;
                    out[a + 2] += tq * mv.z;
                    out[a + 3] += tq * mv.w;
                }
            }
            __syncthreads();
#pragma unroll
            for (int a = 0; a < 16; a++) {
                int l = cb + a;
                float vv = (l >= p0 && l < p0 + 32) ? T[qr * TST + (l - p0)] : out[a];
                M[(p0 + qr) * MST + l] = vv;
            }
            __syncthreads();
        }

        {
            ull acc[6][4];
#pragma unroll
            for (int r = 0; r < 6; r++)
#pragma unroll
                for (int c = 0; c < 4; c++) acc[r][c] = 0ULL;
            for (int q = 0; q < 32; q++) {
                const float* Mp = M + (p0 + q) * MST + tx * 8;
                ull b0 = *(const ull*)(Mp + 0);
                ull b1 = *(const ull*)(Mp + 2);
                ull b2 = *(const ull*)(Mp + 4);
                ull b3 = *(const ull*)(Mp + 6);
#pragma unroll
                for (int r = 0; r < 6; r++) {
                    int z = ty + 16 * r;
                    int i = (z < p0) ? z : z + 32;
                    float av = Cs[i * CST + q];
                    ull a2 = pack2(av, av);
                    ffma2(acc[r][0], a2, b0);
                    ffma2(acc[r][1], a2, b1);
                    ffma2(acc[r][2], a2, b2);
                    ffma2(acc[r][3], a2, b3);
                }
            }
#pragma unroll
            for (int r = 0; r < 6; r++) {
                int z = ty + 16 * r;
                int i = (z < p0) ? z : z + 32;
#pragma unroll
                for (int c = 0; c < 4; c++) {
                    int l = tx * 8 + 2 * c;
                    float lo, hi;
                    unpack2(acc[r][c], lo, hi);
                    float* Mp = M + i * MST + l;
                    bool inP0 = (l >= p0 && l < p0 + 32);
                    bool inP1 = (l + 1 >= p0 && l + 1 < p0 + 32);
                    float o0 = (inP0 ? 0.0f : Mp[0]) - lo;
                    float o1 = (inP1 ? 0.0f : Mp[1]) - hi;
                    Mp[0] = o0;
                    Mp[1] = o1;
                }
            }
            __syncthreads();
        }
    }

#pragma unroll
    for (int u = 0; u < 16; u++) {
        int v = tid + u * 256;
        int m = v >> 5, c4 = (v & 31) << 2;
        *(float4*)(Si + m * 128 + c4) = *(const float4*)(M + m * MST + c4);
    }
}

// ---------------------------------------------------------------------------
// Kernel 5: solve GEMM (unchanged)
// ---------------------------------------------------------------------------
#define EST 20
#define SST 68
__global__ void solve_gemm(float* __restrict__ out, int mode) {
    int id = blockIdx.y;
    int b = id >> 1, dir = id & 1;
    int n0 = blockIdx.x * 64;
    const float* Si = g_Sinv + (size_t)id * (KK * KK);
    const float* Dm = g_D + (size_t)id * (KK * KK);
    const float* Rb = (dir ? g_RT : g_R) + (size_t)b * (KK * KK);
    const float* Xp = (mode == 1 ? g_X0 : g_X1) + (size_t)id * (KK * KK);
    const float* base = g_X0 + (size_t)id * (KK * KK);
    float* Cout;
    if (mode == 0)      Cout = g_X0 + (size_t)id * (KK * KK);
    else if (mode == 1) Cout = g_X1 + (size_t)id * (KK * KK);
    else                Cout = out + (size_t)(dir ? BB * KK * KK : 0) + (size_t)b * (KK * KK);

    __shared__ float Ts[128 * EST];
    __shared__ float Ss[16 * SST];

    int tid = threadIdx.x;
    int ty = tid >> 4, tx = tid & 15;
    int v0 = tid, v1 = tid + 256;
    int tm0 = v0 >> 2, tc0 = (v0 & 3) << 2;
    int tm1 = v1 >> 2, tc1 = (v1 & 3) << 2;
    int sk = tid >> 4, sc = (tid & 15) << 2;

    ull acc[8][2];
#pragma unroll
    for (int r = 0; r < 8; r++) { acc[r][0] = 0ULL; acc[r][1] = 0ULL; }

    for (int k0 = 0; k0 < KK; k0 += 16) {
        if (mode == 0) {
            *(float4*)&Ts[tm0 * EST + tc0] = *(const float4*)(Rb + tm0 * 128 + k0 + tc0);
            *(float4*)&Ts[tm1 * EST + tc1] = *(const float4*)(Rb + tm1 * 128 + k0 + tc1);
        } else {
            float4 d0 = *(const float4*)(Dm + tm0 * 128 + k0 + tc0);
            float4 x0 = *(const float4*)(Xp + tm0 * 128 + k0 + tc0);
            float4 d1 = *(const float4*)(Dm + tm1 * 128 + k0 + tc1);
            float4 x1 = *(const float4*)(Xp + tm1 * 128 + k0 + tc1);
            float4 o0 = make_float4(d0.x * x0.x, d0.y * x0.y, d0.z * x0.z, d0.w * x0.w);
            float4 o1 = make_float4(d1.x * x1.x, d1.y * x1.y, d1.z * x1.z, d1.w * x1.w);
            *(float4*)&Ts[tm0 * EST + tc0] = o0;
            *(float4*)&Ts[tm1 * EST + tc1] = o1;
        }
        *(float4*)&Ss[sk * SST + sc] = *(const float4*)(Si + (size_t)(k0 + sk) * 128 + n0 + sc);
        __syncthreads();
#pragma unroll
        for (int k = 0; k < 16; k++) {
            ull b0 = *(const ull*)&Ss[k * SST + tx * 4];
            ull b1 = *(const ull*)&Ss[k * SST + tx * 4 + 2];
#pragma unroll
            for (int r = 0; r < 8; r++) {
                float av = Ts[(ty * 8 + r) * EST + k];
                ull a2 = pack2(av, av);
                ffma2(acc[r][0], a2, b0);
                ffma2(acc[r][1], a2, b1);
            }
        }
        __syncthreads();
    }
#pragma unroll
    for (int r = 0; r < 8; r++) {
        int m = ty * 8 + r;
#pragma unroll
        for (int c2 = 0; c2 < 2; c2++) {
            int n = n0 + tx * 4 + 2 * c2;
            int idx = m * 128 + n;
            float lo, hi;
            unpack2(acc[r][c2], lo, hi);
            if (mode != 0) {
                lo = base[idx] - lo;
                hi = base[idx + 1] - hi;
            }
            Cout[idx] = lo;
            Cout[idx + 1] = hi;
        }
    }
}

// ---------------------------------------------------------------------------
extern "C" void kernel_launch(void* const* d_in, const int* in_sizes, int n_in,
                              void* d_out, int out_size) {
    const float* feat_x  = (const float*)d_in[0];
    const float* feat_y  = (const float*)d_in[1];
    const float* evals_x = (const float*)d_in[2];
    const float* evals_y = (const float*)d_in[3];
    const float* evecs_x = (const float*)d_in[4];
    const float* evecs_y = (const float*)d_in[5];
    const float* aux_x   = (const float*)d_in[6];
    const float* aux_y   = (const float*)d_in[7];
    float* out = (float*)d_out;

    split_E<<<dim3(8192, 2), 256>>>(evecs_x, evecs_y);
    split_F<<<dim3(64, 8, 32), 256>>>(feat_x, feat_y);

    cudaFuncSetAttribute(mma_proj, cudaFuncAttributeMaxDynamicSharedMemorySize, MMA_SMEM);
    mma_proj<<<dim3(4, 32), 256, MMA_SMEM>>>();

    split_AB<<<dim3(1024, 2), 256>>>();
    cudaFuncSetAttribute(gemm_nt_hmma, cudaFuncAttributeMaxDynamicSharedMemorySize, NT_SMEM);
    gemm_nt_hmma<<<48, 256, NT_SMEM>>>();

    mask_kernel<<<32, 256>>>(evals_x, evals_y, aux_x, aux_y);
    cudaFuncSetAttribute(invert_blocked, cudaFuncAttributeMaxDynamicSharedMemorySize, INV_SMEM);
    invert_blocked<<<32, 256, INV_SMEM>>>();
    solve_gemm<<<dim3(2, 32), 256>>>(out, 0);
    solve_gemm<<<dim3(2, 32), 256>>>(out, 1);
    solve_gemm<<<dim3(2, 32), 256>>>(out, 2);
}

// round 8
// speedup vs baseline: 3.1868x; 1.1020x over previous
#include <cuda_runtime.h>
#include <cuda_bf16.h>

#define BB 16
#define NN 4096
#define DD 512
#define KK 128
#define REGC 1e-6f

typedef unsigned long long ull;

__device__ __forceinline__ ull pack2(float x, float y) {
    ull r; asm("mov.b64 %0, {%1, %2};" : "=l"(r) : "f"(x), "f"(y)); return r;
}
__device__ __forceinline__ void unpack2(ull v, float& lo, float& hi) {
    asm("mov.b64 {%0, %1}, %2;" : "=f"(lo), "=f"(hi) : "l"(v));
}
__device__ __forceinline__ void ffma2(ull& d, ull a, ull b) {
    asm("fma.rn.f32x2 %0, %1, %2, %0;" : "+l"(d) : "l"(a), "l"(b));
}
__device__ __forceinline__ unsigned smem_u32(const void* p) {
    unsigned a;
    asm("{ .reg .u64 t; cvta.to.shared.u64 t, %1; cvt.u32.u64 %0, t; }" : "=r"(a) : "l"(p));
    return a;
}
__device__ __forceinline__ void ldm4(unsigned* r, unsigned addr) {
    asm volatile("ldmatrix.sync.aligned.m8n8.x4.shared.b16 {%0,%1,%2,%3}, [%4];"
                 : "=r"(r[0]), "=r"(r[1]), "=r"(r[2]), "=r"(r[3]) : "r"(addr));
}
__device__ __forceinline__ void mma_bf16(float* d, const unsigned* a, const unsigned* b) {
    asm volatile(
        "mma.sync.aligned.m16n8k16.row.col.f32.bf16.bf16.f32 "
        "{%0,%1,%2,%3}, {%4,%5,%6,%7}, {%8,%9}, {%0,%1,%2,%3};"
        : "+f"(d[0]), "+f"(d[1]), "+f"(d[2]), "+f"(d[3])
        : "r"(a[0]), "r"(a[1]), "r"(a[2]), "r"(a[3]), "r"(b[0]), "r"(b[1]));
}
__device__ __forceinline__ float lds_f32(unsigned a) {
    float v; asm volatile("ld.shared.f32 %0, [%1];" : "=f"(v) : "r"(a)); return v;
}
__device__ __forceinline__ void sts128(unsigned a, unsigned r0, unsigned r1,
                                       unsigned r2, unsigned r3) {
    asm volatile("st.shared.v4.b32 [%0], {%1,%2,%3,%4};"
                 :: "r"(a), "r"(r0), "r"(r1), "r"(r2), "r"(r3) : "memory");
}
#define SWZ(o) ((o) ^ (((o) >> 3) & 0x70))

// Scratch
__device__ float g_A[BB * KK * DD];
__device__ float g_B[BB * KK * DD];
__device__ float g_S[2 * BB * KK * KK];
__device__ float g_Sinv[2 * BB * KK * KK];
__device__ float g_R[BB * KK * KK];
__device__ float g_RT[BB * KK * KK];
__device__ float g_D[2 * BB * KK * KK];
__device__ float g_X0[2 * BB * KK * KK];
__device__ float g_X1[2 * BB * KK * KK];
// bf16 split E: [p=w*16+b][128][4096]
__device__ __nv_bfloat16 g_Ehi[2 * BB * KK * NN];
__device__ __nv_bfloat16 g_Elo[2 * BB * KK * NN];
// bf16 split of projected A/B: [sel][b][128][512]
__device__ __nv_bfloat16 g_ABhi[2 * BB * KK * DD];
__device__ __nv_bfloat16 g_ABlo[2 * BB * KK * DD];

__device__ __forceinline__ void split1(float x, unsigned short& h, unsigned short& l) {
    __nv_bfloat16 hb = __float2bfloat16_rn(x);
    float r = x - __bfloat162float(hb);
    __nv_bfloat16 lb = __float2bfloat16_rn(r);
    h = __bfloat16_as_ushort(hb);
    l = __bfloat16_as_ushort(lb);
}

// ---------------------------------------------------------------------------
// split_E: evecs fp32 [b][128][4096] -> g_Ehi/g_Elo bf16, same layout
// ---------------------------------------------------------------------------
__global__ void split_E(const float* __restrict__ ex, const float* __restrict__ ey) {
    int w = blockIdx.y;
    const float* E = w ? ey : ex;
    size_t i4 = (size_t)blockIdx.x * 256 + threadIdx.x;
    float4 t = *((const float4*)E + i4);
    unsigned short h0, h1, h2, h3, l0, l1, l2, l3;
    split1(t.x, h0, l0); split1(t.y, h1, l1); split1(t.z, h2, l2); split1(t.w, h3, l3);
    ull hp = (ull)h0 | ((ull)h1 << 16) | ((ull)h2 << 32) | ((ull)h3 << 48);
    ull lp = (ull)l0 | ((ull)l1 << 16) | ((ull)l2 << 32) | ((ull)l3 << 48);
    size_t o = (size_t)w * (BB * KK * NN) + i4 * 4;
    *(ull*)(g_Ehi + o) = hp;
    *(ull*)(g_Elo + o) = lp;
}

// ---------------------------------------------------------------------------
// split_AB: g_A/g_B fp32 -> g_ABhi/lo bf16
// ---------------------------------------------------------------------------
__global__ void split_AB() {
    int sel = blockIdx.y;
    const float* src = sel ? g_B : g_A;
    size_t i4 = (size_t)blockIdx.x * 256 + threadIdx.x;
    float4 t = *((const float4*)src + i4);
    unsigned short h0, h1, h2, h3, l0, l1, l2, l3;
    split1(t.x, h0, l0); split1(t.y, h1, l1); split1(t.z, h2, l2); split1(t.w, h3, l3);
    ull hp = (ull)h0 | ((ull)h1 << 16) | ((ull)h2 << 32) | ((ull)h3 << 48);
    ull lp = (ull)l0 | ((ull)l1 << 16) | ((ull)l2 << 32) | ((ull)l3 << 48);
    size_t o = (size_t)sel * (BB * KK * DD) + i4 * 4;
    *(ull*)(g_ABhi + o) = hp;
    *(ull*)(g_ABlo + o) = lp;
}

// ---------------------------------------------------------------------------
// mma_proj: C[128,128-tile] = E @ F, bf16 3-product split, fused F split+transpose.
// smem: [conv Bh 16K | conv Bl 16K | 3 stages of (Ah 16K | Al 16K | Ffp32 32K)]
// ---------------------------------------------------------------------------
#define CONV_BH 0
#define CONV_BL 16384
#define STAGE0 32768
#define STAGE_SZ 65536
#define MMA_SMEM (1024 + STAGE0 + 3 * STAGE_SZ)   // 230400

__global__ void __launch_bounds__(256, 1) mma_proj(const float* __restrict__ fx,
                                                   const float* __restrict__ fy) {
    extern __shared__ char smraw[];
    unsigned base = (smem_u32(smraw) + 1023) & ~1023u;
    int tid = threadIdx.x, wid = tid >> 5, lane = tid & 31;

    int p = blockIdx.y; int w = p >> 4, b = p & 15;
    int n0 = blockIdx.x * 128;
    const __nv_bfloat16* Eh = g_Ehi + (size_t)p * KK * NN;
    const __nv_bfloat16* El = g_Elo + (size_t)p * KK * NN;
    const float* Ff = (w ? fy : fx) + (size_t)b * NN * DD + n0;   // [k=4096][d], take cols n0..n0+127
    float* C = (w ? g_B : g_A) + (size_t)b * KK * DD + n0;

    int wm = (wid & 1) * 64, wn = (wid >> 1) * 32;

    float acc[4][4][4];
#pragma unroll
    for (int mt = 0; mt < 4; mt++)
#pragma unroll
        for (int nt = 0; nt < 4; nt++)
#pragma unroll
            for (int i = 0; i < 4; i++) acc[mt][nt][i] = 0.0f;

    unsigned msk = (unsigned)((lane & 7) << 4);
    unsigned a_c0 = (unsigned)((lane >> 4) * 16);
    unsigned b_c0 = (unsigned)(((lane >> 3) & 1) * 16);
    unsigned a_row[4], b_row[2];
#pragma unroll
    for (int mt = 0; mt < 4; mt++)
        a_row[mt] = (unsigned)((wm + mt * 16 + (lane & 15)) * 128);
#pragma unroll
    for (int np = 0; np < 2; np++)
        b_row[np] = (unsigned)((wn + np * 16 + ((lane >> 4) << 3) + (lane & 7)) * 128);

    int cd = tid & 127, ckg = tid >> 7;   // conversion: thread owns d=cd, k-half ckg

    auto issue = [&](int c) {
        unsigned stage = base + STAGE0 + (unsigned)(c % 3) * STAGE_SZ;
        int k0 = c * 64;
        // A tiles (bf16 hi/lo), 4 chunks each
#pragma unroll
        for (int u = 0; u < 8; u++) {
            int tile = u >> 2;
            int v = tid + (u & 3) * 256;
            int r = v >> 3, s = v & 7;
            unsigned sa = stage + tile * 16384 + SWZ((unsigned)(r * 128 + s * 16));
            const __nv_bfloat16* g = (tile ? El : Eh) + (size_t)r * NN + k0 + s * 8;
            asm volatile("cp.async.cg.shared.global [%0], [%1], 16;"
                         :: "r"(sa), "l"(g) : "memory");
        }
        // F fp32 tile [64 k x 128 d], rows of 512B, linear smem
#pragma unroll
        for (int u = 0; u < 8; u++) {
            int v = tid + u * 256;
            int r = v >> 5, s = v & 31;
            unsigned sa = stage + 32768 + (unsigned)(r * 512 + s * 16);
            const float* g = Ff + (size_t)(k0 + r) * DD + s * 4;
            asm volatile("cp.async.cg.shared.global [%0], [%1], 16;"
                         :: "r"(sa), "l"(g) : "memory");
        }
        asm volatile("cp.async.commit_group;" ::: "memory");
    };

    issue(0);
    issue(1);
    for (int c = 0; c < 64; c++) {
        if (c < 63)
            asm volatile("cp.async.wait_group 1;" ::: "memory");
        else
            asm volatile("cp.async.wait_group 0;" ::: "memory");
        __syncthreads();

        unsigned stage = base + STAGE0 + (unsigned)(c % 3) * STAGE_SZ;
        // ---- convert F fp32 -> Bh/Bl (transpose + split + swizzle) ----
        {
            unsigned fpb = stage + 32768;
#pragma unroll
            for (int kq = 0; kq < 4; kq++) {
                int kstart = ckg * 8 + kq * 16;
                unsigned hw[4], lw[4];
#pragma unroll
                for (int w2 = 0; w2 < 4; w2++) {
                    float x0 = lds_f32(fpb + (unsigned)(((kstart + 2 * w2) * 128 + cd) * 4));
                    float x1 = lds_f32(fpb + (unsigned)(((kstart + 2 * w2 + 1) * 128 + cd) * 4));
                    unsigned short h0, l0, h1, l1;
                    split1(x0, h0, l0); split1(x1, h1, l1);
                    hw[w2] = (unsigned)h0 | ((unsigned)h1 << 16);
                    lw[w2] = (unsigned)l0 | ((unsigned)l1 << 16);
                }
                unsigned off = SWZ((unsigned)(cd * 128 + kstart * 2));
                sts128(base + CONV_BH + off, hw[0], hw[1], hw[2], hw[3]);
                sts128(base + CONV_BL + off, lw[0], lw[1], lw[2], lw[3]);
            }
        }
        __syncthreads();
        if (c + 2 < 64) issue(c + 2);   // stage (c+2)%3 == (c-1)%3, retired

        unsigned sAh = stage, sAl = stage + 16384;
        unsigned sBh = base + CONV_BH, sBl = base + CONV_BL;
#pragma unroll
        for (int kk = 0; kk < 4; kk++) {
            unsigned ca = (a_c0 + (unsigned)(kk * 32)) ^ msk;
            unsigned cb = (b_c0 + (unsigned)(kk * 32)) ^ msk;
            unsigned ah[4][4], al[4][4], bh[2][4], bl[2][4];
#pragma unroll
            for (int mt = 0; mt < 4; mt++) {
                ldm4(ah[mt], sAh + a_row[mt] + ca);
                ldm4(al[mt], sAl + a_row[mt] + ca);
            }
#pragma unroll
            for (int np = 0; np < 2; np++) {
                ldm4(bh[np], sBh + b_row[np] + cb);
                ldm4(bl[np], sBl + b_row[np] + cb);
            }
#pragma unroll
            for (int mt = 0; mt < 4; mt++)
#pragma unroll
                for (int nt = 0; nt < 4; nt++)
                    mma_bf16(acc[mt][nt], ah[mt], &bh[nt >> 1][(nt & 1) * 2]);
#pragma unroll
            for (int mt = 0; mt < 4; mt++)
#pragma unroll
                for (int nt = 0; nt < 4; nt++)
                    mma_bf16(acc[mt][nt], ah[mt], &bl[nt >> 1][(nt & 1) * 2]);
#pragma unroll
            for (int mt = 0; mt < 4; mt++)
#pragma unroll
                for (int nt = 0; nt < 4; nt++)
                    mma_bf16(acc[mt][nt], al[mt], &bh[nt >> 1][(nt & 1) * 2]);
        }
    }

#pragma unroll
    for (int mt = 0; mt < 4; mt++) {
#pragma unroll
        for (int nt = 0; nt < 4; nt++) {
            int r0 = wm + mt * 16 + (lane >> 2);
            int c0 = wn + nt * 8 + (lane & 3) * 2;
            float2 v01 = make_float2(acc[mt][nt][0], acc[mt][nt][1]);
            float2 v23 = make_float2(acc[mt][nt][2], acc[mt][nt][3]);
            *(float2*)(C + (size_t)r0 * DD + c0) = v01;
            *(float2*)(C + (size_t)(r0 + 8) * DD + c0) = v23;
        }
    }
}

// ---------------------------------------------------------------------------
// gemm_nt_hmma: S_x/S_y/R via HMMA on bf16-split A/B. 48 CTAs, 128x128, K=512.
// ---------------------------------------------------------------------------
#define NTSTAGE_BYTES 65536
#define NT_SMEM (1024 + 3 * NTSTAGE_BYTES)
__global__ void __launch_bounds__(256, 1) gemm_nt_hmma() {
    extern __shared__ char smraw[];
    unsigned base = (smem_u32(smraw) + 1023) & ~1023u;
    int tid = threadIdx.x, wid = tid >> 5, lane = tid & 31;

    int id = blockIdx.x;
    int b = id / 3, mode = id % 3;
    size_t offA = (size_t)b * KK * DD;
    size_t offB = (size_t)(BB + b) * KK * DD;
    size_t offP = (mode == 0) ? offA : offB;
    size_t offQ = (mode == 1) ? offB : offA;
    const __nv_bfloat16* Ph = g_ABhi + offP;
    const __nv_bfloat16* Pl = g_ABlo + offP;
    const __nv_bfloat16* Qh = g_ABhi + offQ;
    const __nv_bfloat16* Ql = g_ABlo + offQ;
    float* C = (mode < 2) ? g_S + (size_t)(b * 2 + mode) * KK * KK
                          : g_R + (size_t)b * KK * KK;
    float* CT = g_RT + (size_t)b * KK * KK;

    int wm = (wid & 1) * 64, wn = (wid >> 1) * 32;

    float acc[4][4][4];
#pragma unroll
    for (int mt = 0; mt < 4; mt++)
#pragma unroll
        for (int nt = 0; nt < 4; nt++)
#pragma unroll
            for (int i = 0; i < 4; i++) acc[mt][nt][i] = 0.0f;

    unsigned msk = (unsigned)((lane & 7) << 4);
    unsigned a_c0 = (unsigned)((lane >> 4) * 16);
    unsigned b_c0 = (unsigned)(((lane >> 3) & 1) * 16);
    unsigned a_row[4], b_row[2];
#pragma unroll
    for (int mt = 0; mt < 4; mt++)
        a_row[mt] = (unsigned)((wm + mt * 16 + (lane & 15)) * 128);
#pragma unroll
    for (int np = 0; np < 2; np++)
        b_row[np] = (unsigned)((wn + np * 16 + ((lane >> 4) << 3) + (lane & 7)) * 128);

    auto issue = [&](int c) {
        unsigned stage = base + 1024 + (unsigned)(c % 3) * NTSTAGE_BYTES;
        int k0 = c * 64;
#pragma unroll
        for (int u = 0; u < 16; u++) {
            int tile = u >> 2;
            int v = tid + (u & 3) * 256;
            int r = v >> 3, s = v & 7;
            unsigned sa = stage + tile * 16384 + SWZ((unsigned)(r * 128 + s * 16));
            const __nv_bfloat16* g;
            if (tile == 0)      g = Ph;
            else if (tile == 1) g = Pl;
            else if (tile == 2) g = Qh;
            else                g = Ql;
            g += (size_t)r * DD + k0 + s * 8;
            asm volatile("cp.async.cg.shared.global [%0], [%1], 16;"
                         :: "r"(sa), "l"(g) : "memory");
        }
        asm volatile("cp.async.commit_group;" ::: "memory");
    };

    issue(0);
    issue(1);
    for (int c = 0; c < 8; c++) {
        if (c < 7)
            asm volatile("cp.async.wait_group 1;" ::: "memory");
        else
            asm volatile("cp.async.wait_group 0;" ::: "memory");
        __syncthreads();
        if (c + 2 < 8) issue(c + 2);
        unsigned stage = base + 1024 + (unsigned)(c % 3) * NTSTAGE_BYTES;
        unsigned sAh = stage, sAl = stage + 16384, sBh = stage + 32768, sBl = stage + 49152;
#pragma unroll
        for (int kk = 0; kk < 4; kk++) {
            unsigned ca = (a_c0 + (unsigned)(kk * 32)) ^ msk;
            unsigned cb = (b_c0 + (unsigned)(kk * 32)) ^ msk;
            unsigned ah[4][4], al[4][4], bh[2][4], bl[2][4];
#pragma unroll
            for (int mt = 0; mt < 4; mt++) {
                ldm4(ah[mt], sAh + a_row[mt] + ca);
                ldm4(al[mt], sAl + a_row[mt] + ca);
            }
#pragma unroll
            for (int np = 0; np < 2; np++) {
                ldm4(bh[np], sBh + b_row[np] + cb);
                ldm4(bl[np], sBl + b_row[np] + cb);
            }
#pragma unroll
            for (int mt = 0; mt < 4; mt++)
#pragma unroll
                for (int nt = 0; nt < 4; nt++)
                    mma_bf16(acc[mt][nt], ah[mt], &bh[nt >> 1][(nt & 1) * 2]);
#pragma unroll
            for (int mt = 0; mt < 4; mt++)
#pragma unroll
                for (int nt = 0; nt < 4; nt++)
                    mma_bf16(acc[mt][nt], ah[mt], &bl[nt >> 1][(nt & 1) * 2]);
#pragma unroll
            for (int mt = 0; mt < 4; mt++)
#pragma unroll
                for (int nt = 0; nt < 4; nt++)
                    mma_bf16(acc[mt][nt], al[mt], &bh[nt >> 1][(nt & 1) * 2]);
        }
    }

#pragma unroll
    for (int mt = 0; mt < 4; mt++) {
#pragma unroll
        for (int nt = 0; nt < 4; nt++) {
            int r0 = wm + mt * 16 + (lane >> 2);
            int c0 = wn + nt * 8 + (lane & 3) * 2;
            float v0 = acc[mt][nt][0], v1 = acc[mt][nt][1];
            float v2 = acc[mt][nt][2], v3 = acc[mt][nt][3];
            if (mode < 2) {
                if (r0 == c0) v0 += REGC;
                if (r0 == c0 + 1) v1 += REGC;
                if (r0 + 8 == c0) v2 += REGC;
                if (r0 + 8 == c0 + 1) v3 += REGC;
            }
            C[r0 * KK + c0] = v0;
            C[r0 * KK + c0 + 1] = v1;
            C[(r0 + 8) * KK + c0] = v2;
            C[(r0 + 8) * KK + c0 + 1] = v3;
            if (mode == 2) {
                CT[c0 * KK + r0] = v0;
                CT[(c0 + 1) * KK + r0] = v1;
                CT[c0 * KK + r0 + 8] = v2;
                CT[(c0 + 1) * KK + r0 + 8] = v3;
            }
        }
    }
}

// ---------------------------------------------------------------------------
// mask_kernel (unchanged)
// ---------------------------------------------------------------------------
__global__ void mask_kernel(const float* __restrict__ evx, const float* __restrict__ evy,
                            const float* __restrict__ ax,  const float* __restrict__ ay) {
    int id = blockIdx.x;
    int b = id >> 1, dir = id & 1;
    const float* e1p = (dir ? evy : evx) + b * KK;
    const float* e2p = (dir ? evx : evy) + b * KK;
    const float* a1p = (dir ? ay : ax) + b * KK;
    const float* a2p = (dir ? ax : ay) + b * KK;

    __shared__ float t1[128], u1[128], t2[128], u2[128];
    __shared__ float v1[128], w1[128], v2[128], w2[128];
    __shared__ float red[128];
    __shared__ float sc_main, sc_aux;

    int tid = threadIdx.x;
    float e1 = 0.f, e2 = 0.f, q1 = 0.f, q2 = 0.f;
    if (tid < 128) {
        e1 = fmaxf(e1p[tid], 1e-10f);
        e2 = fmaxf(e2p[tid], 1e-10f);
        q1 = fmaxf(a1p[tid], 1e-10f);
        q2 = fmaxf(a2p[tid], 1e-10f);
        red[tid] = fmaxf(e1, e2);
    }
    __syncthreads();
    for (int off = 64; off; off >>= 1) {
        if (tid < off) red[tid] = fmaxf(red[tid], red[tid + off]);
        __syncthreads();
    }
    if (tid == 0) sc_main = fmaxf(red[0], 1e-10f);
    __syncthreads();
    if (tid < 128) red[tid] = fmaxf(q1, q2);
    __syncthreads();
    for (int off = 64; off; off >>= 1) {
        if (tid < off) red[tid] = fmaxf(red[tid], red[tid + off]);
        __syncthreads();
    }
    if (tid == 0) sc_aux = fmaxf(red[0], 1e-10f);
    __syncthreads();

    if (tid < 128) {
        float r, d;
        r = e1 / sc_main; d = r + 1.0f; t1[tid] = sqrtf(r) / d; u1[tid] = 1.0f / d;
        r = e2 / sc_main; d = r + 1.0f; t2[tid] = sqrtf(r) / d; u2[tid] = 1.0f / d;
        r = q1 / sc_aux;  d = r + 1.0f; v1[tid] = sqrtf(r) / d; w1[tid] = 1.0f / d;
        r = q2 / sc_aux;  d = r + 1.0f; v2[tid] = sqrtf(r) / d; w2[tid] = 1.0f / d;
    }
    __syncthreads();

    float* Dp = g_D + (size_t)id * (KK * KK);
    for (int v = tid; v < KK * KK; v += 256) {
        int i = v >> 7, j = v & 127;
        float mr = t2[i] - t1[j], mi = u2[i] - u1[j];
        float ar = v2[i] - v1[j], ai = w2[i] - w1[j];
        Dp[v] = 100.0f * (mr * mr + mi * mi) + 25.0f * (ar * ar + ai * ai);
    }
}

// ---------------------------------------------------------------------------
// invert_blocked (unchanged)
// ---------------------------------------------------------------------------
#define MST 132
#define CST 36
#define TST 36
#define INV_SMEM ((128 * MST + 128 * CST + 32 * TST) * 4)

__global__ void invert_blocked() {
    extern __shared__ float sm[];
    float* M  = sm;
    float* Cs = sm + 128 * MST;
    float* T  = Cs + 128 * CST;
    int mat = blockIdx.x;
    const float* S = g_S + (size_t)mat * KK * KK;
    float* Si = g_Sinv + (size_t)mat * KK * KK;
    int tid = threadIdx.x;
    int ty = tid >> 4, tx = tid & 15;

#pragma unroll
    for (int u = 0; u < 16; u++) {
        int v = tid + u * 256;
        int m = v >> 5, c4 = (v & 31) << 2;
        *(float4*)(M + m * MST + c4) = *(const float4*)(S + m * 128 + c4);
    }
    __syncthreads();

    for (int p = 0; p < 4; p++) {
        int p0 = p * 32;
#pragma unroll
        for (int u = 0; u < 4; u++) {
            int v = tid + u * 256;
            int i = v >> 3, q4 = (v & 7) << 2;
            *(float4*)(Cs + i * CST + q4) = *(const float4*)(M + i * MST + p0 + q4);
        }
        {
            int q = tid >> 3, r4 = (tid & 7) << 2;
            *(float4*)(T + q * TST + r4) = *(const float4*)(M + (p0 + q) * MST + p0 + r4);
        }
        __syncthreads();

        {
            int q = tid >> 3, rb = (tid & 7) << 2;
            for (int j = 0; j < 32; j++) {
                float pivinv = 1.0f / T[j * TST + j];
                float f = T[q * TST + j];
                float pr[4], cu[4];
#pragma unroll
                for (int a = 0; a < 4; a++) { pr[a] = T[j * TST + rb + a]; cu[a] = T[q * TST + rb + a]; }
                __syncthreads();
                float o[4];
                if (q == j) {
#pragma unroll
                    for (int a = 0; a < 4; a++) o[a] = (rb + a == j) ? pivinv : pr[a] * pivinv;
                } else {
                    float fp = f * pivinv;
#pragma unroll
                    for (int a = 0; a < 4; a++) o[a] = (rb + a == j) ? -fp : cu[a] - fp * pr[a];
                }
#pragma unroll
                for (int a = 0; a < 4; a++) T[q * TST + rb + a] = o[a];
                __syncthreads();
            }
        }

        {
            int qr = tid >> 3;
            int cb = (tid & 7) << 4;
            float out[16];
#pragma unroll
            for (int a = 0; a < 16; a++) out[a] = 0.0f;
            for (int r = 0; r < 32; r++) {
                float tq = T[qr * TST + r];
                const float* Mr = M + (p0 + r) * MST + cb;
#pragma unroll
                for (int a = 0; a < 16; a += 4) {
                    float4 mv = *(const float4*)(Mr + a);
                    out[a + 0] += tq * mv.x;
                    out[a + 1] += tq * mv.y;
                    out[a + 2] += tq * mv.z;
                    out[a + 3] += tq * mv.w;
                }
            }
            __syncthreads();
#pragma unroll
            for (int a = 0; a < 16; a++) {
                int l = cb + a;
                float vv = (l >= p0 && l < p0 + 32) ? T[qr * TST + (l - p0)] : out[a];
                M[(p0 + qr) * MST + l] = vv;
            }
            __syncthreads();
        }

        {
            ull acc[6][4];
#pragma unroll
            for (int r = 0; r < 6; r++)
#pragma unroll
                for (int c = 0; c < 4; c++) acc[r][c] = 0ULL;
            for (int q = 0; q < 32; q++) {
                const float* Mp = M + (p0 + q) * MST + tx * 8;
                ull b0 = *(const ull*)(Mp + 0);
                ull b1 = *(const ull*)(Mp + 2);
                ull b2 = *(const ull*)(Mp + 4);
                ull b3 = *(const ull*)(Mp + 6);
#pragma unroll
                for (int r = 0; r < 6; r++) {
                    int z = ty + 16 * r;
                    int i = (z < p0) ? z : z + 32;
                    float av = Cs[i * CST + q];
                    ull a2 = pack2(av, av);
                    ffma2(acc[r][0], a2, b0);
                    ffma2(acc[r][1], a2, b1);
                    ffma2(acc[r][2], a2, b2);
                    ffma2(acc[r][3], a2, b3);
                }
            }
#pragma unroll
            for (int r = 0; r < 6; r++) {
                int z = ty + 16 * r;
                int i = (z < p0) ? z : z + 32;
#pragma unroll
                for (int c = 0; c < 4; c++) {
                    int l = tx * 8 + 2 * c;
                    float lo, hi;
                    unpack2(acc[r][c], lo, hi);
                    float* Mp = M + i * MST + l;
                    bool inP0 = (l >= p0 && l < p0 + 32);
                    bool inP1 = (l + 1 >= p0 && l + 1 < p0 + 32);
                    float o0 = (inP0 ? 0.0f : Mp[0]) - lo;
                    float o1 = (inP1 ? 0.0f : Mp[1]) - hi;
                    Mp[0] = o0;
                    Mp[1] = o1;
                }
            }
            __syncthreads();
        }
    }

#pragma unroll
    for (int u = 0; u < 16; u++) {
        int v = tid + u * 256;
        int m = v >> 5, c4 = (v & 31) << 2;
        *(float4*)(Si + m * 128 + c4) = *(const float4*)(M + m * MST + c4);
    }
}

// ---------------------------------------------------------------------------
// solve_gemm (unchanged)
// ---------------------------------------------------------------------------
#define EST 20
#define SST 68
__global__ void solve_gemm(float* __restrict__ out, int mode) {
    int id = blockIdx.y;
    int b = id >> 1, dir = id & 1;
    int n0 = blockIdx.x * 64;
    const float* Si = g_Sinv + (size_t)id * (KK * KK);
    const float* Dm = g_D + (size_t)id * (KK * KK);
    const float* Rb = (dir ? g_RT : g_R) + (size_t)b * (KK * KK);
    const float* Xp = (mode == 1 ? g_X0 : g_X1) + (size_t)id * (KK * KK);
    const float* base = g_X0 + (size_t)id * (KK * KK);
    float* Cout;
    if (mode == 0)      Cout = g_X0 + (size_t)id * (KK * KK);
    else if (mode == 1) Cout = g_X1 + (size_t)id * (KK * KK);
    else                Cout = out + (size_t)(dir ? BB * KK * KK : 0) + (size_t)b * (KK * KK);

    __shared__ float Ts[128 * EST];
    __shared__ float Ss[16 * SST];

    int tid = threadIdx.x;
    int ty = tid >> 4, tx = tid & 15;
    int v0 = tid, v1 = tid + 256;
    int tm0 = v0 >> 2, tc0 = (v0 & 3) << 2;
    int tm1 = v1 >> 2, tc1 = (v1 & 3) << 2;
    int sk = tid >> 4, sc = (tid & 15) << 2;

    ull acc[8][2];
#pragma unroll
    for (int r = 0; r < 8; r++) { acc[r][0] = 0ULL; acc[r][1] = 0ULL; }

    for (int k0 = 0; k0 < KK; k0 += 16) {
        if (mode == 0) {
            *(float4*)&Ts[tm0 * EST + tc0] = *(const float4*)(Rb + tm0 * 128 + k0 + tc0);
            *(float4*)&Ts[tm1 * EST + tc1] = *(const float4*)(Rb + tm1 * 128 + k0 + tc1);
        } else {
            float4 d0 = *(const float4*)(Dm + tm0 * 128 + k0 + tc0);
            float4 x0 = *(const float4*)(Xp + tm0 * 128 + k0 + tc0);
            float4 d1 = *(const float4*)(Dm + tm1 * 128 + k0 + tc1);
            float4 x1 = *(const float4*)(Xp + tm1 * 128 + k0 + tc1);
            float4 o0 = make_float4(d0.x * x0.x, d0.y * x0.y, d0.z * x0.z, d0.w * x0.w);
            float4 o1 = make_float4(d1.x * x1.x, d1.y * x1.y, d1.z * x1.z, d1.w * x1.w);
            *(float4*)&Ts[tm0 * EST + tc0] = o0;
            *(float4*)&Ts[tm1 * EST + tc1] = o1;
        }
        *(float4*)&Ss[sk * SST + sc] = *(const float4*)(Si + (size_t)(k0 + sk) * 128 + n0 + sc);
        __syncthreads();
#pragma unroll
        for (int k = 0; k < 16; k++) {
            ull b0 = *(const ull*)&Ss[k * SST + tx * 4];
            ull b1 = *(const ull*)&Ss[k * SST + tx * 4 + 2];
#pragma unroll
            for (int r = 0; r < 8; r++) {
                float av = Ts[(ty * 8 + r) * EST + k];
                ull a2 = pack2(av, av);
                ffma2(acc[r][0], a2, b0);
                ffma2(acc[r][1], a2, b1);
            }
        }
        __syncthreads();
    }
#pragma unroll
    for (int r = 0; r < 8; r++) {
        int m = ty * 8 + r;
#pragma unroll
        for (int c2 = 0; c2 < 2; c2++) {
            int n = n0 + tx * 4 + 2 * c2;
            int idx = m * 128 + n;
            float lo, hi;
            unpack2(acc[r][c2], lo, hi);
            if (mode != 0) {
                lo = base[idx] - lo;
                hi = base[idx + 1] - hi;
            }
            Cout[idx] = lo;
            Cout[idx + 1] = hi;
        }
    }
}

// ---------------------------------------------------------------------------
extern "C" void kernel_launch(void* const* d_in, const int* in_sizes, int n_in,
                              void* d_out, int out_size) {
    const float* feat_x  = (const float*)d_in[0];
    const float* feat_y  = (const float*)d_in[1];
    const float* evals_x = (const float*)d_in[2];
    const float* evals_y = (const float*)d_in[3];
    const float* evecs_x = (const float*)d_in[4];
    const float* evecs_y = (const float*)d_in[5];
    const float* aux_x   = (const float*)d_in[6];
    const float* aux_y   = (const float*)d_in[7];
    float* out = (float*)d_out;

    split_E<<<dim3(8192, 2), 256>>>(evecs_x, evecs_y);

    cudaFuncSetAttribute(mma_proj, cudaFuncAttributeMaxDynamicSharedMemorySize, MMA_SMEM);
    mma_proj<<<dim3(4, 32), 256, MMA_SMEM>>>(feat_x, feat_y);

    split_AB<<<dim3(1024, 2), 256>>>();
    cudaFuncSetAttribute(gemm_nt_hmma, cudaFuncAttributeMaxDynamicSharedMemorySize, NT_SMEM);
    gemm_nt_hmma<<<48, 256, NT_SMEM>>>();

    mask_kernel<<<32, 256>>>(evals_x, evals_y, aux_x, aux_y);
    cudaFuncSetAttribute(invert_blocked, cudaFuncAttributeMaxDynamicSharedMemorySize, INV_SMEM);
    invert_blocked<<<32, 256, INV_SMEM>>>();
    solve_gemm<<<dim3(2, 32), 256>>>(out, 0);
    solve_gemm<<<dim3(2, 32), 256>>>(out, 1);
    solve_gemm<<<dim3(2, 32), 256>>>(out, 2);
}

// round 9
// speedup vs baseline: 3.2242x; 1.0118x over previous
#include <cuda_runtime.h>
#include <cuda_bf16.h>

#define BB 16
#define NN 4096
#define DD 512
#define KK 128
#define REGC 1e-6f

typedef unsigned long long ull;

__device__ __forceinline__ ull pack2(float x, float y) {
    ull r; asm("mov.b64 %0, {%1, %2};" : "=l"(r) : "f"(x), "f"(y)); return r;
}
__device__ __forceinline__ void unpack2(ull v, float& lo, float& hi) {
    asm("mov.b64 {%0, %1}, %2;" : "=f"(lo), "=f"(hi) : "l"(v));
}
__device__ __forceinline__ void ffma2(ull& d, ull a, ull b) {
    asm("fma.rn.f32x2 %0, %1, %2, %0;" : "+l"(d) : "l"(a), "l"(b));
}
__device__ __forceinline__ unsigned smem_u32(const void* p) {
    unsigned a;
    asm("{ .reg .u64 t; cvta.to.shared.u64 t, %1; cvt.u32.u64 %0, t; }" : "=r"(a) : "l"(p));
    return a;
}
__device__ __forceinline__ void ldm4(unsigned* r, unsigned addr) {
    asm volatile("ldmatrix.sync.aligned.m8n8.x4.shared.b16 {%0,%1,%2,%3}, [%4];"
                 : "=r"(r[0]), "=r"(r[1]), "=r"(r[2]), "=r"(r[3]) : "r"(addr));
}
__device__ __forceinline__ void mma_bf16(float* d, const unsigned* a, const unsigned* b) {
    asm volatile(
        "mma.sync.aligned.m16n8k16.row.col.f32.bf16.bf16.f32 "
        "{%0,%1,%2,%3}, {%4,%5,%6,%7}, {%8,%9}, {%0,%1,%2,%3};"
        : "+f"(d[0]), "+f"(d[1]), "+f"(d[2]), "+f"(d[3])
        : "r"(a[0]), "r"(a[1]), "r"(a[2]), "r"(a[3]), "r"(b[0]), "r"(b[1]));
}
__device__ __forceinline__ float lds_f32(unsigned a) {
    float v; asm volatile("ld.shared.f32 %0, [%1];" : "=f"(v) : "r"(a)); return v;
}
__device__ __forceinline__ void sts128(unsigned a, unsigned r0, unsigned r1,
                                       unsigned r2, unsigned r3) {
    asm volatile("st.shared.v4.b32 [%0], {%1,%2,%3,%4};"
                 :: "r"(a), "r"(r0), "r"(r1), "r"(r2), "r"(r3) : "memory");
}
#define SWZ(o) ((o) ^ (((o) >> 3) & 0x70))

// Scratch
__device__ float g_S[2 * BB * KK * KK];
__device__ float g_Sinv[2 * BB * KK * KK];
__device__ float g_R[BB * KK * KK];
__device__ float g_RT[BB * KK * KK];
__device__ float g_D[2 * BB * KK * KK];
__device__ float g_X0[2 * BB * KK * KK];
__device__ float g_X1[2 * BB * KK * KK];
// bf16 split E: [p=w*16+b][128][4096]
__device__ __nv_bfloat16 g_Ehi[2 * BB * KK * NN];
__device__ __nv_bfloat16 g_Elo[2 * BB * KK * NN];
// bf16 split of projected A/B: [sel][b][128][512] (written directly by mma_proj)
__device__ __nv_bfloat16 g_ABhi[2 * BB * KK * DD];
__device__ __nv_bfloat16 g_ABlo[2 * BB * KK * DD];

__device__ __forceinline__ void split1(float x, unsigned short& h, unsigned short& l) {
    __nv_bfloat16 hb = __float2bfloat16_rn(x);
    float r = x - __bfloat162float(hb);
    __nv_bfloat16 lb = __float2bfloat16_rn(r);
    h = __bfloat16_as_ushort(hb);
    l = __bfloat16_as_ushort(lb);
}

// ---------------------------------------------------------------------------
// split_E: evecs fp32 [b][128][4096] -> g_Ehi/g_Elo bf16, same layout
// ---------------------------------------------------------------------------
__global__ void split_E(const float* __restrict__ ex, const float* __restrict__ ey) {
    int w = blockIdx.y;
    const float* E = w ? ey : ex;
    size_t i4 = (size_t)blockIdx.x * 256 + threadIdx.x;
    float4 t = *((const float4*)E + i4);
    unsigned short h0, h1, h2, h3, l0, l1, l2, l3;
    split1(t.x, h0, l0); split1(t.y, h1, l1); split1(t.z, h2, l2); split1(t.w, h3, l3);
    ull hp = (ull)h0 | ((ull)h1 << 16) | ((ull)h2 << 32) | ((ull)h3 << 48);
    ull lp = (ull)l0 | ((ull)l1 << 16) | ((ull)l2 << 32) | ((ull)l3 << 48);
    size_t o = (size_t)w * (BB * KK * NN) + i4 * 4;
    *(ull*)(g_Ehi + o) = hp;
    *(ull*)(g_Elo + o) = lp;
}

// ---------------------------------------------------------------------------
// mma_proj: A/B[128,128-tile] = E @ F, bf16 3-product split, fused F split+
// transpose, epilogue writes bf16 hi/lo split directly (no fp32 A/B).
// ---------------------------------------------------------------------------
#define CONV_BH 0
#define CONV_BL 16384
#define STAGE0 32768
#define STAGE_SZ 65536
#define MMA_SMEM (1024 + STAGE0 + 3 * STAGE_SZ)

__global__ void __launch_bounds__(256, 1) mma_proj(const float* __restrict__ fx,
                                                   const float* __restrict__ fy) {
    extern __shared__ char smraw[];
    unsigned base = (smem_u32(smraw) + 1023) & ~1023u;
    int tid = threadIdx.x, wid = tid >> 5, lane = tid & 31;

    int p = blockIdx.y; int w = p >> 4, b = p & 15;
    int n0 = blockIdx.x * 128;
    const __nv_bfloat16* Eh = g_Ehi + (size_t)p * KK * NN;
    const __nv_bfloat16* El = g_Elo + (size_t)p * KK * NN;
    const float* Ff = (w ? fy : fx) + (size_t)b * NN * DD + n0;
    size_t cbase = (size_t)p * KK * DD + n0;   // p = w*16+b matches [sel][b] layout

    int wm = (wid & 1) * 64, wn = (wid >> 1) * 32;

    float acc[4][4][4];
#pragma unroll
    for (int mt = 0; mt < 4; mt++)
#pragma unroll
        for (int nt = 0; nt < 4; nt++)
#pragma unroll
            for (int i = 0; i < 4; i++) acc[mt][nt][i] = 0.0f;

    unsigned msk = (unsigned)((lane & 7) << 4);
    unsigned a_c0 = (unsigned)((lane >> 4) * 16);
    unsigned b_c0 = (unsigned)(((lane >> 3) & 1) * 16);
    unsigned a_row[4], b_row[2];
#pragma unroll
    for (int mt = 0; mt < 4; mt++)
        a_row[mt] = (unsigned)((wm + mt * 16 + (lane & 15)) * 128);
#pragma unroll
    for (int np = 0; np < 2; np++)
        b_row[np] = (unsigned)((wn + np * 16 + ((lane >> 4) << 3) + (lane & 7)) * 128);

    int cd = tid & 127, ckg = tid >> 7;

    auto issue = [&](int c) {
        unsigned stage = base + STAGE0 + (unsigned)(c % 3) * STAGE_SZ;
        int k0 = c * 64;
#pragma unroll
        for (int u = 0; u < 8; u++) {
            int tile = u >> 2;
            int v = tid + (u & 3) * 256;
            int r = v >> 3, s = v & 7;
            unsigned sa = stage + tile * 16384 + SWZ((unsigned)(r * 128 + s * 16));
            const __nv_bfloat16* g = (tile ? El : Eh) + (size_t)r * NN + k0 + s * 8;
            asm volatile("cp.async.cg.shared.global [%0], [%1], 16;"
                         :: "r"(sa), "l"(g) : "memory");
        }
#pragma unroll
        for (int u = 0; u < 8; u++) {
            int v = tid + u * 256;
            int r = v >> 5, s = v & 31;
            unsigned sa = stage + 32768 + (unsigned)(r * 512 + s * 16);
            const float* g = Ff + (size_t)(k0 + r) * DD + s * 4;
            asm volatile("cp.async.cg.shared.global [%0], [%1], 16;"
                         :: "r"(sa), "l"(g) : "memory");
        }
        asm volatile("cp.async.commit_group;" ::: "memory");
    };

    issue(0);
    issue(1);
    for (int c = 0; c < 64; c++) {
        if (c < 63)
            asm volatile("cp.async.wait_group 1;" ::: "memory");
        else
            asm volatile("cp.async.wait_group 0;" ::: "memory");
        __syncthreads();

        unsigned stage = base + STAGE0 + (unsigned)(c % 3) * STAGE_SZ;
        {
            unsigned fpb = stage + 32768;
#pragma unroll
            for (int kq = 0; kq < 4; kq++) {
                int kstart = ckg * 8 + kq * 16;
                unsigned hw[4], lw[4];
#pragma unroll
                for (int w2 = 0; w2 < 4; w2++) {
                    float x0 = lds_f32(fpb + (unsigned)(((kstart + 2 * w2) * 128 + cd) * 4));
                    float x1 = lds_f32(fpb + (unsigned)(((kstart + 2 * w2 + 1) * 128 + cd) * 4));
                    unsigned short h0, l0, h1, l1;
                    split1(x0, h0, l0); split1(x1, h1, l1);
                    hw[w2] = (unsigned)h0 | ((unsigned)h1 << 16);
                    lw[w2] = (unsigned)l0 | ((unsigned)l1 << 16);
                }
                unsigned off = SWZ((unsigned)(cd * 128 + kstart * 2));
                sts128(base + CONV_BH + off, hw[0], hw[1], hw[2], hw[3]);
                sts128(base + CONV_BL + off, lw[0], lw[1], lw[2], lw[3]);
            }
        }
        __syncthreads();
        if (c + 2 < 64) issue(c + 2);

        unsigned sAh = stage, sAl = stage + 16384;
        unsigned sBh = base + CONV_BH, sBl = base + CONV_BL;
#pragma unroll
        for (int kk = 0; kk < 4; kk++) {
            unsigned ca = (a_c0 + (unsigned)(kk * 32)) ^ msk;
            unsigned cb = (b_c0 + (unsigned)(kk * 32)) ^ msk;
            unsigned ah[4][4], al[4][4], bh[2][4], bl[2][4];
#pragma unroll
            for (int mt = 0; mt < 4; mt++) {
                ldm4(ah[mt], sAh + a_row[mt] + ca);
                ldm4(al[mt], sAl + a_row[mt] + ca);
            }
#pragma unroll
            for (int np = 0; np < 2; np++) {
                ldm4(bh[np], sBh + b_row[np] + cb);
                ldm4(bl[np], sBl + b_row[np] + cb);
            }
#pragma unroll
            for (int mt = 0; mt < 4; mt++)
#pragma unroll
                for (int nt = 0; nt < 4; nt++)
                    mma_bf16(acc[mt][nt], ah[mt], &bh[nt >> 1][(nt & 1) * 2]);
#pragma unroll
            for (int mt = 0; mt < 4; mt++)
#pragma unroll
                for (int nt = 0; nt < 4; nt++)
                    mma_bf16(acc[mt][nt], ah[mt], &bl[nt >> 1][(nt & 1) * 2]);
#pragma unroll
            for (int mt = 0; mt < 4; mt++)
#pragma unroll
                for (int nt = 0; nt < 4; nt++)
                    mma_bf16(acc[mt][nt], al[mt], &bh[nt >> 1][(nt & 1) * 2]);
        }
    }

    // epilogue: write bf16 hi/lo split directly
#pragma unroll
    for (int mt = 0; mt < 4; mt++) {
#pragma unroll
        for (int nt = 0; nt < 4; nt++) {
            int r0 = wm + mt * 16 + (lane >> 2);
            int c0 = wn + nt * 8 + (lane & 3) * 2;
            unsigned short h0, l0, h1, l1, h2, l2, h3, l3;
            split1(acc[mt][nt][0], h0, l0);
            split1(acc[mt][nt][1], h1, l1);
            split1(acc[mt][nt][2], h2, l2);
            split1(acc[mt][nt][3], h3, l3);
            size_t o01 = cbase + (size_t)r0 * DD + c0;
            size_t o23 = cbase + (size_t)(r0 + 8) * DD + c0;
            *(unsigned*)(g_ABhi + o01) = (unsigned)h0 | ((unsigned)h1 << 16);
            *(unsigned*)(g_ABlo + o01) = (unsigned)l0 | ((unsigned)l1 << 16);
            *(unsigned*)(g_ABhi + o23) = (unsigned)h2 | ((unsigned)h3 << 16);
            *(unsigned*)(g_ABlo + o23) = (unsigned)l2 | ((unsigned)l3 << 16);
        }
    }
}

// ---------------------------------------------------------------------------
// gemm_nt_hmma: S_x/S_y/R via HMMA on bf16-split A/B (unchanged)
// ---------------------------------------------------------------------------
#define NTSTAGE_BYTES 65536
#define NT_SMEM (1024 + 3 * NTSTAGE_BYTES)
__global__ void __launch_bounds__(256, 1) gemm_nt_hmma() {
    extern __shared__ char smraw[];
    unsigned base = (smem_u32(smraw) + 1023) & ~1023u;
    int tid = threadIdx.x, wid = tid >> 5, lane = tid & 31;

    int id = blockIdx.x;
    int b = id / 3, mode = id % 3;
    size_t offA = (size_t)b * KK * DD;
    size_t offB = (size_t)(BB + b) * KK * DD;
    size_t offP = (mode == 0) ? offA : offB;
    size_t offQ = (mode == 1) ? offB : offA;
    const __nv_bfloat16* Ph = g_ABhi + offP;
    const __nv_bfloat16* Pl = g_ABlo + offP;
    const __nv_bfloat16* Qh = g_ABhi + offQ;
    const __nv_bfloat16* Ql = g_ABlo + offQ;
    float* C = (mode < 2) ? g_S + (size_t)(b * 2 + mode) * KK * KK
                          : g_R + (size_t)b * KK * KK;
    float* CT = g_RT + (size_t)b * KK * KK;

    int wm = (wid & 1) * 64, wn = (wid >> 1) * 32;

    float acc[4][4][4];
#pragma unroll
    for (int mt = 0; mt < 4; mt++)
#pragma unroll
        for (int nt = 0; nt < 4; nt++)
#pragma unroll
            for (int i = 0; i < 4; i++) acc[mt][nt][i] = 0.0f;

    unsigned msk = (unsigned)((lane & 7) << 4);
    unsigned a_c0 = (unsigned)((lane >> 4) * 16);
    unsigned b_c0 = (unsigned)(((lane >> 3) & 1) * 16);
    unsigned a_row[4], b_row[2];
#pragma unroll
    for (int mt = 0; mt < 4; mt++)
        a_row[mt] = (unsigned)((wm + mt * 16 + (lane & 15)) * 128);
#pragma unroll
    for (int np = 0; np < 2; np++)
        b_row[np] = (unsigned)((wn + np * 16 + ((lane >> 4) << 3) + (lane & 7)) * 128);

    auto issue = [&](int c) {
        unsigned stage = base + 1024 + (unsigned)(c % 3) * NTSTAGE_BYTES;
        int k0 = c * 64;
#pragma unroll
        for (int u = 0; u < 16; u++) {
            int tile = u >> 2;
            int v = tid + (u & 3) * 256;
            int r = v >> 3, s = v & 7;
            unsigned sa = stage + tile * 16384 + SWZ((unsigned)(r * 128 + s * 16));
            const __nv_bfloat16* g;
            if (tile == 0)      g = Ph;
            else if (tile == 1) g = Pl;
            else if (tile == 2) g = Qh;
            else                g = Ql;
            g += (size_t)r * DD + k0 + s * 8;
            asm volatile("cp.async.cg.shared.global [%0], [%1], 16;"
                         :: "r"(sa), "l"(g) : "memory");
        }
        asm volatile("cp.async.commit_group;" ::: "memory");
    };

    issue(0);
    issue(1);
    for (int c = 0; c < 8; c++) {
        if (c < 7)
            asm volatile("cp.async.wait_group 1;" ::: "memory");
        else
            asm volatile("cp.async.wait_group 0;" ::: "memory");
        __syncthreads();
        if (c + 2 < 8) issue(c + 2);
        unsigned stage = base + 1024 + (unsigned)(c % 3) * NTSTAGE_BYTES;
        unsigned sAh = stage, sAl = stage + 16384, sBh = stage + 32768, sBl = stage + 49152;
#pragma unroll
        for (int kk = 0; kk < 4; kk++) {
            unsigned ca = (a_c0 + (unsigned)(kk * 32)) ^ msk;
            unsigned cb = (b_c0 + (unsigned)(kk * 32)) ^ msk;
            unsigned ah[4][4], al[4][4], bh[2][4], bl[2][4];
#pragma unroll
            for (int mt = 0; mt < 4; mt++) {
                ldm4(ah[mt], sAh + a_row[mt] + ca);
                ldm4(al[mt], sAl + a_row[mt] + ca);
            }
#pragma unroll
            for (int np = 0; np < 2; np++) {
                ldm4(bh[np], sBh + b_row[np] + cb);
                ldm4(bl[np], sBl + b_row[np] + cb);
            }
#pragma unroll
            for (int mt = 0; mt < 4; mt++)
#pragma unroll
                for (int nt = 0; nt < 4; nt++)
                    mma_bf16(acc[mt][nt], ah[mt], &bh[nt >> 1][(nt & 1) * 2]);
#pragma unroll
            for (int mt = 0; mt < 4; mt++)
#pragma unroll
                for (int nt = 0; nt < 4; nt++)
                    mma_bf16(acc[mt][nt], ah[mt], &bl[nt >> 1][(nt & 1) * 2]);
#pragma unroll
            for (int mt = 0; mt < 4; mt++)
#pragma unroll
                for (int nt = 0; nt < 4; nt++)
                    mma_bf16(acc[mt][nt], al[mt], &bh[nt >> 1][(nt & 1) * 2]);
        }
    }

#pragma unroll
    for (int mt = 0; mt < 4; mt++) {
#pragma unroll
        for (int nt = 0; nt < 4; nt++) {
            int r0 = wm + mt * 16 + (lane >> 2);
            int c0 = wn + nt * 8 + (lane & 3) * 2;
            float v0 = acc[mt][nt][0], v1 = acc[mt][nt][1];
            float v2 = acc[mt][nt][2], v3 = acc[mt][nt][3];
            if (mode < 2) {
                if (r0 == c0) v0 += REGC;
                if (r0 == c0 + 1) v1 += REGC;
                if (r0 + 8 == c0) v2 += REGC;
                if (r0 + 8 == c0 + 1) v3 += REGC;
            }
            C[r0 * KK + c0] = v0;
            C[r0 * KK + c0 + 1] = v1;
            C[(r0 + 8) * KK + c0] = v2;
            C[(r0 + 8) * KK + c0 + 1] = v3;
            if (mode == 2) {
                CT[c0 * KK + r0] = v0;
                CT[(c0 + 1) * KK + r0] = v1;
                CT[c0 * KK + r0 + 8] = v2;
                CT[(c0 + 1) * KK + r0 + 8] = v3;
            }
        }
    }
}

// ---------------------------------------------------------------------------
// mask_kernel (unchanged)
// ---------------------------------------------------------------------------
__global__ void mask_kernel(const float* __restrict__ evx, const float* __restrict__ evy,
                            const float* __restrict__ ax,  const float* __restrict__ ay) {
    int id = blockIdx.x;
    int b = id >> 1, dir = id & 1;
    const float* e1p = (dir ? evy : evx) + b * KK;
    const float* e2p = (dir ? evx : evy) + b * KK;
    const float* a1p = (dir ? ay : ax) + b * KK;
    const float* a2p = (dir ? ax : ay) + b * KK;

    __shared__ float t1[128], u1[128], t2[128], u2[128];
    __shared__ float v1[128], w1[128], v2[128], w2[128];
    __shared__ float red[128];
    __shared__ float sc_main, sc_aux;

    int tid = threadIdx.x;
    float e1 = 0.f, e2 = 0.f, q1 = 0.f, q2 = 0.f;
    if (tid < 128) {
        e1 = fmaxf(e1p[tid], 1e-10f);
        e2 = fmaxf(e2p[tid], 1e-10f);
        q1 = fmaxf(a1p[tid], 1e-10f);
        q2 = fmaxf(a2p[tid], 1e-10f);
        red[tid] = fmaxf(e1, e2);
    }
    __syncthreads();
    for (int off = 64; off; off >>= 1) {
        if (tid < off) red[tid] = fmaxf(red[tid], red[tid + off]);
        __syncthreads();
    }
    if (tid == 0) sc_main = fmaxf(red[0], 1e-10f);
    __syncthreads();
    if (tid < 128) red[tid] = fmaxf(q1, q2);
    __syncthreads();
    for (int off = 64; off; off >>= 1) {
        if (tid < off) red[tid] = fmaxf(red[tid], red[tid + off]);
        __syncthreads();
    }
    if (tid == 0) sc_aux = fmaxf(red[0], 1e-10f);
    __syncthreads();

    if (tid < 128) {
        float r, d;
        r = e1 / sc_main; d = r + 1.0f; t1[tid] = sqrtf(r) / d; u1[tid] = 1.0f / d;
        r = e2 / sc_main; d = r + 1.0f; t2[tid] = sqrtf(r) / d; u2[tid] = 1.0f / d;
        r = q1 / sc_aux;  d = r + 1.0f; v1[tid] = sqrtf(r) / d; w1[tid] = 1.0f / d;
        r = q2 / sc_aux;  d = r + 1.0f; v2[tid] = sqrtf(r) / d; w2[tid] = 1.0f / d;
    }
    __syncthreads();

    float* Dp = g_D + (size_t)id * (KK * KK);
    for (int v = tid; v < KK * KK; v += 256) {
        int i = v >> 7, j = v & 127;
        float mr = t2[i] - t1[j], mi = u2[i] - u1[j];
        float ar = v2[i] - v1[j], ai = w2[i] - w1[j];
        Dp[v] = 100.0f * (mr * mr + mi * mi) + 25.0f * (ar * ar + ai * ai);
    }
}

// ---------------------------------------------------------------------------
// invert_blocked: blocked GJ, pivot block inverted IN WARP-0 REGISTERS
// (no block barriers inside the 32-iteration GJ; lane l owns column l).
// ---------------------------------------------------------------------------
#define MST 132
#define CST 36
#define TST 36
#define INV_SMEM ((128 * MST + 128 * CST + 32 * TST) * 4)

__global__ void invert_blocked() {
    extern __shared__ float sm[];
    float* M  = sm;
    float* Cs = sm + 128 * MST;
    float* T  = Cs + 128 * CST;
    int mat = blockIdx.x;
    const float* S = g_S + (size_t)mat * KK * KK;
    float* Si = g_Sinv + (size_t)mat * KK * KK;
    int tid = threadIdx.x;
    int lane = tid & 31;
    int ty = tid >> 4, tx = tid & 15;

#pragma unroll
    for (int u = 0; u < 16; u++) {
        int v = tid + u * 256;
        int m = v >> 5, c4 = (v & 31) << 2;
        *(float4*)(M + m * MST + c4) = *(const float4*)(S + m * 128 + c4);
    }
    __syncthreads();

    for (int p = 0; p < 4; p++) {
        int p0 = p * 32;
        // save column panel Cs (all 128 rows x 32 cols)
#pragma unroll
        for (int u = 0; u < 4; u++) {
            int v = tid + u * 256;
            int i = v >> 3, q4 = (v & 7) << 2;
            *(float4*)(Cs + i * CST + q4) = *(const float4*)(M + i * MST + p0 + q4);
        }
        __syncthreads();

        // --- warp 0: invert 32x32 pivot block in registers (lane = column) ---
        if (tid < 32) {
            float reg[32];
#pragma unroll
            for (int i = 0; i < 32; i++)
                reg[i] = M[(p0 + i) * MST + p0 + lane];
#pragma unroll
            for (int j = 0; j < 32; j++) {
                float piv = __shfl_sync(0xffffffffu, reg[j], j);
                float pivinv = 1.0f / piv;
                float rowj = (lane == j) ? pivinv : reg[j] * pivinv;
#pragma unroll
                for (int i = 0; i < 32; i++) {
                    if (i == j) continue;
                    float f = __shfl_sync(0xffffffffu, reg[i], j);
                    reg[i] = (lane == j) ? (-f * pivinv) : fmaf(-f, rowj, reg[i]);
                }
                reg[j] = rowj;
            }
#pragma unroll
            for (int i = 0; i < 32; i++)
                T[i * TST + lane] = reg[i];
        }
        __syncthreads();

        // row panel: M[P,:] <- T * Mold[P,:], with M[P,P] <- T
        {
            int qr = tid >> 3;
            int cb = (tid & 7) << 4;
            float out[16];
#pragma unroll
            for (int a = 0; a < 16; a++) out[a] = 0.0f;
            for (int r = 0; r < 32; r++) {
                float tq = T[qr * TST + r];
                const float* Mr = M + (p0 + r) * MST + cb;
#pragma unroll
                for (int a = 0; a < 16; a += 4) {
                    float4 mv = *(const float4*)(Mr + a);
                    out[a + 0] += tq * mv.x;
                    out[a + 1] += tq * mv.y;
                    out[a + 2] += tq * mv.z;
                    out[a + 3] += tq * mv.w;
                }
            }
            __syncthreads();
#pragma unroll
            for (int a = 0; a < 16; a++) {
                int l = cb + a;
                float vv = (l >= p0 && l < p0 + 32) ? T[qr * TST + (l - p0)] : out[a];
                M[(p0 + qr) * MST + l] = vv;
            }
            __syncthreads();
        }

        // rank-32 update
        {
            ull acc[6][4];
#pragma unroll
            for (int r = 0; r < 6; r++)
#pragma unroll
                for (int c = 0; c < 4; c++) acc[r][c] = 0ULL;
            for (int q = 0; q < 32; q++) {
                const float* Mp = M + (p0 + q) * MST + tx * 8;
                ull b0 = *(const ull*)(Mp + 0);
                ull b1 = *(const ull*)(Mp + 2);
                ull b2 = *(const ull*)(Mp + 4);
                ull b3 = *(const ull*)(Mp + 6);
#pragma unroll
                for (int r = 0; r < 6; r++) {
                    int z = ty + 16 * r;
                    int i = (z < p0) ? z : z + 32;
                    float av = Cs[i * CST + q];
                    ull a2 = pack2(av, av);
                    ffma2(acc[r][0], a2, b0);
                    ffma2(acc[r][1], a2, b1);
                    ffma2(acc[r][2], a2, b2);
                    ffma2(acc[r][3], a2, b3);
                }
            }
#pragma unroll
            for (int r = 0; r < 6; r++) {
                int z = ty + 16 * r;
                int i = (z < p0) ? z : z + 32;
#pragma unroll
                for (int c = 0; c < 4; c++) {
                    int l = tx * 8 + 2 * c;
                    float lo, hi;
                    unpack2(acc[r][c], lo, hi);
                    float* Mp = M + i * MST + l;
                    bool inP0 = (l >= p0 && l < p0 + 32);
                    bool inP1 = (l + 1 >= p0 && l + 1 < p0 + 32);
                    float o0 = (inP0 ? 0.0f : Mp[0]) - lo;
                    float o1 = (inP1 ? 0.0f : Mp[1]) - hi;
                    Mp[0] = o0;
                    Mp[1] = o1;
                }
            }
            __syncthreads();
        }
    }

#pragma unroll
    for (int u = 0; u < 16; u++) {
        int v = tid + u * 256;
        int m = v >> 5, c4 = (v & 31) << 2;
        *(float4*)(Si + m * 128 + c4) = *(const float4*)(M + m * MST + c4);
    }
}

// ---------------------------------------------------------------------------
// solve_gemm (unchanged)
// ---------------------------------------------------------------------------
#define EST 20
#define SST 68
__global__ void solve_gemm(float* __restrict__ out, int mode) {
    int id = blockIdx.y;
    int b = id >> 1, dir = id & 1;
    int n0 = blockIdx.x * 64;
    const float* Si = g_Sinv + (size_t)id * (KK * KK);
    const float* Dm = g_D + (size_t)id * (KK * KK);
    const float* Rb = (dir ? g_RT : g_R) + (size_t)b * (KK * KK);
    const float* Xp = (mode == 1 ? g_X0 : g_X1) + (size_t)id * (KK * KK);
    const float* base = g_X0 + (size_t)id * (KK * KK);
    float* Cout;
    if (mode == 0)      Cout = g_X0 + (size_t)id * (KK * KK);
    else if (mode == 1) Cout = g_X1 + (size_t)id * (KK * KK);
    else                Cout = out + (size_t)(dir ? BB * KK * KK : 0) + (size_t)b * (KK * KK);

    __shared__ float Ts[128 * EST];
    __shared__ float Ss[16 * SST];

    int tid = threadIdx.x;
    int ty = tid >> 4, tx = tid & 15;
    int v0 = tid, v1 = tid + 256;
    int tm0 = v0 >> 2, tc0 = (v0 & 3) << 2;
    int tm1 = v1 >> 2, tc1 = (v1 & 3) << 2;
    int sk = tid >> 4, sc = (tid & 15) << 2;

    ull acc[8][2];
#pragma unroll
    for (int r = 0; r < 8; r++) { acc[r][0] = 0ULL; acc[r][1] = 0ULL; }

    for (int k0 = 0; k0 < KK; k0 += 16) {
        if (mode == 0) {
            *(float4*)&Ts[tm0 * EST + tc0] = *(const float4*)(Rb + tm0 * 128 + k0 + tc0);
            *(float4*)&Ts[tm1 * EST + tc1] = *(const float4*)(Rb + tm1 * 128 + k0 + tc1);
        } else {
            float4 d0 = *(const float4*)(Dm + tm0 * 128 + k0 + tc0);
            float4 x0 = *(const float4*)(Xp + tm0 * 128 + k0 + tc0);
            float4 d1 = *(const float4*)(Dm + tm1 * 128 + k0 + tc1);
            float4 x1 = *(const float4*)(Xp + tm1 * 128 + k0 + tc1);
            float4 o0 = make_float4(d0.x * x0.x, d0.y * x0.y, d0.z * x0.z, d0.w * x0.w);
            float4 o1 = make_float4(d1.x * x1.x, d1.y * x1.y, d1.z * x1.z, d1.w * x1.w);
            *(float4*)&Ts[tm0 * EST + tc0] = o0;
            *(float4*)&Ts[tm1 * EST + tc1] = o1;
        }
        *(float4*)&Ss[sk * SST + sc] = *(const float4*)(Si + (size_t)(k0 + sk) * 128 + n0 + sc);
        __syncthreads();
#pragma unroll
        for (int k = 0; k < 16; k++) {
            ull b0 = *(const ull*)&Ss[k * SST + tx * 4];
            ull b1 = *(const ull*)&Ss[k * SST + tx * 4 + 2];
#pragma unroll
            for (int r = 0; r < 8; r++) {
                float av = Ts[(ty * 8 + r) * EST + k];
                ull a2 = pack2(av, av);
                ffma2(acc[r][0], a2, b0);
                ffma2(acc[r][1], a2, b1);
            }
        }
        __syncthreads();
    }
#pragma unroll
    for (int r = 0; r < 8; r++) {
        int m = ty * 8 + r;
#pragma unroll
        for (int c2 = 0; c2 < 2; c2++) {
            int n = n0 + tx * 4 + 2 * c2;
            int idx = m * 128 + n;
            float lo, hi;
            unpack2(acc[r][c2], lo, hi);
            if (mode != 0) {
                lo = base[idx] - lo;
                hi = base[idx + 1] - hi;
            }
            Cout[idx] = lo;
            Cout[idx + 1] = hi;
        }
    }
}

// ---------------------------------------------------------------------------
extern "C" void kernel_launch(void* const* d_in, const int* in_sizes, int n_in,
                              void* d_out, int out_size) {
    const float* feat_x  = (const float*)d_in[0];
    const float* feat_y  = (const float*)d_in[1];
    const float* evals_x = (const float*)d_in[2];
    const float* evals_y = (const float*)d_in[3];
    const float* evecs_x = (const float*)d_in[4];
    const float* evecs_y = (const float*)d_in[5];
    const float* aux_x   = (const float*)d_in[6];
    const float* aux_y   = (const float*)d_in[7];
    float* out = (float*)d_out;

    split_E<<<dim3(8192, 2), 256>>>(evecs_x, evecs_y);

    cudaFuncSetAttribute(mma_proj, cudaFuncAttributeMaxDynamicSharedMemorySize, MMA_SMEM);
    mma_proj<<<dim3(4, 32), 256, MMA_SMEM>>>(feat_x, feat_y);

    cudaFuncSetAttribute(gemm_nt_hmma, cudaFuncAttributeMaxDynamicSharedMemorySize, NT_SMEM);
    gemm_nt_hmma<<<48, 256, NT_SMEM>>>();

    mask_kernel<<<32, 256>>>(evals_x, evals_y, aux_x, aux_y);
    cudaFuncSetAttribute(invert_blocked, cudaFuncAttributeMaxDynamicSharedMemorySize, INV_SMEM);
    invert_blocked<<<32, 256, INV_SMEM>>>();
    solve_gemm<<<dim3(2, 32), 256>>>(out, 0);
    solve_gemm<<<dim3(2, 32), 256>>>(out, 1);
    solve_gemm<<<dim3(2, 32), 256>>>(out, 2);
}

// round 10
// speedup vs baseline: 3.2949x; 1.0219x over previous
#include <cuda_runtime.h>
#include <cuda_bf16.h>

#define BB 16
#define NN 4096
#define DD 512
#define KK 128
#define REGC 1e-6f

typedef unsigned long long ull;

__device__ __forceinline__ ull pack2(float x, float y) {
    ull r; asm("mov.b64 %0, {%1, %2};" : "=l"(r) : "f"(x), "f"(y)); return r;
}
__device__ __forceinline__ void unpack2(ull v, float& lo, float& hi) {
    asm("mov.b64 {%0, %1}, %2;" : "=f"(lo), "=f"(hi) : "l"(v));
}
__device__ __forceinline__ void ffma2(ull& d, ull a, ull b) {
    asm("fma.rn.f32x2 %0, %1, %2, %0;" : "+l"(d) : "l"(a), "l"(b));
}
__device__ __forceinline__ unsigned smem_u32(const void* p) {
    unsigned a;
    asm("{ .reg .u64 t; cvta.to.shared.u64 t, %1; cvt.u32.u64 %0, t; }" : "=r"(a) : "l"(p));
    return a;
}
__device__ __forceinline__ void ldm4(unsigned* r, unsigned addr) {
    asm volatile("ldmatrix.sync.aligned.m8n8.x4.shared.b16 {%0,%1,%2,%3}, [%4];"
                 : "=r"(r[0]), "=r"(r[1]), "=r"(r[2]), "=r"(r[3]) : "r"(addr));
}
__device__ __forceinline__ void mma_bf16(float* d, const unsigned* a, const unsigned* b) {
    asm volatile(
        "mma.sync.aligned.m16n8k16.row.col.f32.bf16.bf16.f32 "
        "{%0,%1,%2,%3}, {%4,%5,%6,%7}, {%8,%9}, {%0,%1,%2,%3};"
        : "+f"(d[0]), "+f"(d[1]), "+f"(d[2]), "+f"(d[3])
        : "r"(a[0]), "r"(a[1]), "r"(a[2]), "r"(a[3]), "r"(b[0]), "r"(b[1]));
}
__device__ __forceinline__ float lds_f32(unsigned a) {
    float v; asm volatile("ld.shared.f32 %0, [%1];" : "=f"(v) : "r"(a)); return v;
}
__device__ __forceinline__ void sts128(unsigned a, unsigned r0, unsigned r1,
                                       unsigned r2, unsigned r3) {
    asm volatile("st.shared.v4.b32 [%0], {%1,%2,%3,%4};"
                 :: "r"(a), "r"(r0), "r"(r1), "r"(r2), "r"(r3) : "memory");
}
#define SWZ(o) ((o) ^ (((o) >> 3) & 0x70))

// Scratch
__device__ float g_S[2 * BB * KK * KK];
__device__ float g_Sinv[2 * BB * KK * KK];
__device__ float g_R[BB * KK * KK];
__device__ float g_RT[BB * KK * KK];
__device__ float g_D[2 * BB * KK * KK];
__device__ float g_X0[2 * BB * KK * KK];
__device__ float g_X1[2 * BB * KK * KK];
__device__ __nv_bfloat16 g_Ehi[2 * BB * KK * NN];
__device__ __nv_bfloat16 g_Elo[2 * BB * KK * NN];
__device__ __nv_bfloat16 g_ABhi[2 * BB * KK * DD];
__device__ __nv_bfloat16 g_ABlo[2 * BB * KK * DD];

__device__ __forceinline__ void split1(float x, unsigned short& h, unsigned short& l) {
    __nv_bfloat16 hb = __float2bfloat16_rn(x);
    float r = x - __bfloat162float(hb);
    __nv_bfloat16 lb = __float2bfloat16_rn(r);
    h = __bfloat16_as_ushort(hb);
    l = __bfloat16_as_ushort(lb);
}

// ---------------------------------------------------------------------------
// split_E: evecs fp32 [b][128][4096] -> g_Ehi/g_Elo bf16
// ---------------------------------------------------------------------------
__global__ void split_E(const float* __restrict__ ex, const float* __restrict__ ey) {
    int w = blockIdx.y;
    const float* E = w ? ey : ex;
    size_t i4 = (size_t)blockIdx.x * 256 + threadIdx.x;
    float4 t = *((const float4*)E + i4);
    unsigned short h0, h1, h2, h3, l0, l1, l2, l3;
    split1(t.x, h0, l0); split1(t.y, h1, l1); split1(t.z, h2, l2); split1(t.w, h3, l3);
    ull hp = (ull)h0 | ((ull)h1 << 16) | ((ull)h2 << 32) | ((ull)h3 << 48);
    ull lp = (ull)l0 | ((ull)l1 << 16) | ((ull)l2 << 32) | ((ull)l3 << 48);
    size_t o = (size_t)w * (BB * KK * NN) + i4 * 4;
    *(ull*)(g_Ehi + o) = hp;
    *(ull*)(g_Elo + o) = lp;
}

// ---------------------------------------------------------------------------
// mma_proj (unchanged from R9)
// ---------------------------------------------------------------------------
#define CONV_BH 0
#define CONV_BL 16384
#define STAGE0 32768
#define STAGE_SZ 65536
#define MMA_SMEM (1024 + STAGE0 + 3 * STAGE_SZ)

__global__ void __launch_bounds__(256, 1) mma_proj(const float* __restrict__ fx,
                                                   const float* __restrict__ fy) {
    extern __shared__ char smraw[];
    unsigned base = (smem_u32(smraw) + 1023) & ~1023u;
    int tid = threadIdx.x, wid = tid >> 5, lane = tid & 31;

    int p = blockIdx.y; int w = p >> 4, b = p & 15;
    int n0 = blockIdx.x * 128;
    const __nv_bfloat16* Eh = g_Ehi + (size_t)p * KK * NN;
    const __nv_bfloat16* El = g_Elo + (size_t)p * KK * NN;
    const float* Ff = (w ? fy : fx) + (size_t)b * NN * DD + n0;
    size_t cbase = (size_t)p * KK * DD + n0;

    int wm = (wid & 1) * 64, wn = (wid >> 1) * 32;

    float acc[4][4][4];
#pragma unroll
    for (int mt = 0; mt < 4; mt++)
#pragma unroll
        for (int nt = 0; nt < 4; nt++)
#pragma unroll
            for (int i = 0; i < 4; i++) acc[mt][nt][i] = 0.0f;

    unsigned msk = (unsigned)((lane & 7) << 4);
    unsigned a_c0 = (unsigned)((lane >> 4) * 16);
    unsigned b_c0 = (unsigned)(((lane >> 3) & 1) * 16);
    unsigned a_row[4], b_row[2];
#pragma unroll
    for (int mt = 0; mt < 4; mt++)
        a_row[mt] = (unsigned)((wm + mt * 16 + (lane & 15)) * 128);
#pragma unroll
    for (int np = 0; np < 2; np++)
        b_row[np] = (unsigned)((wn + np * 16 + ((lane >> 4) << 3) + (lane & 7)) * 128);

    int cd = tid & 127, ckg = tid >> 7;

    auto issue = [&](int c) {
        unsigned stage = base + STAGE0 + (unsigned)(c % 3) * STAGE_SZ;
        int k0 = c * 64;
#pragma unroll
        for (int u = 0; u < 8; u++) {
            int tile = u >> 2;
            int v = tid + (u & 3) * 256;
            int r = v >> 3, s = v & 7;
            unsigned sa = stage + tile * 16384 + SWZ((unsigned)(r * 128 + s * 16));
            const __nv_bfloat16* g = (tile ? El : Eh) + (size_t)r * NN + k0 + s * 8;
            asm volatile("cp.async.cg.shared.global [%0], [%1], 16;"
                         :: "r"(sa), "l"(g) : "memory");
        }
#pragma unroll
        for (int u = 0; u < 8; u++) {
            int v = tid + u * 256;
            int r = v >> 5, s = v & 31;
            unsigned sa = stage + 32768 + (unsigned)(r * 512 + s * 16);
            const float* g = Ff + (size_t)(k0 + r) * DD + s * 4;
            asm volatile("cp.async.cg.shared.global [%0], [%1], 16;"
                         :: "r"(sa), "l"(g) : "memory");
        }
        asm volatile("cp.async.commit_group;" ::: "memory");
    };

    issue(0);
    issue(1);
    for (int c = 0; c < 64; c++) {
        if (c < 63)
            asm volatile("cp.async.wait_group 1;" ::: "memory");
        else
            asm volatile("cp.async.wait_group 0;" ::: "memory");
        __syncthreads();

        unsigned stage = base + STAGE0 + (unsigned)(c % 3) * STAGE_SZ;
        {
            unsigned fpb = stage + 32768;
#pragma unroll
            for (int kq = 0; kq < 4; kq++) {
                int kstart = ckg * 8 + kq * 16;
                unsigned hw[4], lw[4];
#pragma unroll
                for (int w2 = 0; w2 < 4; w2++) {
                    float x0 = lds_f32(fpb + (unsigned)(((kstart + 2 * w2) * 128 + cd) * 4));
                    float x1 = lds_f32(fpb + (unsigned)(((kstart + 2 * w2 + 1) * 128 + cd) * 4));
                    unsigned short h0, l0, h1, l1;
                    split1(x0, h0, l0); split1(x1, h1, l1);
                    hw[w2] = (unsigned)h0 | ((unsigned)h1 << 16);
                    lw[w2] = (unsigned)l0 | ((unsigned)l1 << 16);
                }
                unsigned off = SWZ((unsigned)(cd * 128 + kstart * 2));
                sts128(base + CONV_BH + off, hw[0], hw[1], hw[2], hw[3]);
                sts128(base + CONV_BL + off, lw[0], lw[1], lw[2], lw[3]);
            }
        }
        __syncthreads();
        if (c + 2 < 64) issue(c + 2);

        unsigned sAh = stage, sAl = stage + 16384;
        unsigned sBh = base + CONV_BH, sBl = base + CONV_BL;
#pragma unroll
        for (int kk = 0; kk < 4; kk++) {
            unsigned ca = (a_c0 + (unsigned)(kk * 32)) ^ msk;
            unsigned cb = (b_c0 + (unsigned)(kk * 32)) ^ msk;
            unsigned ah[4][4], al[4][4], bh[2][4], bl[2][4];
#pragma unroll
            for (int mt = 0; mt < 4; mt++) {
                ldm4(ah[mt], sAh + a_row[mt] + ca);
                ldm4(al[mt], sAl + a_row[mt] + ca);
            }
#pragma unroll
            for (int np = 0; np < 2; np++) {
                ldm4(bh[np], sBh + b_row[np] + cb);
                ldm4(bl[np], sBl + b_row[np] + cb);
            }
#pragma unroll
            for (int mt = 0; mt < 4; mt++)
#pragma unroll
                for (int nt = 0; nt < 4; nt++)
                    mma_bf16(acc[mt][nt], ah[mt], &bh[nt >> 1][(nt & 1) * 2]);
#pragma unroll
            for (int mt = 0; mt < 4; mt++)
#pragma unroll
                for (int nt = 0; nt < 4; nt++)
                    mma_bf16(acc[mt][nt], ah[mt], &bl[nt >> 1][(nt & 1) * 2]);
#pragma unroll
            for (int mt = 0; mt < 4; mt++)
#pragma unroll
                for (int nt = 0; nt < 4; nt++)
                    mma_bf16(acc[mt][nt], al[mt], &bh[nt >> 1][(nt & 1) * 2]);
        }
    }

#pragma unroll
    for (int mt = 0; mt < 4; mt++) {
#pragma unroll
        for (int nt = 0; nt < 4; nt++) {
            int r0 = wm + mt * 16 + (lane >> 2);
            int c0 = wn + nt * 8 + (lane & 3) * 2;
            unsigned short h0, l0, h1, l1, h2, l2, h3, l3;
            split1(acc[mt][nt][0], h0, l0);
            split1(acc[mt][nt][1], h1, l1);
            split1(acc[mt][nt][2], h2, l2);
            split1(acc[mt][nt][3], h3, l3);
            size_t o01 = cbase + (size_t)r0 * DD + c0;
            size_t o23 = cbase + (size_t)(r0 + 8) * DD + c0;
            *(unsigned*)(g_ABhi + o01) = (unsigned)h0 | ((unsigned)h1 << 16);
            *(unsigned*)(g_ABlo + o01) = (unsigned)l0 | ((unsigned)l1 << 16);
            *(unsigned*)(g_ABhi + o23) = (unsigned)h2 | ((unsigned)h3 << 16);
            *(unsigned*)(g_ABlo + o23) = (unsigned)l2 | ((unsigned)l3 << 16);
        }
    }
}

// ---------------------------------------------------------------------------
// gemm_nt_hmma (unchanged)
// ---------------------------------------------------------------------------
#define NTSTAGE_BYTES 65536
#define NT_SMEM (1024 + 3 * NTSTAGE_BYTES)
__global__ void __launch_bounds__(256, 1) gemm_nt_hmma() {
    extern __shared__ char smraw[];
    unsigned base = (smem_u32(smraw) + 1023) & ~1023u;
    int tid = threadIdx.x, wid = tid >> 5, lane = tid & 31;

    int id = blockIdx.x;
    int b = id / 3, mode = id % 3;
    size_t offA = (size_t)b * KK * DD;
    size_t offB = (size_t)(BB + b) * KK * DD;
    size_t offP = (mode == 0) ? offA : offB;
    size_t offQ = (mode == 1) ? offB : offA;
    const __nv_bfloat16* Ph = g_ABhi + offP;
    const __nv_bfloat16* Pl = g_ABlo + offP;
    const __nv_bfloat16* Qh = g_ABhi + offQ;
    const __nv_bfloat16* Ql = g_ABlo + offQ;
    float* C = (mode < 2) ? g_S + (size_t)(b * 2 + mode) * KK * KK
                          : g_R + (size_t)b * KK * KK;
    float* CT = g_RT + (size_t)b * KK * KK;

    int wm = (wid & 1) * 64, wn = (wid >> 1) * 32;

    float acc[4][4][4];
#pragma unroll
    for (int mt = 0; mt < 4; mt++)
#pragma unroll
        for (int nt = 0; nt < 4; nt++)
#pragma unroll
            for (int i = 0; i < 4; i++) acc[mt][nt][i] = 0.0f;

    unsigned msk = (unsigned)((lane & 7) << 4);
    unsigned a_c0 = (unsigned)((lane >> 4) * 16);
    unsigned b_c0 = (unsigned)(((lane >> 3) & 1) * 16);
    unsigned a_row[4], b_row[2];
#pragma unroll
    for (int mt = 0; mt < 4; mt++)
        a_row[mt] = (unsigned)((wm + mt * 16 + (lane & 15)) * 128);
#pragma unroll
    for (int np = 0; np < 2; np++)
        b_row[np] = (unsigned)((wn + np * 16 + ((lane >> 4) << 3) + (lane & 7)) * 128);

    auto issue = [&](int c) {
        unsigned stage = base + 1024 + (unsigned)(c % 3) * NTSTAGE_BYTES;
        int k0 = c * 64;
#pragma unroll
        for (int u = 0; u < 16; u++) {
            int tile = u >> 2;
            int v = tid + (u & 3) * 256;
            int r = v >> 3, s = v & 7;
            unsigned sa = stage + tile * 16384 + SWZ((unsigned)(r * 128 + s * 16));
            const __nv_bfloat16* g;
            if (tile == 0)      g = Ph;
            else if (tile == 1) g = Pl;
            else if (tile == 2) g = Qh;
            else                g = Ql;
            g += (size_t)r * DD + k0 + s * 8;
            asm volatile("cp.async.cg.shared.global [%0], [%1], 16;"
                         :: "r"(sa), "l"(g) : "memory");
        }
        asm volatile("cp.async.commit_group;" ::: "memory");
    };

    issue(0);
    issue(1);
    for (int c = 0; c < 8; c++) {
        if (c < 7)
            asm volatile("cp.async.wait_group 1;" ::: "memory");
        else
            asm volatile("cp.async.wait_group 0;" ::: "memory");
        __syncthreads();
        if (c + 2 < 8) issue(c + 2);
        unsigned stage = base + 1024 + (unsigned)(c % 3) * NTSTAGE_BYTES;
        unsigned sAh = stage, sAl = stage + 16384, sBh = stage + 32768, sBl = stage + 49152;
#pragma unroll
        for (int kk = 0; kk < 4; kk++) {
            unsigned ca = (a_c0 + (unsigned)(kk * 32)) ^ msk;
            unsigned cb = (b_c0 + (unsigned)(kk * 32)) ^ msk;
            unsigned ah[4][4], al[4][4], bh[2][4], bl[2][4];
#pragma unroll
            for (int mt = 0; mt < 4; mt++) {
                ldm4(ah[mt], sAh + a_row[mt] + ca);
                ldm4(al[mt], sAl + a_row[mt] + ca);
            }
#pragma unroll
            for (int np = 0; np < 2; np++) {
                ldm4(bh[np], sBh + b_row[np] + cb);
                ldm4(bl[np], sBl + b_row[np] + cb);
            }
#pragma unroll
            for (int mt = 0; mt < 4; mt++)
#pragma unroll
                for (int nt = 0; nt < 4; nt++)
                    mma_bf16(acc[mt][nt], ah[mt], &bh[nt >> 1][(nt & 1) * 2]);
#pragma unroll
            for (int mt = 0; mt < 4; mt++)
#pragma unroll
                for (int nt = 0; nt < 4; nt++)
                    mma_bf16(acc[mt][nt], ah[mt], &bl[nt >> 1][(nt & 1) * 2]);
#pragma unroll
            for (int mt = 0; mt < 4; mt++)
#pragma unroll
                for (int nt = 0; nt < 4; nt++)
                    mma_bf16(acc[mt][nt], al[mt], &bh[nt >> 1][(nt & 1) * 2]);
        }
    }

#pragma unroll
    for (int mt = 0; mt < 4; mt++) {
#pragma unroll
        for (int nt = 0; nt < 4; nt++) {
            int r0 = wm + mt * 16 + (lane >> 2);
            int c0 = wn + nt * 8 + (lane & 3) * 2;
            float v0 = acc[mt][nt][0], v1 = acc[mt][nt][1];
            float v2 = acc[mt][nt][2], v3 = acc[mt][nt][3];
            if (mode < 2) {
                if (r0 == c0) v0 += REGC;
                if (r0 == c0 + 1) v1 += REGC;
                if (r0 + 8 == c0) v2 += REGC;
                if (r0 + 8 == c0 + 1) v3 += REGC;
            }
            C[r0 * KK + c0] = v0;
            C[r0 * KK + c0 + 1] = v1;
            C[(r0 + 8) * KK + c0] = v2;
            C[(r0 + 8) * KK + c0 + 1] = v3;
            if (mode == 2) {
                CT[c0 * KK + r0] = v0;
                CT[(c0 + 1) * KK + r0] = v1;
                CT[c0 * KK + r0 + 8] = v2;
                CT[(c0 + 1) * KK + r0 + 8] = v3;
            }
        }
    }
}

// ---------------------------------------------------------------------------
// invert_mask: fused mask computation + blocked GJ inversion. 512 threads.
// grid 32 (id = b*2+dir, same indexing for g_S/g_Sinv/g_D).
// ---------------------------------------------------------------------------
#define MST 132
#define CST 36
#define TST 36
#define INV_SMEM ((128 * MST + 128 * CST + 32 * TST) * 4)

__global__ void __launch_bounds__(512, 1)
invert_mask(const float* __restrict__ evx, const float* __restrict__ evy,
            const float* __restrict__ ax,  const float* __restrict__ ay) {
    extern __shared__ float sm[];
    float* M  = sm;
    float* Cs = sm + 128 * MST;
    float* T  = Cs + 128 * CST;
    int id = blockIdx.x;
    int b = id >> 1, dir = id & 1;
    const float* S = g_S + (size_t)id * KK * KK;
    float* Si = g_Sinv + (size_t)id * KK * KK;
    int tid = threadIdx.x;
    int lane = tid & 31;
    int tx = tid & 15, ty = tid >> 4;   // update partition: ty 0..31, tx 0..15

    // ===== mask part =====
    {
        __shared__ float t1[128], u1[128], t2[128], u2[128];
        __shared__ float v1[128], w1[128], v2[128], w2[128];
        __shared__ float red[128];
        __shared__ float sc_main, sc_aux;

        const float* e1p = (dir ? evy : evx) + b * KK;
        const float* e2p = (dir ? evx : evy) + b * KK;
        const float* a1p = (dir ? ay : ax) + b * KK;
        const float* a2p = (dir ? ax : ay) + b * KK;

        float e1 = 0.f, e2 = 0.f, q1 = 0.f, q2 = 0.f;
        if (tid < 128) {
            e1 = fmaxf(e1p[tid], 1e-10f);
            e2 = fmaxf(e2p[tid], 1e-10f);
            q1 = fmaxf(a1p[tid], 1e-10f);
            q2 = fmaxf(a2p[tid], 1e-10f);
            red[tid] = fmaxf(e1, e2);
        }
        __syncthreads();
        for (int off = 64; off; off >>= 1) {
            if (tid < off) red[tid] = fmaxf(red[tid], red[tid + off]);
            __syncthreads();
        }
        if (tid == 0) sc_main = fmaxf(red[0], 1e-10f);
        __syncthreads();
        if (tid < 128) red[tid] = fmaxf(q1, q2);
        __syncthreads();
        for (int off = 64; off; off >>= 1) {
            if (tid < off) red[tid] = fmaxf(red[tid], red[tid + off]);
            __syncthreads();
        }
        if (tid == 0) sc_aux = fmaxf(red[0], 1e-10f);
        __syncthreads();

        if (tid < 128) {
            float r, d;
            r = e1 / sc_main; d = r + 1.0f; t1[tid] = sqrtf(r) / d; u1[tid] = 1.0f / d;
            r = e2 / sc_main; d = r + 1.0f; t2[tid] = sqrtf(r) / d; u2[tid] = 1.0f / d;
            r = q1 / sc_aux;  d = r + 1.0f; v1[tid] = sqrtf(r) / d; w1[tid] = 1.0f / d;
            r = q2 / sc_aux;  d = r + 1.0f; v2[tid] = sqrtf(r) / d; w2[tid] = 1.0f / d;
        }
        __syncthreads();

        float* Dp = g_D + (size_t)id * (KK * KK);
        for (int v = tid; v < KK * KK; v += 512) {
            int i = v >> 7, j = v & 127;
            float mr = t2[i] - t1[j], mi = u2[i] - u1[j];
            float ar = v2[i] - v1[j], ai = w2[i] - w1[j];
            Dp[v] = 100.0f * (mr * mr + mi * mi) + 25.0f * (ar * ar + ai * ai);
        }
    }

    // ===== inversion part =====
#pragma unroll
    for (int u = 0; u < 8; u++) {
        int v = tid + u * 512;
        int m = v >> 5, c4 = (v & 31) << 2;
        *(float4*)(M + m * MST + c4) = *(const float4*)(S + m * 128 + c4);
    }
    __syncthreads();

    for (int p = 0; p < 4; p++) {
        int p0 = p * 32;
        // save column panel Cs (128 rows x 32 cols)
#pragma unroll
        for (int u = 0; u < 2; u++) {
            int v = tid + u * 512;
            int i = v >> 3, q4 = (v & 7) << 2;
            *(float4*)(Cs + i * CST + q4) = *(const float4*)(M + i * MST + p0 + q4);
        }
        __syncthreads();

        // warp 0: invert 32x32 pivot block in registers (lane = column)
        if (tid < 32) {
            float reg[32];
#pragma unroll
            for (int i = 0; i < 32; i++)
                reg[i] = M[(p0 + i) * MST + p0 + lane];
#pragma unroll
            for (int j = 0; j < 32; j++) {
                float piv = __shfl_sync(0xffffffffu, reg[j], j);
                float pivinv = 1.0f / piv;
                float rowj = (lane == j) ? pivinv : reg[j] * pivinv;
#pragma unroll
                for (int i = 0; i < 32; i++) {
                    if (i == j) continue;
                    float f = __shfl_sync(0xffffffffu, reg[i], j);
                    reg[i] = (lane == j) ? (-f * pivinv) : fmaf(-f, rowj, reg[i]);
                }
                reg[j] = rowj;
            }
#pragma unroll
            for (int i = 0; i < 32; i++)
                T[i * TST + lane] = reg[i];
        }
        __syncthreads();

        // row panel: M[P,:] <- T * Mold[P,:] ; M[P,P] <- T
        // thread (qr = ty, col block cb = tx*8): 8 outputs
        {
            int qr = ty;
            int cb = tx * 8;
            float out[8];
#pragma unroll
            for (int a = 0; a < 8; a++) out[a] = 0.0f;
            for (int r = 0; r < 32; r++) {
                float tq = T[qr * TST + r];
                const float* Mr = M + (p0 + r) * MST + cb;
#pragma unroll
                for (int a = 0; a < 8; a += 4) {
                    float4 mv = *(const float4*)(Mr + a);
                    out[a + 0] += tq * mv.x;
                    out[a + 1] += tq * mv.y;
                    out[a + 2] += tq * mv.z;
                    out[a + 3] += tq * mv.w;
                }
            }
            __syncthreads();
#pragma unroll
            for (int a = 0; a < 8; a++) {
                int l = cb + a;
                float vv = (l >= p0 && l < p0 + 32) ? T[qr * TST + (l - p0)] : out[a];
                M[(p0 + qr) * MST + l] = vv;
            }
            __syncthreads();
        }

        // rank-32 update: 96 rows x 128 cols; thread does 3 rows x 8 cols
        {
            ull acc[3][4];
#pragma unroll
            for (int r = 0; r < 3; r++)
#pragma unroll
                for (int c = 0; c < 4; c++) acc[r][c] = 0ULL;
            for (int q = 0; q < 32; q++) {
                const float* Mp = M + (p0 + q) * MST + tx * 8;
                ull b0 = *(const ull*)(Mp + 0);
                ull b1 = *(const ull*)(Mp + 2);
                ull b2 = *(const ull*)(Mp + 4);
                ull b3 = *(const ull*)(Mp + 6);
#pragma unroll
                for (int r = 0; r < 3; r++) {
                    int z = ty + 32 * r;
                    int i = (z < p0) ? z : z + 32;
                    float av = Cs[i * CST + q];
                    ull a2 = pack2(av, av);
                    ffma2(acc[r][0], a2, b0);
                    ffma2(acc[r][1], a2, b1);
                    ffma2(acc[r][2], a2, b2);
                    ffma2(acc[r][3], a2, b3);
                }
            }
#pragma unroll
            for (int r = 0; r < 3; r++) {
                int z = ty + 32 * r;
                int i = (z < p0) ? z : z + 32;
#pragma unroll
                for (int c = 0; c < 4; c++) {
                    int l = tx * 8 + 2 * c;
                    float lo, hi;
                    unpack2(acc[r][c], lo, hi);
                    float* Mp = M + i * MST + l;
                    bool inP0 = (l >= p0 && l < p0 + 32);
                    bool inP1 = (l + 1 >= p0 && l + 1 < p0 + 32);
                    float o0 = (inP0 ? 0.0f : Mp[0]) - lo;
                    float o1 = (inP1 ? 0.0f : Mp[1]) - hi;
                    Mp[0] = o0;
                    Mp[1] = o1;
                }
            }
            __syncthreads();
        }
    }

#pragma unroll
    for (int u = 0; u < 8; u++) {
        int v = tid + u * 512;
        int m = v >> 5, c4 = (v & 31) << 2;
        *(float4*)(Si + m * 128 + c4) = *(const float4*)(M + m * MST + c4);
    }
}

// ---------------------------------------------------------------------------
// solve_gemm (unchanged)
// ---------------------------------------------------------------------------
#define EST 20
#define SST 68
__global__ void solve_gemm(float* __restrict__ out, int mode) {
    int id = blockIdx.y;
    int b = id >> 1, dir = id & 1;
    int n0 = blockIdx.x * 64;
    const float* Si = g_Sinv + (size_t)id * (KK * KK);
    const float* Dm = g_D + (size_t)id * (KK * KK);
    const float* Rb = (dir ? g_RT : g_R) + (size_t)b * (KK * KK);
    const float* Xp = (mode == 1 ? g_X0 : g_X1) + (size_t)id * (KK * KK);
    const float* base = g_X0 + (size_t)id * (KK * KK);
    float* Cout;
    if (mode == 0)      Cout = g_X0 + (size_t)id * (KK * KK);
    else if (mode == 1) Cout = g_X1 + (size_t)id * (KK * KK);
    else                Cout = out + (size_t)(dir ? BB * KK * KK : 0) + (size_t)b * (KK * KK);

    __shared__ float Ts[128 * EST];
    __shared__ float Ss[16 * SST];

    int tid = threadIdx.x;
    int ty = tid >> 4, tx = tid & 15;
    int v0 = tid, v1 = tid + 256;
    int tm0 = v0 >> 2, tc0 = (v0 & 3) << 2;
    int tm1 = v1 >> 2, tc1 = (v1 & 3) << 2;
    int sk = tid >> 4, sc = (tid & 15) << 2;

    ull acc[8][2];
#pragma unroll
    for (int r = 0; r < 8; r++) { acc[r][0] = 0ULL; acc[r][1] = 0ULL; }

    for (int k0 = 0; k0 < KK; k0 += 16) {
        if (mode == 0) {
            *(float4*)&Ts[tm0 * EST + tc0] = *(const float4*)(Rb + tm0 * 128 + k0 + tc0);
            *(float4*)&Ts[tm1 * EST + tc1] = *(const float4*)(Rb + tm1 * 128 + k0 + tc1);
        } else {
            float4 d0 = *(const float4*)(Dm + tm0 * 128 + k0 + tc0);
            float4 x0 = *(const float4*)(Xp + tm0 * 128 + k0 + tc0);
            float4 d1 = *(const float4*)(Dm + tm1 * 128 + k0 + tc1);
            float4 x1 = *(const float4*)(Xp + tm1 * 128 + k0 + tc1);
            float4 o0 = make_float4(d0.x * x0.x, d0.y * x0.y, d0.z * x0.z, d0.w * x0.w);
            float4 o1 = make_float4(d1.x * x1.x, d1.y * x1.y, d1.z * x1.z, d1.w * x1.w);
            *(float4*)&Ts[tm0 * EST + tc0] = o0;
            *(float4*)&Ts[tm1 * EST + tc1] = o1;
        }
        *(float4*)&Ss[sk * SST + sc] = *(const float4*)(Si + (size_t)(k0 + sk) * 128 + n0 + sc);
        __syncthreads();
#pragma unroll
        for (int k = 0; k < 16; k++) {
            ull b0 = *(const ull*)&Ss[k * SST + tx * 4];
            ull b1 = *(const ull*)&Ss[k * SST + tx * 4 + 2];
#pragma unroll
            for (int r = 0; r < 8; r++) {
                float av = Ts[(ty * 8 + r) * EST + k];
                ull a2 = pack2(av, av);
                ffma2(acc[r][0], a2, b0);
                ffma2(acc[r][1], a2, b1);
            }
        }
        __syncthreads();
    }
#pragma unroll
    for (int r = 0; r < 8; r++) {
        int m = ty * 8 + r;
#pragma unroll
        for (int c2 = 0; c2 < 2; c2++) {
            int n = n0 + tx * 4 + 2 * c2;
            int idx = m * 128 + n;
            float lo, hi;
            unpack2(acc[r][c2], lo, hi);
            if (mode != 0) {
                lo = base[idx] - lo;
                hi = base[idx + 1] - hi;
            }
            Cout[idx] = lo;
            Cout[idx + 1] = hi;
        }
    }
}

// ---------------------------------------------------------------------------
extern "C" void kernel_launch(void* const* d_in, const int* in_sizes, int n_in,
                              void* d_out, int out_size) {
    const float* feat_x  = (const float*)d_in[0];
    const float* feat_y  = (const float*)d_in[1];
    const float* evals_x = (const float*)d_in[2];
    const float* evals_y = (const float*)d_in[3];
    const float* evecs_x = (const float*)d_in[4];
    const float* evecs_y = (const float*)d_in[5];
    const float* aux_x   = (const float*)d_in[6];
    const float* aux_y   = (const float*)d_in[7];
    float* out = (float*)d_out;

    split_E<<<dim3(8192, 2), 256>>>(evecs_x, evecs_y);

    cudaFuncSetAttribute(mma_proj, cudaFuncAttributeMaxDynamicSharedMemorySize, MMA_SMEM);
    mma_proj<<<dim3(4, 32), 256, MMA_SMEM>>>(feat_x, feat_y);

    cudaFuncSetAttribute(gemm_nt_hmma, cudaFuncAttributeMaxDynamicSharedMemorySize, NT_SMEM);
    gemm_nt_hmma<<<48, 256, NT_SMEM>>>();

    cudaFuncSetAttribute(invert_mask, cudaFuncAttributeMaxDynamicSharedMemorySize, INV_SMEM);
    invert_mask<<<32, 512, INV_SMEM>>>(evals_x, evals_y, aux_x, aux_y);

    solve_gemm<<<dim3(2, 32), 256>>>(out, 0);
    solve_gemm<<<dim3(2, 32), 256>>>(out, 1);
    solve_gemm<<<dim3(2, 32), 256>>>(out, 2);
}